// round 1
// baseline (speedup 1.0000x reference)
#include <cuda_runtime.h>
#include <cstdint>

#define SEQ   2048
#define DMODEL 1024
#define NHEAD 16
#define DVDIM 64
#define NBATCH 4
#define MROWS (NBATCH * SEQ)   // 8192
#define MWORDS (SEQ / 32)      // 64 packed mask words per row

// ---------------- scratch (device globals: no allocation allowed) ----------
__device__ float g_Q[MROWS * DMODEL];
__device__ float g_K[MROWS * DMODEL];
__device__ float g_V[MROWS * DMODEL];
__device__ float g_C[MROWS * DMODEL];
__device__ unsigned g_mbits[SEQ * MWORDS];
__device__ int g_mode;

// ---------------- mask dtype detection -------------------------------------
// Scans first 4096 32-bit words of the mask buffer. Identifies which dtype's
// "true" bit pattern appears. Deterministic (same input -> same mode).
__global__ void detect_mask(const unsigned* __restrict__ m) {
    __shared__ int f[4];  // 0:u8  1:f16  2:bf16  3:f32
    int t = threadIdx.x;
    if (t < 4) f[t] = 0;
    __syncthreads();
    int fu8 = 0, ff16 = 0, fbf16 = 0, ff32 = 0;
    for (int i = t; i < 4096; i += 256) {
        unsigned w = m[i];
        if (w == 0x3F800000u) ff32 = 1;
        if (w == 0x3F803F80u || w == 0x00003F80u) fbf16 = 1;
        if (w == 0x3C003C00u || w == 0x00003C00u || w == 0x3C000000u) ff16 = 1;
        if ((w & 0xFEFEFEFEu) == 0u && w > 1u) fu8 = 1;
    }
    if (fu8)  atomicOr(&f[0], 1);
    if (ff16) atomicOr(&f[1], 1);
    if (fbf16) atomicOr(&f[2], 1);
    if (ff32) atomicOr(&f[3], 1);
    __syncthreads();
    if (t == 0) {
        int mode;
        if (f[1]) mode = 4;        // fp16
        else if (f[2]) mode = 3;   // bf16
        else if (f[3]) mode = 2;   // fp32
        else if (f[0]) mode = 1;   // uint8/bool
        else mode = 0;             // int32
        g_mode = mode;
    }
}

// Pack mask into bit table: bit j of word (row, w) = mask[row][w*32+j] != 0
__global__ void pack_mask(const void* __restrict__ mp) {
    int idx = blockIdx.x * blockDim.x + threadIdx.x;   // word index
    int mode = g_mode;
    long base = (long)idx * 32;
    unsigned bits = 0;
    if (mode == 0) {
        const int* p = (const int*)mp;
        #pragma unroll 8
        for (int j = 0; j < 32; j++) if (p[base + j] != 0) bits |= 1u << j;
    } else if (mode == 1) {
        const unsigned char* p = (const unsigned char*)mp;
        #pragma unroll 8
        for (int j = 0; j < 32; j++) if (p[base + j] != 0) bits |= 1u << j;
    } else if (mode == 2) {
        const float* p = (const float*)mp;
        #pragma unroll 8
        for (int j = 0; j < 32; j++) if (p[base + j] != 0.0f) bits |= 1u << j;
    } else {
        const unsigned short* p = (const unsigned short*)mp;
        #pragma unroll 8
        for (int j = 0; j < 32; j++) if (p[base + j] != 0) bits |= 1u << j;
    }
    g_mbits[idx] = bits;
}

// ---------------- SGEMM: Y[M,N] = X[M,K] @ W[N,K]^T + bias[N] ---------------
// 128x128 block tile, BK=8, 256 threads, 8x8 per thread, global prefetch.
__global__ void __launch_bounds__(256) sgemm_bias(
    const float* __restrict__ X, const float* __restrict__ W,
    const float* __restrict__ bias, float* __restrict__ Y,
    int M, int N, int K)
{
    __shared__ float As[8][128];
    __shared__ float Bs[8][128];
    int tid = threadIdx.x;
    int tx = tid & 15, ty = tid >> 4;
    int m0 = blockIdx.y << 7, n0 = blockIdx.x << 7;

    int lr = tid >> 1;            // 0..127: row within tile
    int lc = (tid & 1) << 2;      // 0 or 4: k offset
    const float* Xp = X + (size_t)(m0 + lr) * K + lc;
    const float* Wp = W + (size_t)(n0 + lr) * K + lc;

    float4 av = *(const float4*)Xp;
    float4 bv = *(const float4*)Wp;

    float acc[8][8];
    #pragma unroll
    for (int i = 0; i < 8; i++)
        #pragma unroll
        for (int j = 0; j < 8; j++) acc[i][j] = 0.0f;

    for (int k0 = 0; k0 < K; k0 += 8) {
        As[lc + 0][lr] = av.x; As[lc + 1][lr] = av.y;
        As[lc + 2][lr] = av.z; As[lc + 3][lr] = av.w;
        Bs[lc + 0][lr] = bv.x; Bs[lc + 1][lr] = bv.y;
        Bs[lc + 2][lr] = bv.z; Bs[lc + 3][lr] = bv.w;
        __syncthreads();
        if (k0 + 8 < K) {
            av = *(const float4*)(Xp + k0 + 8);
            bv = *(const float4*)(Wp + k0 + 8);
        }
        #pragma unroll
        for (int k = 0; k < 8; k++) {
            float a[8], b[8];
            *(float4*)(a)     = *(const float4*)&As[k][ty * 8];
            *(float4*)(a + 4) = *(const float4*)&As[k][ty * 8 + 4];
            *(float4*)(b)     = *(const float4*)&Bs[k][tx * 8];
            *(float4*)(b + 4) = *(const float4*)&Bs[k][tx * 8 + 4];
            #pragma unroll
            for (int i = 0; i < 8; i++)
                #pragma unroll
                for (int j = 0; j < 8; j++)
                    acc[i][j] = fmaf(a[i], b[j], acc[i][j]);
        }
        __syncthreads();
    }

    // epilogue with bias, vectorized stores
    #pragma unroll
    for (int i = 0; i < 8; i++) {
        float* yp = Y + (size_t)(m0 + ty * 8 + i) * N + n0 + tx * 8;
        #pragma unroll
        for (int jj = 0; jj < 2; jj++) {
            float4 r;
            int j = jj * 4;
            r.x = acc[i][j + 0] + bias[n0 + tx * 8 + j + 0];
            r.y = acc[i][j + 1] + bias[n0 + tx * 8 + j + 1];
            r.z = acc[i][j + 2] + bias[n0 + tx * 8 + j + 2];
            r.w = acc[i][j + 3] + bias[n0 + tx * 8 + j + 3];
            *(float4*)(yp + j) = r;
        }
    }
}

// ---------------- fused flash attention ------------------------------------
// Grid (S/128, H, B), 128 threads. Thread t owns q-row q0+t entirely:
// q-row (64) and O accumulator (64) in registers, per-row online softmax
// (no cross-thread reductions). K/V tiles of 32 rows staged in smem
// (broadcast reads). Mask read as 1 packed word per tile per row.
__global__ void __launch_bounds__(128) flash_attn() {
    __shared__ float Ks[32][68];
    __shared__ float Vs[32][68];
    __shared__ float Ss[128][33];

    int tid = threadIdx.x;
    int q0 = blockIdx.x << 7;
    int h = blockIdx.y, b = blockIdx.z;
    int row = q0 + tid;

    const float* qp = g_Q + ((size_t)(b * SEQ + row)) * DMODEL + h * DVDIM;
    float qr[64];
    #pragma unroll
    for (int i = 0; i < 16; i++) {
        float4 t4 = *(const float4*)(qp + i * 4);
        qr[4 * i + 0] = t4.x; qr[4 * i + 1] = t4.y;
        qr[4 * i + 2] = t4.z; qr[4 * i + 3] = t4.w;
    }
    float o[64];
    #pragma unroll
    for (int d = 0; d < 64; d++) o[d] = 0.0f;
    float mv = -1e30f, l = 0.0f;

    int jr = tid >> 2;            // which K/V row this thread loads
    int c0 = (tid & 3) << 4;      // 16-float chunk within the row
    const float* kb = g_K + ((size_t)b * SEQ) * DMODEL + h * DVDIM;
    const float* vb = g_V + ((size_t)b * SEQ) * DMODEL + h * DVDIM;
    const unsigned* mrow = g_mbits + (size_t)row * MWORDS;

    for (int k0 = 0; k0 < SEQ; k0 += 32) {
        const float* kp = kb + (size_t)(k0 + jr) * DMODEL + c0;
        const float* vp = vb + (size_t)(k0 + jr) * DMODEL + c0;
        #pragma unroll
        for (int f = 0; f < 4; f++) {
            *(float4*)&Ks[jr][c0 + 4 * f] = *(const float4*)(kp + 4 * f);
            *(float4*)&Vs[jr][c0 + 4 * f] = *(const float4*)(vp + 4 * f);
        }
        unsigned mw = mrow[k0 >> 5];
        __syncthreads();

        // scores for this 32-key tile (per-thread row, smem-staged)
        float mt = mv;
        for (int j = 0; j < 32; j++) {
            float a0 = 0.f, a1 = 0.f, a2 = 0.f, a3 = 0.f;
            #pragma unroll
            for (int k = 0; k < 64; k += 16) {
                float4 u0 = *(const float4*)&Ks[j][k];
                float4 u1 = *(const float4*)&Ks[j][k + 4];
                float4 u2 = *(const float4*)&Ks[j][k + 8];
                float4 u3 = *(const float4*)&Ks[j][k + 12];
                a0 = fmaf(qr[k + 0],  u0.x, a0); a0 = fmaf(qr[k + 1],  u0.y, a0);
                a0 = fmaf(qr[k + 2],  u0.z, a0); a0 = fmaf(qr[k + 3],  u0.w, a0);
                a1 = fmaf(qr[k + 4],  u1.x, a1); a1 = fmaf(qr[k + 5],  u1.y, a1);
                a1 = fmaf(qr[k + 6],  u1.z, a1); a1 = fmaf(qr[k + 7],  u1.w, a1);
                a2 = fmaf(qr[k + 8],  u2.x, a2); a2 = fmaf(qr[k + 9],  u2.y, a2);
                a2 = fmaf(qr[k + 10], u2.z, a2); a2 = fmaf(qr[k + 11], u2.w, a2);
                a3 = fmaf(qr[k + 12], u3.x, a3); a3 = fmaf(qr[k + 13], u3.y, a3);
                a3 = fmaf(qr[k + 14], u3.z, a3); a3 = fmaf(qr[k + 15], u3.w, a3);
            }
            float sum = (a0 + a1) + (a2 + a3);
            float sv = ((mw >> j) & 1u) ? 1e-9f : sum * 0.125f;
            Ss[tid][j] = sv;
            mt = fmaxf(mt, sv);
        }

        float alpha = __expf(mv - mt);
        mv = mt;
        l *= alpha;
        #pragma unroll
        for (int d = 0; d < 64; d++) o[d] *= alpha;

        for (int j = 0; j < 32; j++) {
            float p = __expf(Ss[tid][j] - mt);
            l += p;
            #pragma unroll
            for (int d = 0; d < 64; d += 4) {
                float4 u = *(const float4*)&Vs[j][d];
                o[d + 0] = fmaf(p, u.x, o[d + 0]);
                o[d + 1] = fmaf(p, u.y, o[d + 1]);
                o[d + 2] = fmaf(p, u.z, o[d + 2]);
                o[d + 3] = fmaf(p, u.w, o[d + 3]);
            }
        }
        __syncthreads();
    }

    float inv = 1.0f / l;
    float* op = g_C + ((size_t)(b * SEQ + row)) * DMODEL + h * DVDIM;
    #pragma unroll
    for (int d = 0; d < 64; d += 4) {
        float4 r;
        r.x = o[d + 0] * inv; r.y = o[d + 1] * inv;
        r.z = o[d + 2] * inv; r.w = o[d + 3] * inv;
        *(float4*)(op + d) = r;
    }
}

// ---------------- launch ----------------------------------------------------
extern "C" void kernel_launch(void* const* d_in, const int* in_sizes, int n_in,
                              void* d_out, int out_size)
{
    const float* q    = (const float*)d_in[0];
    const float* k    = (const float*)d_in[1];
    const float* v    = (const float*)d_in[2];
    const void*  mask = d_in[3];
    const float* Wq   = (const float*)d_in[4];
    const float* bq   = (const float*)d_in[5];
    const float* Wk   = (const float*)d_in[6];
    const float* bk   = (const float*)d_in[7];
    const float* Wv   = (const float*)d_in[8];
    const float* bv   = (const float*)d_in[9];
    const float* Wo   = (const float*)d_in[10];
    const float* bo   = (const float*)d_in[11];

    float *gq, *gk, *gv, *gc;
    cudaGetSymbolAddress((void**)&gq, g_Q);
    cudaGetSymbolAddress((void**)&gk, g_K);
    cudaGetSymbolAddress((void**)&gv, g_V);
    cudaGetSymbolAddress((void**)&gc, g_C);

    detect_mask<<<1, 256>>>((const unsigned*)mask);
    pack_mask<<<(SEQ * MWORDS) / 256, 256>>>(mask);

    dim3 gg(DMODEL / 128, MROWS / 128);
    sgemm_bias<<<gg, 256>>>(q, Wq, bq, gq, MROWS, DMODEL, DMODEL);
    sgemm_bias<<<gg, 256>>>(k, Wk, bk, gk, MROWS, DMODEL, DMODEL);
    sgemm_bias<<<gg, 256>>>(v, Wv, bv, gv, MROWS, DMODEL, DMODEL);

    flash_attn<<<dim3(SEQ / 128, NHEAD, NBATCH), 128>>>();

    sgemm_bias<<<gg, 256>>>(gc, Wo, bo, (float*)d_out, MROWS, DMODEL, DMODEL);
}

// round 3
// speedup vs baseline: 1.2912x; 1.2912x over previous
#include <cuda_runtime.h>
#include <cuda_bf16.h>
#include <cstdint>

#define SEQ    2048
#define DMODEL 1024
#define NHEAD  16
#define DVDIM  64
#define NBATCH 4
#define MROWS  (NBATCH * SEQ)   // 8192
#define MWORDS (SEQ / 32)

// ---------------- scratch (device globals) ----------------------------------
__device__ float g_Q[MROWS * DMODEL];
__device__ float g_K[MROWS * DMODEL];
__device__ float g_V[MROWS * DMODEL];
__device__ float g_C[MROWS * DMODEL];
__device__ __align__(16) __nv_bfloat16 g_ahi[MROWS * DMODEL];
__device__ __align__(16) __nv_bfloat16 g_alo[MROWS * DMODEL];
__device__ __align__(16) __nv_bfloat16 g_whi[DMODEL * DMODEL];
__device__ __align__(16) __nv_bfloat16 g_wlo[DMODEL * DMODEL];
__device__ unsigned g_mbits[SEQ * MWORDS];
__device__ int g_mode;

// ---------------- PTX helpers (sm_103-safe: no 'a' features) ----------------
__device__ __forceinline__ uint32_t smem_u32(const void* p) {
    uint32_t a;
    asm("{ .reg .u64 t; cvta.to.shared.u64 t, %1; cvt.u32.u64 %0, t; }" : "=r"(a) : "l"(p));
    return a;
}
#define CP_ASYNC16(dst, src) \
    asm volatile("cp.async.ca.shared.global [%0], [%1], 16;" :: "r"(dst), "l"(src))
#define CP_COMMIT() asm volatile("cp.async.commit_group;" ::: "memory")
#define CP_WAIT(n)  asm volatile("cp.async.wait_group %0;" :: "n"(n) : "memory")

__device__ __forceinline__ void ldsm4(uint32_t* r, uint32_t addr) {
    asm volatile("ldmatrix.sync.aligned.m8n8.x4.shared.b16 {%0,%1,%2,%3}, [%4];"
                 : "=r"(r[0]), "=r"(r[1]), "=r"(r[2]), "=r"(r[3]) : "r"(addr));
}
__device__ __forceinline__ void mma16816(float* d, const uint32_t* a, const uint32_t* b) {
    asm volatile(
        "mma.sync.aligned.m16n8k16.row.col.f32.bf16.bf16.f32 "
        "{%0,%1,%2,%3}, {%4,%5,%6,%7}, {%8,%9}, {%0,%1,%2,%3};"
        : "+f"(d[0]), "+f"(d[1]), "+f"(d[2]), "+f"(d[3])
        : "r"(a[0]), "r"(a[1]), "r"(a[2]), "r"(a[3]), "r"(b[0]), "r"(b[1]));
}

// ---------------- mask handling ----------------------------------------------
__global__ void detect_mask(const unsigned* __restrict__ m) {
    __shared__ int f[4];
    int t = threadIdx.x;
    if (t < 4) f[t] = 0;
    __syncthreads();
    int fu8 = 0, ff16 = 0, fbf16 = 0, ff32 = 0;
    for (int i = t; i < 4096; i += 256) {
        unsigned w = m[i];
        if (w == 0x3F800000u) ff32 = 1;
        if (w == 0x3F803F80u || w == 0x00003F80u) fbf16 = 1;
        if (w == 0x3C003C00u || w == 0x00003C00u || w == 0x3C000000u) ff16 = 1;
        if ((w & 0xFEFEFEFEu) == 0u && w > 1u) fu8 = 1;
    }
    if (fu8)  atomicOr(&f[0], 1);
    if (ff16) atomicOr(&f[1], 1);
    if (fbf16) atomicOr(&f[2], 1);
    if (ff32) atomicOr(&f[3], 1);
    __syncthreads();
    if (t == 0) {
        int mode;
        if (f[1]) mode = 4;
        else if (f[2]) mode = 3;
        else if (f[3]) mode = 2;
        else if (f[0]) mode = 1;
        else mode = 0;
        g_mode = mode;
    }
}

__global__ void pack_mask(const void* __restrict__ mp) {
    int idx = blockIdx.x * blockDim.x + threadIdx.x;
    int mode = g_mode;
    long base = (long)idx * 32;
    unsigned bits = 0;
    if (mode == 0) {
        const int* p = (const int*)mp;
        #pragma unroll 8
        for (int j = 0; j < 32; j++) if (p[base + j] != 0) bits |= 1u << j;
    } else if (mode == 1) {
        const unsigned char* p = (const unsigned char*)mp;
        #pragma unroll 8
        for (int j = 0; j < 32; j++) if (p[base + j] != 0) bits |= 1u << j;
    } else if (mode == 2) {
        const float* p = (const float*)mp;
        #pragma unroll 8
        for (int j = 0; j < 32; j++) if (p[base + j] != 0.0f) bits |= 1u << j;
    } else {
        const unsigned short* p = (const unsigned short*)mp;
        #pragma unroll 8
        for (int j = 0; j < 32; j++) if (p[base + j] != 0) bits |= 1u << j;
    }
    g_mbits[idx] = bits;
}

// ---------------- fp32 -> bf16 hi/lo split -----------------------------------
__global__ void split_bf16(const float4* __restrict__ x,
                           __nv_bfloat16* __restrict__ hi,
                           __nv_bfloat16* __restrict__ lo, int n4) {
    int i = blockIdx.x * blockDim.x + threadIdx.x;
    if (i >= n4) return;
    float4 v = x[i];
    float f[4] = {v.x, v.y, v.z, v.w};
    __nv_bfloat16 h[4], l[4];
    #pragma unroll
    for (int j = 0; j < 4; j++) {
        h[j] = __float2bfloat16_rn(f[j]);
        l[j] = __float2bfloat16_rn(f[j] - __bfloat162float(h[j]));
    }
    __nv_bfloat162* hp = (__nv_bfloat162*)hi + 2 * i;
    __nv_bfloat162* lp = (__nv_bfloat162*)lo + 2 * i;
    hp[0] = __nv_bfloat162{h[0], h[1]}; hp[1] = __nv_bfloat162{h[2], h[3]};
    lp[0] = __nv_bfloat162{l[0], l[1]}; lp[1] = __nv_bfloat162{l[2], l[3]};
}

// ---------------- mma.sync GEMM: Y[M,1024] = X @ W^T + b ---------------------
// CTA 128x128, BK=32, 8 warps (2x4), warp tile 64x32, 3-term bf16 split.
// smem per stage: 4 tiles (Ahi,Alo,Bhi,Blo) of 128 rows x 40 bf16 (80B, padded).
#define LDA_B   80          // padded row stride in bytes (40 bf16)
#define TILE_B  10240       // 128 * 80
#define STAGE_B 40960       // 4 tiles
#define NITER   (DMODEL / 32)

__global__ void __launch_bounds__(256) gemm_mma(
    const __nv_bfloat16* __restrict__ Ahi, const __nv_bfloat16* __restrict__ Alo,
    const __nv_bfloat16* __restrict__ Whi, const __nv_bfloat16* __restrict__ Wlo,
    const float* __restrict__ bias, float* __restrict__ Y)
{
    extern __shared__ char sm[];
    uint32_t smb = smem_u32(sm);
    int tid = threadIdx.x, lane = tid & 31, wid = tid >> 5;
    int wm = wid >> 2, wn = wid & 3;          // 2 x 4 warp grid
    int m0 = blockIdx.y * 128, n0 = blockIdx.x * 128;

    float acc[4][4][4];
    #pragma unroll
    for (int i = 0; i < 4; i++)
        #pragma unroll
        for (int j = 0; j < 4; j++)
            #pragma unroll
            for (int q = 0; q < 4; q++) acc[i][j][q] = 0.0f;

    // per-thread copy slots: 2 chunks of 16B per tile
    int c_row0 = tid >> 2, c_c8_0 = tid & 3;
    int idx1 = tid + 256;
    int c_row1 = idx1 >> 2, c_c8_1 = idx1 & 3;

    // prologue: stage 0
    {
        uint32_t st = smb;
        uint32_t d0 = st + c_row0 * LDA_B + c_c8_0 * 16;
        uint32_t d1 = st + c_row1 * LDA_B + c_c8_1 * 16;
        size_t ga0 = (size_t)(m0 + c_row0) * DMODEL + c_c8_0 * 8;
        size_t ga1 = (size_t)(m0 + c_row1) * DMODEL + c_c8_1 * 8;
        size_t gb0 = (size_t)(n0 + c_row0) * DMODEL + c_c8_0 * 8;
        size_t gb1 = (size_t)(n0 + c_row1) * DMODEL + c_c8_1 * 8;
        CP_ASYNC16(d0,             Ahi + ga0);
        CP_ASYNC16(d1,             Ahi + ga1);
        CP_ASYNC16(d0 + TILE_B,    Alo + ga0);
        CP_ASYNC16(d1 + TILE_B,    Alo + ga1);
        CP_ASYNC16(d0 + 2*TILE_B,  Whi + gb0);
        CP_ASYNC16(d1 + 2*TILE_B,  Whi + gb1);
        CP_ASYNC16(d0 + 3*TILE_B,  Wlo + gb0);
        CP_ASYNC16(d1 + 3*TILE_B,  Wlo + gb1);
        CP_COMMIT();
    }

    for (int it = 0; it < NITER; it++) {
        int s = it & 1;
        if (it + 1 < NITER) {
            int k0 = (it + 1) * 32;
            uint32_t st = smb + (s ^ 1) * STAGE_B;
            uint32_t d0 = st + c_row0 * LDA_B + c_c8_0 * 16;
            uint32_t d1 = st + c_row1 * LDA_B + c_c8_1 * 16;
            size_t ga0 = (size_t)(m0 + c_row0) * DMODEL + k0 + c_c8_0 * 8;
            size_t ga1 = (size_t)(m0 + c_row1) * DMODEL + k0 + c_c8_1 * 8;
            size_t gb0 = (size_t)(n0 + c_row0) * DMODEL + k0 + c_c8_0 * 8;
            size_t gb1 = (size_t)(n0 + c_row1) * DMODEL + k0 + c_c8_1 * 8;
            CP_ASYNC16(d0,             Ahi + ga0);
            CP_ASYNC16(d1,             Ahi + ga1);
            CP_ASYNC16(d0 + TILE_B,    Alo + ga0);
            CP_ASYNC16(d1 + TILE_B,    Alo + ga1);
            CP_ASYNC16(d0 + 2*TILE_B,  Whi + gb0);
            CP_ASYNC16(d1 + 2*TILE_B,  Whi + gb1);
            CP_ASYNC16(d0 + 3*TILE_B,  Wlo + gb0);
            CP_ASYNC16(d1 + 3*TILE_B,  Wlo + gb1);
            CP_COMMIT();
            CP_WAIT(1);
        } else {
            CP_WAIT(0);
        }
        __syncthreads();

        uint32_t st = smb + s * STAGE_B;
        // ldmatrix bases
        uint32_t aA = st + (wm * 64 + (lane & 15)) * LDA_B + (lane >> 4) * 16;
        uint32_t aB = st + 2 * TILE_B + (wn * 32 + (lane & 7)) * LDA_B + (lane >> 3) * 16;

        // B fragments for full BK=32: regs [0,1]=kstep0, [2,3]=kstep1
        uint32_t bh[4][4], bl[4][4];
        #pragma unroll
        for (int ni = 0; ni < 4; ni++) {
            ldsm4(bh[ni], aB + ni * 8 * LDA_B);
            ldsm4(bl[ni], aB + ni * 8 * LDA_B + TILE_B);
        }
        #pragma unroll
        for (int ks = 0; ks < 2; ks++) {
            uint32_t ah[4][4], al[4][4];
            #pragma unroll
            for (int mi = 0; mi < 4; mi++) {
                ldsm4(ah[mi], aA + mi * 16 * LDA_B + ks * 32);
                ldsm4(al[mi], aA + mi * 16 * LDA_B + ks * 32 + TILE_B);
            }
            #pragma unroll
            for (int mi = 0; mi < 4; mi++)
                #pragma unroll
                for (int ni = 0; ni < 4; ni++) {
                    mma16816(acc[mi][ni], ah[mi], &bh[ni][2 * ks]);
                    mma16816(acc[mi][ni], ah[mi], &bl[ni][2 * ks]);
                    mma16816(acc[mi][ni], al[mi], &bh[ni][2 * ks]);
                }
        }
        __syncthreads();
    }

    // epilogue: acc fragment (m16n8): d0=(r,c) d1=(r,c+1) d2=(r+8,c) d3=(r+8,c+1)
    int er = lane >> 2, ec = (lane & 3) * 2;
    #pragma unroll
    for (int mi = 0; mi < 4; mi++) {
        #pragma unroll
        for (int ni = 0; ni < 4; ni++) {
            int row = m0 + wm * 64 + mi * 16 + er;
            int col = n0 + wn * 32 + ni * 8 + ec;
            float b0 = bias[col], b1 = bias[col + 1];
            float2 v0 = {acc[mi][ni][0] + b0, acc[mi][ni][1] + b1};
            float2 v1 = {acc[mi][ni][2] + b0, acc[mi][ni][3] + b1};
            *(float2*)(Y + (size_t)row * DMODEL + col) = v0;
            *(float2*)(Y + (size_t)(row + 8) * DMODEL + col) = v1;
        }
    }
}

// ---------------- fused flash attention (unchanged, fp32 SIMT) --------------
__global__ void __launch_bounds__(128) flash_attn() {
    __shared__ float Ks[32][68];
    __shared__ float Vs[32][68];
    __shared__ float Ss[128][33];

    int tid = threadIdx.x;
    int q0 = blockIdx.x << 7;
    int h = blockIdx.y, b = blockIdx.z;
    int row = q0 + tid;

    const float* qp = g_Q + ((size_t)(b * SEQ + row)) * DMODEL + h * DVDIM;
    float qr[64];
    #pragma unroll
    for (int i = 0; i < 16; i++) {
        float4 t4 = *(const float4*)(qp + i * 4);
        qr[4 * i + 0] = t4.x; qr[4 * i + 1] = t4.y;
        qr[4 * i + 2] = t4.z; qr[4 * i + 3] = t4.w;
    }
    float o[64];
    #pragma unroll
    for (int d = 0; d < 64; d++) o[d] = 0.0f;
    float mv = -1e30f, l = 0.0f;

    int jr = tid >> 2;
    int c0 = (tid & 3) << 4;
    const float* kb = g_K + ((size_t)b * SEQ) * DMODEL + h * DVDIM;
    const float* vb = g_V + ((size_t)b * SEQ) * DMODEL + h * DVDIM;
    const unsigned* mrow = g_mbits + (size_t)row * MWORDS;

    for (int k0 = 0; k0 < SEQ; k0 += 32) {
        const float* kp = kb + (size_t)(k0 + jr) * DMODEL + c0;
        const float* vp = vb + (size_t)(k0 + jr) * DMODEL + c0;
        #pragma unroll
        for (int f = 0; f < 4; f++) {
            *(float4*)&Ks[jr][c0 + 4 * f] = *(const float4*)(kp + 4 * f);
            *(float4*)&Vs[jr][c0 + 4 * f] = *(const float4*)(vp + 4 * f);
        }
        unsigned mw = mrow[k0 >> 5];
        __syncthreads();

        float mt = mv;
        for (int j = 0; j < 32; j++) {
            float a0 = 0.f, a1 = 0.f, a2 = 0.f, a3 = 0.f;
            #pragma unroll
            for (int k = 0; k < 64; k += 16) {
                float4 u0 = *(const float4*)&Ks[j][k];
                float4 u1 = *(const float4*)&Ks[j][k + 4];
                float4 u2 = *(const float4*)&Ks[j][k + 8];
                float4 u3 = *(const float4*)&Ks[j][k + 12];
                a0 = fmaf(qr[k + 0],  u0.x, a0); a0 = fmaf(qr[k + 1],  u0.y, a0);
                a0 = fmaf(qr[k + 2],  u0.z, a0); a0 = fmaf(qr[k + 3],  u0.w, a0);
                a1 = fmaf(qr[k + 4],  u1.x, a1); a1 = fmaf(qr[k + 5],  u1.y, a1);
                a1 = fmaf(qr[k + 6],  u1.z, a1); a1 = fmaf(qr[k + 7],  u1.w, a1);
                a2 = fmaf(qr[k + 8],  u2.x, a2); a2 = fmaf(qr[k + 9],  u2.y, a2);
                a2 = fmaf(qr[k + 10], u2.z, a2); a2 = fmaf(qr[k + 11], u2.w, a2);
                a3 = fmaf(qr[k + 12], u3.x, a3); a3 = fmaf(qr[k + 13], u3.y, a3);
                a3 = fmaf(qr[k + 14], u3.z, a3); a3 = fmaf(qr[k + 15], u3.w, a3);
            }
            float sum = (a0 + a1) + (a2 + a3);
            float sv = ((mw >> j) & 1u) ? 1e-9f : sum * 0.125f;
            Ss[tid][j] = sv;
            mt = fmaxf(mt, sv);
        }

        float alpha = __expf(mv - mt);
        mv = mt;
        l *= alpha;
        #pragma unroll
        for (int d = 0; d < 64; d++) o[d] *= alpha;

        for (int j = 0; j < 32; j++) {
            float p = __expf(Ss[tid][j] - mt);
            l += p;
            #pragma unroll
            for (int d = 0; d < 64; d += 4) {
                float4 u = *(const float4*)&Vs[j][d];
                o[d + 0] = fmaf(p, u.x, o[d + 0]);
                o[d + 1] = fmaf(p, u.y, o[d + 1]);
                o[d + 2] = fmaf(p, u.z, o[d + 2]);
                o[d + 3] = fmaf(p, u.w, o[d + 3]);
            }
        }
        __syncthreads();
    }

    float inv = 1.0f / l;
    float* op = g_C + ((size_t)(b * SEQ + row)) * DMODEL + h * DVDIM;
    #pragma unroll
    for (int d = 0; d < 64; d += 4) {
        float4 r;
        r.x = o[d + 0] * inv; r.y = o[d + 1] * inv;
        r.z = o[d + 2] * inv; r.w = o[d + 3] * inv;
        *(float4*)(op + d) = r;
    }
}

// ---------------- launch ------------------------------------------------------
extern "C" void kernel_launch(void* const* d_in, const int* in_sizes, int n_in,
                              void* d_out, int out_size)
{
    const float* q    = (const float*)d_in[0];
    const float* k    = (const float*)d_in[1];
    const float* v    = (const float*)d_in[2];
    const void*  mask = d_in[3];
    const float* Wq   = (const float*)d_in[4];
    const float* bq   = (const float*)d_in[5];
    const float* Wk   = (const float*)d_in[6];
    const float* bk   = (const float*)d_in[7];
    const float* Wv   = (const float*)d_in[8];
    const float* bv   = (const float*)d_in[9];
    const float* Wo   = (const float*)d_in[10];
    const float* bo   = (const float*)d_in[11];

    float *gq, *gk, *gv, *gc;
    __nv_bfloat16 *ahi, *alo, *whi, *wlo;
    cudaGetSymbolAddress((void**)&gq, g_Q);
    cudaGetSymbolAddress((void**)&gk, g_K);
    cudaGetSymbolAddress((void**)&gv, g_V);
    cudaGetSymbolAddress((void**)&gc, g_C);
    cudaGetSymbolAddress((void**)&ahi, g_ahi);
    cudaGetSymbolAddress((void**)&alo, g_alo);
    cudaGetSymbolAddress((void**)&whi, g_whi);
    cudaGetSymbolAddress((void**)&wlo, g_wlo);

    static bool attr_set = false;
    if (!attr_set) {
        cudaFuncSetAttribute(gemm_mma, cudaFuncAttributeMaxDynamicSharedMemorySize,
                             2 * STAGE_B);
        attr_set = true;
    }
    const int smem_bytes = 2 * STAGE_B;
    const int nACT4 = MROWS * DMODEL / 4;
    const int nW4   = DMODEL * DMODEL / 4;
    dim3 gg(DMODEL / 128, MROWS / 128);   // (8, 64)

    detect_mask<<<1, 256>>>((const unsigned*)mask);
    pack_mask<<<(SEQ * MWORDS) / 256, 256>>>(mask);

    split_bf16<<<nACT4 / 256, 256>>>((const float4*)q, ahi, alo, nACT4);
    split_bf16<<<nW4 / 256, 256>>>((const float4*)Wq, whi, wlo, nW4);
    gemm_mma<<<gg, 256, smem_bytes>>>(ahi, alo, whi, wlo, bq, gq);

    split_bf16<<<nACT4 / 256, 256>>>((const float4*)k, ahi, alo, nACT4);
    split_bf16<<<nW4 / 256, 256>>>((const float4*)Wk, whi, wlo, nW4);
    gemm_mma<<<gg, 256, smem_bytes>>>(ahi, alo, whi, wlo, bk, gk);

    split_bf16<<<nACT4 / 256, 256>>>((const float4*)v, ahi, alo, nACT4);
    split_bf16<<<nW4 / 256, 256>>>((const float4*)Wv, whi, wlo, nW4);
    gemm_mma<<<gg, 256, smem_bytes>>>(ahi, alo, whi, wlo, bv, gv);

    flash_attn<<<dim3(SEQ / 128, NHEAD, NBATCH), 128>>>();

    split_bf16<<<nACT4 / 256, 256>>>((const float4*)gc, ahi, alo, nACT4);
    split_bf16<<<nW4 / 256, 256>>>((const float4*)Wo, whi, wlo, nW4);
    gemm_mma<<<gg, 256, smem_bytes>>>(ahi, alo, whi, wlo, bo, (float*)d_out);
}

// round 4
// speedup vs baseline: 3.5099x; 2.7183x over previous
#include <cuda_runtime.h>
#include <cuda_bf16.h>
#include <cuda_fp16.h>
#include <cstdint>

#define SEQ    2048
#define DMODEL 1024
#define NHEAD  16
#define DVDIM  64
#define NBATCH 4
#define MROWS  (NBATCH * SEQ)   // 8192
#define MWORDS (SEQ / 32)
#define LOG2E  1.4426950408889634f

// ---------------- scratch (device globals) ----------------------------------
__device__ __align__(16) __half g_qhi[MROWS * DMODEL];
__device__ __align__(16) __half g_qlo[MROWS * DMODEL];
__device__ __align__(16) __half g_khi[MROWS * DMODEL];
__device__ __align__(16) __half g_klo[MROWS * DMODEL];
__device__ __align__(16) __half g_vhi[MROWS * DMODEL];
__device__ __align__(16) __nv_bfloat16 g_ahi[MROWS * DMODEL];
__device__ __align__(16) __nv_bfloat16 g_alo[MROWS * DMODEL];
__device__ __align__(16) __nv_bfloat16 g_whi[DMODEL * DMODEL];
__device__ __align__(16) __nv_bfloat16 g_wlo[DMODEL * DMODEL];
__device__ unsigned g_mbits[SEQ * MWORDS];
__device__ int g_mode;

// ---------------- PTX helpers (sm_103-safe) ---------------------------------
__device__ __forceinline__ uint32_t smem_u32(const void* p) {
    uint32_t a;
    asm("{ .reg .u64 t; cvta.to.shared.u64 t, %1; cvt.u32.u64 %0, t; }" : "=r"(a) : "l"(p));
    return a;
}
#define CP_ASYNC16(dst, src) \
    asm volatile("cp.async.ca.shared.global [%0], [%1], 16;" :: "r"(dst), "l"(src))
#define CP_COMMIT() asm volatile("cp.async.commit_group;" ::: "memory")
#define CP_WAIT(n)  asm volatile("cp.async.wait_group %0;" :: "n"(n) : "memory")

__device__ __forceinline__ void ldsm4(uint32_t* r, uint32_t addr) {
    asm volatile("ldmatrix.sync.aligned.m8n8.x4.shared.b16 {%0,%1,%2,%3}, [%4];"
                 : "=r"(r[0]), "=r"(r[1]), "=r"(r[2]), "=r"(r[3]) : "r"(addr));
}
__device__ __forceinline__ void ldsm2(uint32_t* r, uint32_t addr) {
    asm volatile("ldmatrix.sync.aligned.m8n8.x2.shared.b16 {%0,%1}, [%2];"
                 : "=r"(r[0]), "=r"(r[1]) : "r"(addr));
}
__device__ __forceinline__ void ldsm4t(uint32_t* r, uint32_t addr) {
    asm volatile("ldmatrix.sync.aligned.m8n8.x4.trans.shared.b16 {%0,%1,%2,%3}, [%4];"
                 : "=r"(r[0]), "=r"(r[1]), "=r"(r[2]), "=r"(r[3]) : "r"(addr));
}
__device__ __forceinline__ void mma_bf16(float* d, const uint32_t* a, const uint32_t* b) {
    asm volatile(
        "mma.sync.aligned.m16n8k16.row.col.f32.bf16.bf16.f32 "
        "{%0,%1,%2,%3}, {%4,%5,%6,%7}, {%8,%9}, {%0,%1,%2,%3};"
        : "+f"(d[0]), "+f"(d[1]), "+f"(d[2]), "+f"(d[3])
        : "r"(a[0]), "r"(a[1]), "r"(a[2]), "r"(a[3]), "r"(b[0]), "r"(b[1]));
}
__device__ __forceinline__ void mma_f16(float* d, const uint32_t* a, const uint32_t* b) {
    asm volatile(
        "mma.sync.aligned.m16n8k16.row.col.f32.f16.f16.f32 "
        "{%0,%1,%2,%3}, {%4,%5,%6,%7}, {%8,%9}, {%0,%1,%2,%3};"
        : "+f"(d[0]), "+f"(d[1]), "+f"(d[2]), "+f"(d[3])
        : "r"(a[0]), "r"(a[1]), "r"(a[2]), "r"(a[3]), "r"(b[0]), "r"(b[1]));
}
__device__ __forceinline__ float ex2f(float x) {
    float r; asm("ex2.approx.f32 %0, %1;" : "=f"(r) : "f"(x)); return r;
}
__device__ __forceinline__ uint32_t packh2(float lo, float hi) {
    uint32_t d; asm("cvt.rn.f16x2.f32 %0, %1, %2;" : "=r"(d) : "f"(hi), "f"(lo)); return d;
}

// ---------------- mask handling ----------------------------------------------
__global__ void detect_mask(const unsigned* __restrict__ m) {
    __shared__ int f[4];
    int t = threadIdx.x;
    if (t < 4) f[t] = 0;
    __syncthreads();
    int fu8 = 0, ff16 = 0, fbf16 = 0, ff32 = 0;
    for (int i = t; i < 4096; i += 256) {
        unsigned w = m[i];
        if (w == 0x3F800000u) ff32 = 1;
        if (w == 0x3F803F80u || w == 0x00003F80u) fbf16 = 1;
        if (w == 0x3C003C00u || w == 0x00003C00u || w == 0x3C000000u) ff16 = 1;
        if ((w & 0xFEFEFEFEu) == 0u && w > 1u) fu8 = 1;
    }
    if (fu8)  atomicOr(&f[0], 1);
    if (ff16) atomicOr(&f[1], 1);
    if (fbf16) atomicOr(&f[2], 1);
    if (ff32) atomicOr(&f[3], 1);
    __syncthreads();
    if (t == 0) {
        int mode;
        if (f[1]) mode = 4;
        else if (f[2]) mode = 3;
        else if (f[3]) mode = 2;
        else if (f[0]) mode = 1;
        else mode = 0;
        g_mode = mode;
    }
}

__global__ void pack_mask(const void* __restrict__ mp) {
    int idx = blockIdx.x * blockDim.x + threadIdx.x;
    int mode = g_mode;
    long base = (long)idx * 32;
    unsigned bits = 0;
    if (mode == 0) {
        const int* p = (const int*)mp;
        #pragma unroll 8
        for (int j = 0; j < 32; j++) if (p[base + j] != 0) bits |= 1u << j;
    } else if (mode == 1) {
        const unsigned char* p = (const unsigned char*)mp;
        #pragma unroll 8
        for (int j = 0; j < 32; j++) if (p[base + j] != 0) bits |= 1u << j;
    } else if (mode == 2) {
        const float* p = (const float*)mp;
        #pragma unroll 8
        for (int j = 0; j < 32; j++) if (p[base + j] != 0.0f) bits |= 1u << j;
    } else {
        const unsigned short* p = (const unsigned short*)mp;
        #pragma unroll 8
        for (int j = 0; j < 32; j++) if (p[base + j] != 0) bits |= 1u << j;
    }
    g_mbits[idx] = bits;
}

// ---------------- fp32 -> bf16 hi/lo split (GEMM A inputs) -------------------
__global__ void split_bf16(const float4* __restrict__ x,
                           __nv_bfloat16* __restrict__ hi,
                           __nv_bfloat16* __restrict__ lo, int n4) {
    int i = blockIdx.x * blockDim.x + threadIdx.x;
    if (i >= n4) return;
    float4 v = x[i];
    float f[4] = {v.x, v.y, v.z, v.w};
    __nv_bfloat16 h[4], l[4];
    #pragma unroll
    for (int j = 0; j < 4; j++) {
        h[j] = __float2bfloat16_rn(f[j]);
        l[j] = __float2bfloat16_rn(f[j] - __bfloat162float(h[j]));
    }
    __nv_bfloat162* hp = (__nv_bfloat162*)hi + 2 * i;
    __nv_bfloat162* lp = (__nv_bfloat162*)lo + 2 * i;
    hp[0] = __nv_bfloat162{h[0], h[1]}; hp[1] = __nv_bfloat162{h[2], h[3]};
    lp[0] = __nv_bfloat162{l[0], l[1]}; lp[1] = __nv_bfloat162{l[2], l[3]};
}

// ---------------- mma.sync GEMM: Y[M,1024] = X @ W^T + b ---------------------
// modes: 0 = fp32 out; 1 = fp16 hi/lo out with scale; 2 = fp16 hi only.
#define LDA_B   80
#define TILE_B  10240
#define STAGE_B 40960
#define NITER   (DMODEL / 32)

__global__ void __launch_bounds__(256) gemm_mma(
    const __nv_bfloat16* __restrict__ Ahi, const __nv_bfloat16* __restrict__ Alo,
    const __nv_bfloat16* __restrict__ Whi, const __nv_bfloat16* __restrict__ Wlo,
    const float* __restrict__ bias, float* __restrict__ Y,
    __half* __restrict__ H1, __half* __restrict__ H2, int mode, float scale)
{
    extern __shared__ char sm[];
    uint32_t smb = smem_u32(sm);
    int tid = threadIdx.x, lane = tid & 31, wid = tid >> 5;
    int wm = wid >> 2, wn = wid & 3;
    int m0 = blockIdx.y * 128, n0 = blockIdx.x * 128;

    float acc[4][4][4];
    #pragma unroll
    for (int i = 0; i < 4; i++)
        #pragma unroll
        for (int j = 0; j < 4; j++)
            #pragma unroll
            for (int q = 0; q < 4; q++) acc[i][j][q] = 0.0f;

    int c_row0 = tid >> 2, c_c8_0 = tid & 3;
    int idx1 = tid + 256;
    int c_row1 = idx1 >> 2, c_c8_1 = idx1 & 3;

    {
        uint32_t st = smb;
        uint32_t d0 = st + c_row0 * LDA_B + c_c8_0 * 16;
        uint32_t d1 = st + c_row1 * LDA_B + c_c8_1 * 16;
        size_t ga0 = (size_t)(m0 + c_row0) * DMODEL + c_c8_0 * 8;
        size_t ga1 = (size_t)(m0 + c_row1) * DMODEL + c_c8_1 * 8;
        size_t gb0 = (size_t)(n0 + c_row0) * DMODEL + c_c8_0 * 8;
        size_t gb1 = (size_t)(n0 + c_row1) * DMODEL + c_c8_1 * 8;
        CP_ASYNC16(d0,             Ahi + ga0);
        CP_ASYNC16(d1,             Ahi + ga1);
        CP_ASYNC16(d0 + TILE_B,    Alo + ga0);
        CP_ASYNC16(d1 + TILE_B,    Alo + ga1);
        CP_ASYNC16(d0 + 2*TILE_B,  Whi + gb0);
        CP_ASYNC16(d1 + 2*TILE_B,  Whi + gb1);
        CP_ASYNC16(d0 + 3*TILE_B,  Wlo + gb0);
        CP_ASYNC16(d1 + 3*TILE_B,  Wlo + gb1);
        CP_COMMIT();
    }

    for (int it = 0; it < NITER; it++) {
        int s = it & 1;
        if (it + 1 < NITER) {
            int k0 = (it + 1) * 32;
            uint32_t st = smb + (s ^ 1) * STAGE_B;
            uint32_t d0 = st + c_row0 * LDA_B + c_c8_0 * 16;
            uint32_t d1 = st + c_row1 * LDA_B + c_c8_1 * 16;
            size_t ga0 = (size_t)(m0 + c_row0) * DMODEL + k0 + c_c8_0 * 8;
            size_t ga1 = (size_t)(m0 + c_row1) * DMODEL + k0 + c_c8_1 * 8;
            size_t gb0 = (size_t)(n0 + c_row0) * DMODEL + k0 + c_c8_0 * 8;
            size_t gb1 = (size_t)(n0 + c_row1) * DMODEL + k0 + c_c8_1 * 8;
            CP_ASYNC16(d0,             Ahi + ga0);
            CP_ASYNC16(d1,             Ahi + ga1);
            CP_ASYNC16(d0 + TILE_B,    Alo + ga0);
            CP_ASYNC16(d1 + TILE_B,    Alo + ga1);
            CP_ASYNC16(d0 + 2*TILE_B,  Whi + gb0);
            CP_ASYNC16(d1 + 2*TILE_B,  Whi + gb1);
            CP_ASYNC16(d0 + 3*TILE_B,  Wlo + gb0);
            CP_ASYNC16(d1 + 3*TILE_B,  Wlo + gb1);
            CP_COMMIT();
            CP_WAIT(1);
        } else {
            CP_WAIT(0);
        }
        __syncthreads();

        uint32_t st = smb + s * STAGE_B;
        uint32_t aA = st + (wm * 64 + (lane & 15)) * LDA_B + (lane >> 4) * 16;
        uint32_t aB = st + 2 * TILE_B + (wn * 32 + (lane & 7)) * LDA_B + (lane >> 3) * 16;

        uint32_t bh[4][4], bl[4][4];
        #pragma unroll
        for (int ni = 0; ni < 4; ni++) {
            ldsm4(bh[ni], aB + ni * 8 * LDA_B);
            ldsm4(bl[ni], aB + ni * 8 * LDA_B + TILE_B);
        }
        #pragma unroll
        for (int ks = 0; ks < 2; ks++) {
            uint32_t ah[4][4], al[4][4];
            #pragma unroll
            for (int mi = 0; mi < 4; mi++) {
                ldsm4(ah[mi], aA + mi * 16 * LDA_B + ks * 32);
                ldsm4(al[mi], aA + mi * 16 * LDA_B + ks * 32 + TILE_B);
            }
            #pragma unroll
            for (int mi = 0; mi < 4; mi++)
                #pragma unroll
                for (int ni = 0; ni < 4; ni++) {
                    mma_bf16(acc[mi][ni], ah[mi], &bh[ni][2 * ks]);
                    mma_bf16(acc[mi][ni], ah[mi], &bl[ni][2 * ks]);
                    mma_bf16(acc[mi][ni], al[mi], &bh[ni][2 * ks]);
                }
        }
        __syncthreads();
    }

    int er = lane >> 2, ec = (lane & 3) * 2;
    #pragma unroll
    for (int mi = 0; mi < 4; mi++) {
        #pragma unroll
        for (int ni = 0; ni < 4; ni++) {
            int row = m0 + wm * 64 + mi * 16 + er;
            int col = n0 + wn * 32 + ni * 8 + ec;
            float b0 = bias[col], b1 = bias[col + 1];
            float x00 = acc[mi][ni][0] + b0, x01 = acc[mi][ni][1] + b1;
            float x10 = acc[mi][ni][2] + b0, x11 = acc[mi][ni][3] + b1;
            if (mode == 0) {
                *(float2*)(Y + (size_t)row * DMODEL + col) = float2{x00, x01};
                *(float2*)(Y + (size_t)(row + 8) * DMODEL + col) = float2{x10, x11};
            } else {
                x00 *= scale; x01 *= scale; x10 *= scale; x11 *= scale;
                __half h00 = __float2half_rn(x00), h01 = __float2half_rn(x01);
                __half h10 = __float2half_rn(x10), h11 = __float2half_rn(x11);
                *(__half2*)(H1 + (size_t)row * DMODEL + col) = __half2{h00, h01};
                *(__half2*)(H1 + (size_t)(row + 8) * DMODEL + col) = __half2{h10, h11};
                if (mode == 1) {
                    __half l00 = __float2half_rn(x00 - __half2float(h00));
                    __half l01 = __float2half_rn(x01 - __half2float(h01));
                    __half l10 = __float2half_rn(x10 - __half2float(h10));
                    __half l11 = __float2half_rn(x11 - __half2float(h11));
                    *(__half2*)(H2 + (size_t)row * DMODEL + col) = __half2{l00, l01};
                    *(__half2*)(H2 + (size_t)(row + 8) * DMODEL + col) = __half2{l10, l11};
                }
            }
        }
    }
}

// ---------------- fused MMA flash attention ----------------------------------
// CTA: 128 q-rows of one (b,h). 4 warps x 32 rows. 64-key tiles, cp.async 2-stage.
// Q pre-scaled by 0.125*log2e; softmax in base 2 (ex2.approx).
#define FSTR 72
#define MASKVAL 1.4426950409e-9f

__global__ void __launch_bounds__(128) flash_mma(
    const __half* __restrict__ qhi, const __half* __restrict__ qlo,
    const __half* __restrict__ khi, const __half* __restrict__ klo,
    const __half* __restrict__ vhi,
    __nv_bfloat16* __restrict__ chi, __nv_bfloat16* __restrict__ clo)
{
    extern __shared__ __half sh[];
    // half-element offsets
    const int O_QHI = 0, O_QLO = 9216;
    const int O_KH[2] = {18432, 27648};
    const int O_KL[2] = {23040, 32256};
    const int O_V[2]  = {36864, 41472};
    uint32_t sb = smem_u32(sh);

    int tid = threadIdx.x, lane = tid & 31, wm = tid >> 5;
    int q0 = blockIdx.x * 128, h = blockIdx.y, b = blockIdx.z;
    size_t rowbase = (size_t)b * SEQ;
    int r4 = lane >> 2, c2 = lane & 3;

    // Q tile load (hi+lo): 128 rows x 64 halves
    {
        const __half* qh = qhi + (rowbase + q0) * DMODEL + h * 64;
        const __half* ql = qlo + (rowbase + q0) * DMODEL + h * 64;
        #pragma unroll
        for (int c = tid; c < 1024; c += 128) {
            int r = c >> 3, dc = c & 7;
            CP_ASYNC16(sb + (O_QHI + r * FSTR + dc * 8) * 2, qh + (size_t)r * DMODEL + dc * 8);
            CP_ASYNC16(sb + (O_QLO + r * FSTR + dc * 8) * 2, ql + (size_t)r * DMODEL + dc * 8);
        }
        CP_COMMIT();
    }
    const __half* kbh = khi + rowbase * DMODEL + h * 64;
    const __half* kbl = klo + rowbase * DMODEL + h * 64;
    const __half* vb  = vhi + rowbase * DMODEL + h * 64;

    // K/V tile issue
    auto issue_kv = [&](int t) {
        int st = t & 1;
        int k0 = t * 64;
        #pragma unroll
        for (int c = tid; c < 512; c += 128) {
            int r = c >> 3, dc = c & 7;
            size_t g = (size_t)(k0 + r) * DMODEL + dc * 8;
            CP_ASYNC16(sb + (O_KH[st] + r * FSTR + dc * 8) * 2, kbh + g);
            CP_ASYNC16(sb + (O_KL[st] + r * FSTR + dc * 8) * 2, kbl + g);
            CP_ASYNC16(sb + (O_V[st]  + r * FSTR + dc * 8) * 2, vb + g);
        }
        CP_COMMIT();
    };
    issue_kv(0);
    issue_kv(1);

    float O[2][8][4];
    #pragma unroll
    for (int mi = 0; mi < 2; mi++)
        #pragma unroll
        for (int ni = 0; ni < 8; ni++)
            #pragma unroll
            for (int q = 0; q < 4; q++) O[mi][ni][q] = 0.0f;
    float lsum[4] = {0.f, 0.f, 0.f, 0.f};
    float mrow[4] = {-1e30f, -1e30f, -1e30f, -1e30f};

    for (int t = 0; t < SEQ / 64; t++) {
        if (t < SEQ / 64 - 2) { CP_WAIT(1); } else { CP_WAIT(0); }
        __syncthreads();
        int st = t & 1;

        // mask words for this 64-key window (2 words per row, 4 rows/thread)
        uint2 mw[2][2];
        #pragma unroll
        for (int mi = 0; mi < 2; mi++)
            #pragma unroll
            for (int rr = 0; rr < 2; rr++) {
                int grow = q0 + wm * 32 + mi * 16 + r4 + rr * 8;
                mw[mi][rr] = __ldg((const uint2*)&g_mbits[(size_t)grow * MWORDS + 2 * t]);
            }

        // ---- QK^T (3-term fp16 split) ----
        float S[2][8][4];
        #pragma unroll
        for (int mi = 0; mi < 2; mi++)
            #pragma unroll
            for (int ni = 0; ni < 8; ni++)
                #pragma unroll
                for (int q = 0; q < 4; q++) S[mi][ni][q] = 0.0f;

        #pragma unroll
        for (int ks = 0; ks < 4; ks++) {
            uint32_t aH[2][4], aL[2][4];
            #pragma unroll
            for (int mi = 0; mi < 2; mi++) {
                uint32_t abase = sb + (((wm * 32 + mi * 16 + (lane & 15)) * FSTR) +
                                       (lane >> 4) * 8 + ks * 16) * 2;
                ldsm4(aH[mi], abase + O_QHI * 2);
                ldsm4(aL[mi], abase + (O_QLO - O_QHI) * 2 + O_QHI * 2);
            }
            uint32_t bH[8][2], bL[8][2];
            #pragma unroll
            for (int ni = 0; ni < 8; ni++) {
                uint32_t boff = ((ni * 8 + (lane & 7)) * FSTR + ks * 16 + ((lane >> 3) & 1) * 8) * 2;
                ldsm2(bH[ni], sb + O_KH[st] * 2 + boff);
                ldsm2(bL[ni], sb + O_KL[st] * 2 + boff);
            }
            #pragma unroll
            for (int mi = 0; mi < 2; mi++)
                #pragma unroll
                for (int ni = 0; ni < 8; ni++) {
                    mma_f16(S[mi][ni], aH[mi], bH[ni]);
                    mma_f16(S[mi][ni], aH[mi], bL[ni]);
                    mma_f16(S[mi][ni], aL[mi], bH[ni]);
                }
        }

        // ---- mask + online softmax ----
        float mnew[4] = {mrow[0], mrow[1], mrow[2], mrow[3]};
        #pragma unroll
        for (int mi = 0; mi < 2; mi++)
            #pragma unroll
            for (int ni = 0; ni < 8; ni++) {
                uint32_t w0 = (ni < 4) ? mw[mi][0].x : mw[mi][0].y;
                uint32_t w1 = (ni < 4) ? mw[mi][1].x : mw[mi][1].y;
                int shf = (ni & 3) * 8 + 2 * c2;
                if ((w0 >> shf) & 1u)       S[mi][ni][0] = MASKVAL;
                if ((w0 >> (shf + 1)) & 1u) S[mi][ni][1] = MASKVAL;
                if ((w1 >> shf) & 1u)       S[mi][ni][2] = MASKVAL;
                if ((w1 >> (shf + 1)) & 1u) S[mi][ni][3] = MASKVAL;
                mnew[mi * 2 + 0] = fmaxf(mnew[mi * 2 + 0], fmaxf(S[mi][ni][0], S[mi][ni][1]));
                mnew[mi * 2 + 1] = fmaxf(mnew[mi * 2 + 1], fmaxf(S[mi][ni][2], S[mi][ni][3]));
            }
        #pragma unroll
        for (int j = 0; j < 4; j++) {
            mnew[j] = fmaxf(mnew[j], __shfl_xor_sync(0xffffffffu, mnew[j], 1));
            mnew[j] = fmaxf(mnew[j], __shfl_xor_sync(0xffffffffu, mnew[j], 2));
        }
        float al[4];
        #pragma unroll
        for (int j = 0; j < 4; j++) {
            al[j] = ex2f(mrow[j] - mnew[j]);
            mrow[j] = mnew[j];
            lsum[j] *= al[j];
        }
        #pragma unroll
        for (int mi = 0; mi < 2; mi++)
            #pragma unroll
            for (int ni = 0; ni < 8; ni++) {
                O[mi][ni][0] *= al[mi * 2];     O[mi][ni][1] *= al[mi * 2];
                O[mi][ni][2] *= al[mi * 2 + 1]; O[mi][ni][3] *= al[mi * 2 + 1];
            }

        // p = 2^(s - m); pack into PV A-fragments
        uint32_t pa[2][4][4];
        #pragma unroll
        for (int mi = 0; mi < 2; mi++)
            #pragma unroll
            for (int ni = 0; ni < 8; ni++) {
                float p0 = ex2f(S[mi][ni][0] - mnew[mi * 2]);
                float p1 = ex2f(S[mi][ni][1] - mnew[mi * 2]);
                float p2 = ex2f(S[mi][ni][2] - mnew[mi * 2 + 1]);
                float p3 = ex2f(S[mi][ni][3] - mnew[mi * 2 + 1]);
                lsum[mi * 2]     += p0 + p1;
                lsum[mi * 2 + 1] += p2 + p3;
                int ks = ni >> 1, half = ni & 1;
                pa[mi][ks][half * 2 + 0] = packh2(p0, p1);
                pa[mi][ks][half * 2 + 1] = packh2(p2, p3);
            }

        // ---- P @ V ----
        #pragma unroll
        for (int ks = 0; ks < 4; ks++) {
            #pragma unroll
            for (int nn = 0; nn < 4; nn++) {
                uint32_t vb4[4];
                int key = ks * 16 + (lane & 7) + ((lane >> 3) & 1) * 8;
                int dim = nn * 16 + ((lane >> 4) & 1) * 8;
                ldsm4t(vb4, sb + (O_V[st] + key * FSTR + dim) * 2);
                mma_f16(O[0][2 * nn],     pa[0][ks], &vb4[0]);
                mma_f16(O[0][2 * nn + 1], pa[0][ks], &vb4[2]);
                mma_f16(O[1][2 * nn],     pa[1][ks], &vb4[0]);
                mma_f16(O[1][2 * nn + 1], pa[1][ks], &vb4[2]);
            }
        }
        __syncthreads();
        if (t + 2 < SEQ / 64) issue_kv(t + 2);
    }

    // final reduce + normalize + bf16 hi/lo ctx write
    #pragma unroll
    for (int j = 0; j < 4; j++) {
        lsum[j] += __shfl_xor_sync(0xffffffffu, lsum[j], 1);
        lsum[j] += __shfl_xor_sync(0xffffffffu, lsum[j], 2);
        lsum[j] = 1.0f / lsum[j];
    }
    #pragma unroll
    for (int mi = 0; mi < 2; mi++)
        #pragma unroll
        for (int ni = 0; ni < 8; ni++) {
            size_t grow = rowbase + q0 + wm * 32 + mi * 16 + r4;
            int col = h * 64 + ni * 8 + 2 * c2;
            float x00 = O[mi][ni][0] * lsum[mi * 2];
            float x01 = O[mi][ni][1] * lsum[mi * 2];
            float x10 = O[mi][ni][2] * lsum[mi * 2 + 1];
            float x11 = O[mi][ni][3] * lsum[mi * 2 + 1];
            __nv_bfloat16 h00 = __float2bfloat16_rn(x00), h01 = __float2bfloat16_rn(x01);
            __nv_bfloat16 h10 = __float2bfloat16_rn(x10), h11 = __float2bfloat16_rn(x11);
            *(__nv_bfloat162*)(chi + grow * DMODEL + col) = __nv_bfloat162{h00, h01};
            *(__nv_bfloat162*)(chi + (grow + 8) * DMODEL + col) = __nv_bfloat162{h10, h11};
            __nv_bfloat16 l00 = __float2bfloat16_rn(x00 - __bfloat162float(h00));
            __nv_bfloat16 l01 = __float2bfloat16_rn(x01 - __bfloat162float(h01));
            __nv_bfloat16 l10 = __float2bfloat16_rn(x10 - __bfloat162float(h10));
            __nv_bfloat16 l11 = __float2bfloat16_rn(x11 - __bfloat162float(h11));
            *(__nv_bfloat162*)(clo + grow * DMODEL + col) = __nv_bfloat162{l00, l01};
            *(__nv_bfloat162*)(clo + (grow + 8) * DMODEL + col) = __nv_bfloat162{l10, l11};
        }
}

// ---------------- launch ------------------------------------------------------
extern "C" void kernel_launch(void* const* d_in, const int* in_sizes, int n_in,
                              void* d_out, int out_size)
{
    const float* q    = (const float*)d_in[0];
    const float* k    = (const float*)d_in[1];
    const float* v    = (const float*)d_in[2];
    const void*  mask = d_in[3];
    const float* Wq   = (const float*)d_in[4];
    const float* bq   = (const float*)d_in[5];
    const float* Wk   = (const float*)d_in[6];
    const float* bk   = (const float*)d_in[7];
    const float* Wv   = (const float*)d_in[8];
    const float* bv   = (const float*)d_in[9];
    const float* Wo   = (const float*)d_in[10];
    const float* bo   = (const float*)d_in[11];

    __half *qhi, *qlo, *khi, *klo, *vhi;
    __nv_bfloat16 *ahi, *alo, *whi, *wlo;
    cudaGetSymbolAddress((void**)&qhi, g_qhi);
    cudaGetSymbolAddress((void**)&qlo, g_qlo);
    cudaGetSymbolAddress((void**)&khi, g_khi);
    cudaGetSymbolAddress((void**)&klo, g_klo);
    cudaGetSymbolAddress((void**)&vhi, g_vhi);
    cudaGetSymbolAddress((void**)&ahi, g_ahi);
    cudaGetSymbolAddress((void**)&alo, g_alo);
    cudaGetSymbolAddress((void**)&whi, g_whi);
    cudaGetSymbolAddress((void**)&wlo, g_wlo);

    const int gemm_smem = 2 * STAGE_B;
    const int flash_smem = 46080 * 2;   // 92160 B
    cudaFuncSetAttribute(gemm_mma, cudaFuncAttributeMaxDynamicSharedMemorySize, gemm_smem);
    cudaFuncSetAttribute(flash_mma, cudaFuncAttributeMaxDynamicSharedMemorySize, flash_smem);

    const int nACT4 = MROWS * DMODEL / 4;
    const int nW4   = DMODEL * DMODEL / 4;
    dim3 gg(DMODEL / 128, MROWS / 128);   // (8, 64)
    const float qscale = 0.125f * LOG2E;

    detect_mask<<<1, 256>>>((const unsigned*)mask);
    pack_mask<<<(SEQ * MWORDS) / 256, 256>>>(mask);

    // Q projection -> fp16 hi/lo, pre-scaled
    split_bf16<<<nACT4 / 256, 256>>>((const float4*)q, ahi, alo, nACT4);
    split_bf16<<<nW4 / 256, 256>>>((const float4*)Wq, whi, wlo, nW4);
    gemm_mma<<<gg, 256, gemm_smem>>>(ahi, alo, whi, wlo, bq, nullptr, qhi, qlo, 1, qscale);

    // K projection -> fp16 hi/lo
    split_bf16<<<nACT4 / 256, 256>>>((const float4*)k, ahi, alo, nACT4);
    split_bf16<<<nW4 / 256, 256>>>((const float4*)Wk, whi, wlo, nW4);
    gemm_mma<<<gg, 256, gemm_smem>>>(ahi, alo, whi, wlo, bk, nullptr, khi, klo, 1, 1.0f);

    // V projection -> fp16
    split_bf16<<<nACT4 / 256, 256>>>((const float4*)v, ahi, alo, nACT4);
    split_bf16<<<nW4 / 256, 256>>>((const float4*)Wv, whi, wlo, nW4);
    gemm_mma<<<gg, 256, gemm_smem>>>(ahi, alo, whi, wlo, bv, nullptr, vhi, nullptr, 2, 1.0f);

    // attention -> ctx in bf16 hi/lo (A operand of final GEMM)
    flash_mma<<<dim3(SEQ / 128, NHEAD, NBATCH), 128, flash_smem>>>(
        qhi, qlo, khi, klo, vhi, ahi, alo);

    // output projection -> fp32 d_out
    split_bf16<<<nW4 / 256, 256>>>((const float4*)Wo, whi, wlo, nW4);
    gemm_mma<<<gg, 256, gemm_smem>>>(ahi, alo, whi, wlo, bo, (float*)d_out,
                                     nullptr, nullptr, 0, 1.0f);
}

// round 5
// speedup vs baseline: 4.6108x; 1.3137x over previous
#include <cuda_runtime.h>
#include <cuda_fp16.h>
#include <cstdint>

#define SEQ    2048
#define DMODEL 1024
#define NHEAD  16
#define DVDIM  64
#define NBATCH 4
#define MROWS  (NBATCH * SEQ)   // 8192
#define MWORDS (SEQ / 32)
#define LOG2E  1.4426950408889634f

// ---------------- scratch (device globals) ----------------------------------
// activation splits (GEMM A operands)
__device__ __align__(16) __half g_qsh[MROWS * DMODEL];
__device__ __align__(16) __half g_qsl[MROWS * DMODEL];
__device__ __align__(16) __half g_ksh[MROWS * DMODEL];
__device__ __align__(16) __half g_ksl[MROWS * DMODEL];
__device__ __align__(16) __half g_vsh[MROWS * DMODEL];
__device__ __align__(16) __half g_vsl[MROWS * DMODEL];
// projected Q/K/V for attention
__device__ __align__(16) __half g_qhi[MROWS * DMODEL];
__device__ __align__(16) __half g_qlo[MROWS * DMODEL];
__device__ __align__(16) __half g_khi[MROWS * DMODEL];
__device__ __align__(16) __half g_klo[MROWS * DMODEL];
__device__ __align__(16) __half g_vhi[MROWS * DMODEL];
// attention context (A operand of output GEMM)
__device__ __align__(16) __half g_chi[MROWS * DMODEL];
__device__ __align__(16) __half g_clo[MROWS * DMODEL];
// weights fp16 (4 matrices packed)
__device__ __align__(16) __half g_w16[4 * DMODEL * DMODEL];
__device__ unsigned g_mbits[SEQ * MWORDS];
__device__ int g_mode;

// ---------------- PTX helpers (sm_103-safe) ---------------------------------
__device__ __forceinline__ uint32_t smem_u32(const void* p) {
    uint32_t a;
    asm("{ .reg .u64 t; cvta.to.shared.u64 t, %1; cvt.u32.u64 %0, t; }" : "=r"(a) : "l"(p));
    return a;
}
#define CP_ASYNC16(dst, src) \
    asm volatile("cp.async.ca.shared.global [%0], [%1], 16;" :: "r"(dst), "l"(src))
#define CP_COMMIT() asm volatile("cp.async.commit_group;" ::: "memory")
#define CP_WAIT(n)  asm volatile("cp.async.wait_group %0;" :: "n"(n) : "memory")

__device__ __forceinline__ void ldsm4(uint32_t* r, uint32_t addr) {
    asm volatile("ldmatrix.sync.aligned.m8n8.x4.shared.b16 {%0,%1,%2,%3}, [%4];"
                 : "=r"(r[0]), "=r"(r[1]), "=r"(r[2]), "=r"(r[3]) : "r"(addr));
}
__device__ __forceinline__ void ldsm2(uint32_t* r, uint32_t addr) {
    asm volatile("ldmatrix.sync.aligned.m8n8.x2.shared.b16 {%0,%1}, [%2];"
                 : "=r"(r[0]), "=r"(r[1]) : "r"(addr));
}
__device__ __forceinline__ void ldsm4t(uint32_t* r, uint32_t addr) {
    asm volatile("ldmatrix.sync.aligned.m8n8.x4.trans.shared.b16 {%0,%1,%2,%3}, [%4];"
                 : "=r"(r[0]), "=r"(r[1]), "=r"(r[2]), "=r"(r[3]) : "r"(addr));
}
__device__ __forceinline__ void mma_f16(float* d, const uint32_t* a, const uint32_t* b) {
    asm volatile(
        "mma.sync.aligned.m16n8k16.row.col.f32.f16.f16.f32 "
        "{%0,%1,%2,%3}, {%4,%5,%6,%7}, {%8,%9}, {%0,%1,%2,%3};"
        : "+f"(d[0]), "+f"(d[1]), "+f"(d[2]), "+f"(d[3])
        : "r"(a[0]), "r"(a[1]), "r"(a[2]), "r"(a[3]), "r"(b[0]), "r"(b[1]));
}
__device__ __forceinline__ float ex2f(float x) {
    float r; asm("ex2.approx.f32 %0, %1;" : "=f"(r) : "f"(x)); return r;
}
__device__ __forceinline__ uint32_t packh2(float lo, float hi) {
    uint32_t d; asm("cvt.rn.f16x2.f32 %0, %1, %2;" : "=r"(d) : "f"(hi), "f"(lo)); return d;
}

// ---------------- mask handling ----------------------------------------------
__global__ void detect_mask(const unsigned* __restrict__ m) {
    __shared__ int f[4];
    int t = threadIdx.x;
    if (t < 4) f[t] = 0;
    __syncthreads();
    int fu8 = 0, ff16 = 0, fbf16 = 0, ff32 = 0;
    for (int i = t; i < 4096; i += 256) {
        unsigned w = m[i];
        if (w == 0x3F800000u) ff32 = 1;
        if (w == 0x3F803F80u || w == 0x00003F80u) fbf16 = 1;
        if (w == 0x3C003C00u || w == 0x00003C00u || w == 0x3C000000u) ff16 = 1;
        if ((w & 0xFEFEFEFEu) == 0u && w > 1u) fu8 = 1;
    }
    if (fu8)  atomicOr(&f[0], 1);
    if (ff16) atomicOr(&f[1], 1);
    if (fbf16) atomicOr(&f[2], 1);
    if (ff32) atomicOr(&f[3], 1);
    __syncthreads();
    if (t == 0) {
        int mode;
        if (f[1]) mode = 4;
        else if (f[2]) mode = 3;
        else if (f[3]) mode = 2;
        else if (f[0]) mode = 1;
        else mode = 0;
        g_mode = mode;
    }
}

__global__ void pack_mask(const void* __restrict__ mp) {
    int idx = blockIdx.x * blockDim.x + threadIdx.x;
    int mode = g_mode;
    long base = (long)idx * 32;
    unsigned bits = 0;
    if (mode == 0) {
        const int* p = (const int*)mp;
        #pragma unroll 8
        for (int j = 0; j < 32; j++) if (p[base + j] != 0) bits |= 1u << j;
    } else if (mode == 1) {
        const unsigned char* p = (const unsigned char*)mp;
        #pragma unroll 8
        for (int j = 0; j < 32; j++) if (p[base + j] != 0) bits |= 1u << j;
    } else if (mode == 2) {
        const float* p = (const float*)mp;
        #pragma unroll 8
        for (int j = 0; j < 32; j++) if (p[base + j] != 0.0f) bits |= 1u << j;
    } else {
        const unsigned short* p = (const unsigned short*)mp;
        #pragma unroll 8
        for (int j = 0; j < 32; j++) if (p[base + j] != 0) bits |= 1u << j;
    }
    g_mbits[idx] = bits;
}

// ---------------- prep: fp32 -> fp16 hi/lo split (3 activations) -------------
__global__ void split3_f16(const float4* __restrict__ q, const float4* __restrict__ k,
                           const float4* __restrict__ v,
                           __half* __restrict__ qh, __half* __restrict__ ql,
                           __half* __restrict__ kh, __half* __restrict__ kl,
                           __half* __restrict__ vh, __half* __restrict__ vl, int n4)
{
    int i = blockIdx.x * blockDim.x + threadIdx.x;
    if (i >= n4) return;
    int z = blockIdx.y;
    const float4* x = (z == 0) ? q : (z == 1) ? k : v;
    __half* hp = (z == 0) ? qh : (z == 1) ? kh : vh;
    __half* lp = (z == 0) ? ql : (z == 1) ? kl : vl;
    float4 vv = x[i];
    float f[4] = {vv.x, vv.y, vv.z, vv.w};
    __half h[4], l[4];
    #pragma unroll
    for (int j = 0; j < 4; j++) {
        h[j] = __float2half_rn(f[j]);
        l[j] = __float2half_rn(f[j] - __half2float(h[j]));
    }
    __half2* hq = (__half2*)hp + 2 * i;
    __half2* lq = (__half2*)lp + 2 * i;
    hq[0] = __half2{h[0], h[1]}; hq[1] = __half2{h[2], h[3]};
    lq[0] = __half2{l[0], l[1]}; lq[1] = __half2{l[2], l[3]};
}

// ---------------- prep: weights fp32 -> fp16 (hi only, 4 matrices) ----------
__global__ void convw4_f16(const float4* __restrict__ wq, const float4* __restrict__ wk,
                           const float4* __restrict__ wv, const float4* __restrict__ wo,
                           __half* __restrict__ out, int n4)
{
    int i = blockIdx.x * blockDim.x + threadIdx.x;
    if (i >= n4) return;
    int z = blockIdx.y;
    const float4* x = (z == 0) ? wq : (z == 1) ? wk : (z == 2) ? wv : wo;
    float4 vv = x[i];
    __half2* op = (__half2*)(out + (size_t)z * DMODEL * DMODEL) + 2 * i;
    op[0] = __half2{__float2half_rn(vv.x), __float2half_rn(vv.y)};
    op[1] = __half2{__float2half_rn(vv.z), __float2half_rn(vv.w)};
}

// ---------------- mma.sync fp16 GEMM: Y[M,1024] = A @ B^T + bias -------------
// A fp16 hi/lo (2-term), B fp16 hi. CTA 128x128, BK=32, 3-stage cp.async ring,
// one __syncthreads per iteration. grid.z selects job.
#define LDA_B   80
#define TILE_B  10240
#define STAGE_B 30720       // Ahi + Alo + Bhi
#define NITER   (DMODEL / 32)

struct Job {
    const __half* A1; const __half* A2; const __half* B1;
    const float* bias;
    float* Yf; __half* H1; __half* H2;
    int mode; float scale;
};
struct Jobs3 { Job j[3]; };

__global__ void __launch_bounds__(256) gemm_mma(Jobs3 jobs)
{
    extern __shared__ char sm[];
    uint32_t smb = smem_u32(sm);
    Job jb = jobs.j[blockIdx.z];
    int tid = threadIdx.x, lane = tid & 31, wid = tid >> 5;
    int wm = wid >> 2, wn = wid & 3;
    int m0 = blockIdx.y * 128, n0 = blockIdx.x * 128;

    float acc[4][4][4];
    #pragma unroll
    for (int i = 0; i < 4; i++)
        #pragma unroll
        for (int j = 0; j < 4; j++)
            #pragma unroll
            for (int q = 0; q < 4; q++) acc[i][j][q] = 0.0f;

    // copy slots: per tile 512 16B-chunks, 256 threads -> 2 chunks/thread
    int r0 = tid >> 2, c0 = tid & 3;
    int r1 = (tid + 256) >> 2, c1 = (tid + 256) & 3;
    const __half* A1p = jb.A1; const __half* A2p = jb.A2; const __half* B1p = jb.B1;

    auto issue = [&](int t) {
        uint32_t st = smb + (t % 3) * STAGE_B;
        int k0 = t * 32;
        uint32_t d0 = st + r0 * LDA_B + c0 * 16;
        uint32_t d1 = st + r1 * LDA_B + c1 * 16;
        size_t ga0 = (size_t)(m0 + r0) * DMODEL + k0 + c0 * 8;
        size_t ga1 = (size_t)(m0 + r1) * DMODEL + k0 + c1 * 8;
        size_t gb0 = (size_t)(n0 + r0) * DMODEL + k0 + c0 * 8;
        size_t gb1 = (size_t)(n0 + r1) * DMODEL + k0 + c1 * 8;
        CP_ASYNC16(d0,            A1p + ga0);
        CP_ASYNC16(d1,            A1p + ga1);
        CP_ASYNC16(d0 + TILE_B,   A2p + ga0);
        CP_ASYNC16(d1 + TILE_B,   A2p + ga1);
        CP_ASYNC16(d0 + 2*TILE_B, B1p + gb0);
        CP_ASYNC16(d1 + 2*TILE_B, B1p + gb1);
        CP_COMMIT();
    };
    issue(0);
    issue(1);

    for (int t = 0; t < NITER; t++) {
        if (t + 1 < NITER) { CP_WAIT(1); } else { CP_WAIT(0); }
        __syncthreads();
        if (t + 2 < NITER) issue(t + 2);   // writes ring slot (t-1)%3: safe after sync

        uint32_t st = smb + (t % 3) * STAGE_B;
        uint32_t aA = st + (wm * 64 + (lane & 15)) * LDA_B + (lane >> 4) * 16;
        uint32_t aB = st + 2 * TILE_B + (wn * 32 + (lane & 7)) * LDA_B + (lane >> 3) * 16;

        uint32_t bh[4][4];
        #pragma unroll
        for (int ni = 0; ni < 4; ni++) ldsm4(bh[ni], aB + ni * 8 * LDA_B);

        #pragma unroll
        for (int ks = 0; ks < 2; ks++) {
            uint32_t ah[4][4], al[4][4];
            #pragma unroll
            for (int mi = 0; mi < 4; mi++) {
                ldsm4(ah[mi], aA + mi * 16 * LDA_B + ks * 32);
                ldsm4(al[mi], aA + mi * 16 * LDA_B + ks * 32 + TILE_B);
            }
            #pragma unroll
            for (int mi = 0; mi < 4; mi++)
                #pragma unroll
                for (int ni = 0; ni < 4; ni++) {
                    mma_f16(acc[mi][ni], ah[mi], &bh[ni][2 * ks]);
                    mma_f16(acc[mi][ni], al[mi], &bh[ni][2 * ks]);
                }
        }
    }

    int er = lane >> 2, ec = (lane & 3) * 2;
    #pragma unroll
    for (int mi = 0; mi < 4; mi++) {
        #pragma unroll
        for (int ni = 0; ni < 4; ni++) {
            int row = m0 + wm * 64 + mi * 16 + er;
            int col = n0 + wn * 32 + ni * 8 + ec;
            float b0 = jb.bias[col], b1 = jb.bias[col + 1];
            float x00 = acc[mi][ni][0] + b0, x01 = acc[mi][ni][1] + b1;
            float x10 = acc[mi][ni][2] + b0, x11 = acc[mi][ni][3] + b1;
            if (jb.mode == 0) {
                *(float2*)(jb.Yf + (size_t)row * DMODEL + col) = float2{x00, x01};
                *(float2*)(jb.Yf + (size_t)(row + 8) * DMODEL + col) = float2{x10, x11};
            } else {
                x00 *= jb.scale; x01 *= jb.scale; x10 *= jb.scale; x11 *= jb.scale;
                __half h00 = __float2half_rn(x00), h01 = __float2half_rn(x01);
                __half h10 = __float2half_rn(x10), h11 = __float2half_rn(x11);
                *(__half2*)(jb.H1 + (size_t)row * DMODEL + col) = __half2{h00, h01};
                *(__half2*)(jb.H1 + (size_t)(row + 8) * DMODEL + col) = __half2{h10, h11};
                if (jb.mode == 1) {
                    __half l00 = __float2half_rn(x00 - __half2float(h00));
                    __half l01 = __float2half_rn(x01 - __half2float(h01));
                    __half l10 = __float2half_rn(x10 - __half2float(h10));
                    __half l11 = __float2half_rn(x11 - __half2float(h11));
                    *(__half2*)(jb.H2 + (size_t)row * DMODEL + col) = __half2{l00, l01};
                    *(__half2*)(jb.H2 + (size_t)(row + 8) * DMODEL + col) = __half2{l10, l11};
                }
            }
        }
    }
}

// ---------------- fused MMA flash attention ----------------------------------
#define FSTR 72
#define MASKVAL 1.4426950409e-9f

__global__ void __launch_bounds__(128) flash_mma(
    const __half* __restrict__ qhi, const __half* __restrict__ qlo,
    const __half* __restrict__ khi, const __half* __restrict__ klo,
    const __half* __restrict__ vhi,
    __half* __restrict__ chi, __half* __restrict__ clo)
{
    extern __shared__ __half sh[];
    const int O_QHI = 0, O_QLO = 9216;
    const int O_KH[2] = {18432, 27648};
    const int O_KL[2] = {23040, 32256};
    const int O_V[2]  = {36864, 41472};
    uint32_t sb = smem_u32(sh);

    int tid = threadIdx.x, lane = tid & 31, wm = tid >> 5;
    int q0 = blockIdx.x * 128, h = blockIdx.y, b = blockIdx.z;
    size_t rowbase = (size_t)b * SEQ;
    int r4 = lane >> 2, c2 = lane & 3;

    {
        const __half* qh = qhi + (rowbase + q0) * DMODEL + h * 64;
        const __half* ql = qlo + (rowbase + q0) * DMODEL + h * 64;
        #pragma unroll
        for (int c = tid; c < 1024; c += 128) {
            int r = c >> 3, dc = c & 7;
            CP_ASYNC16(sb + (O_QHI + r * FSTR + dc * 8) * 2, qh + (size_t)r * DMODEL + dc * 8);
            CP_ASYNC16(sb + (O_QLO + r * FSTR + dc * 8) * 2, ql + (size_t)r * DMODEL + dc * 8);
        }
        CP_COMMIT();
    }
    const __half* kbh = khi + rowbase * DMODEL + h * 64;
    const __half* kbl = klo + rowbase * DMODEL + h * 64;
    const __half* vb  = vhi + rowbase * DMODEL + h * 64;

    auto issue_kv = [&](int t) {
        int st = t & 1;
        int k0 = t * 64;
        #pragma unroll
        for (int c = tid; c < 512; c += 128) {
            int r = c >> 3, dc = c & 7;
            size_t g = (size_t)(k0 + r) * DMODEL + dc * 8;
            CP_ASYNC16(sb + (O_KH[st] + r * FSTR + dc * 8) * 2, kbh + g);
            CP_ASYNC16(sb + (O_KL[st] + r * FSTR + dc * 8) * 2, kbl + g);
            CP_ASYNC16(sb + (O_V[st]  + r * FSTR + dc * 8) * 2, vb + g);
        }
        CP_COMMIT();
    };
    issue_kv(0);
    issue_kv(1);

    float O[2][8][4];
    #pragma unroll
    for (int mi = 0; mi < 2; mi++)
        #pragma unroll
        for (int ni = 0; ni < 8; ni++)
            #pragma unroll
            for (int q = 0; q < 4; q++) O[mi][ni][q] = 0.0f;
    float lsum[4] = {0.f, 0.f, 0.f, 0.f};
    float mrow[4] = {-1e30f, -1e30f, -1e30f, -1e30f};

    for (int t = 0; t < SEQ / 64; t++) {
        if (t < SEQ / 64 - 2) { CP_WAIT(1); } else { CP_WAIT(0); }
        __syncthreads();
        int st = t & 1;

        uint2 mw[2][2];
        #pragma unroll
        for (int mi = 0; mi < 2; mi++)
            #pragma unroll
            for (int rr = 0; rr < 2; rr++) {
                int grow = q0 + wm * 32 + mi * 16 + r4 + rr * 8;
                mw[mi][rr] = __ldg((const uint2*)&g_mbits[(size_t)grow * MWORDS + 2 * t]);
            }

        float S[2][8][4];
        #pragma unroll
        for (int mi = 0; mi < 2; mi++)
            #pragma unroll
            for (int ni = 0; ni < 8; ni++)
                #pragma unroll
                for (int q = 0; q < 4; q++) S[mi][ni][q] = 0.0f;

        #pragma unroll
        for (int ks = 0; ks < 4; ks++) {
            uint32_t aH[2][4], aL[2][4];
            #pragma unroll
            for (int mi = 0; mi < 2; mi++) {
                uint32_t abase = sb + (((wm * 32 + mi * 16 + (lane & 15)) * FSTR) +
                                       (lane >> 4) * 8 + ks * 16) * 2;
                ldsm4(aH[mi], abase + O_QHI * 2);
                ldsm4(aL[mi], abase + (O_QLO - O_QHI) * 2 + O_QHI * 2);
            }
            uint32_t bH[8][2], bL[8][2];
            #pragma unroll
            for (int ni = 0; ni < 8; ni++) {
                uint32_t boff = ((ni * 8 + (lane & 7)) * FSTR + ks * 16 + ((lane >> 3) & 1) * 8) * 2;
                ldsm2(bH[ni], sb + O_KH[st] * 2 + boff);
                ldsm2(bL[ni], sb + O_KL[st] * 2 + boff);
            }
            #pragma unroll
            for (int mi = 0; mi < 2; mi++)
                #pragma unroll
                for (int ni = 0; ni < 8; ni++) {
                    mma_f16(S[mi][ni], aH[mi], bH[ni]);
                    mma_f16(S[mi][ni], aH[mi], bL[ni]);
                    mma_f16(S[mi][ni], aL[mi], bH[ni]);
                }
        }

        float mnew[4] = {mrow[0], mrow[1], mrow[2], mrow[3]};
        #pragma unroll
        for (int mi = 0; mi < 2; mi++)
            #pragma unroll
            for (int ni = 0; ni < 8; ni++) {
                uint32_t w0 = (ni < 4) ? mw[mi][0].x : mw[mi][0].y;
                uint32_t w1 = (ni < 4) ? mw[mi][1].x : mw[mi][1].y;
                int shf = (ni & 3) * 8 + 2 * c2;
                if ((w0 >> shf) & 1u)       S[mi][ni][0] = MASKVAL;
                if ((w0 >> (shf + 1)) & 1u) S[mi][ni][1] = MASKVAL;
                if ((w1 >> shf) & 1u)       S[mi][ni][2] = MASKVAL;
                if ((w1 >> (shf + 1)) & 1u) S[mi][ni][3] = MASKVAL;
                mnew[mi * 2 + 0] = fmaxf(mnew[mi * 2 + 0], fmaxf(S[mi][ni][0], S[mi][ni][1]));
                mnew[mi * 2 + 1] = fmaxf(mnew[mi * 2 + 1], fmaxf(S[mi][ni][2], S[mi][ni][3]));
            }
        #pragma unroll
        for (int j = 0; j < 4; j++) {
            mnew[j] = fmaxf(mnew[j], __shfl_xor_sync(0xffffffffu, mnew[j], 1));
            mnew[j] = fmaxf(mnew[j], __shfl_xor_sync(0xffffffffu, mnew[j], 2));
        }
        float al[4];
        #pragma unroll
        for (int j = 0; j < 4; j++) {
            al[j] = ex2f(mrow[j] - mnew[j]);
            mrow[j] = mnew[j];
            lsum[j] *= al[j];
        }
        #pragma unroll
        for (int mi = 0; mi < 2; mi++)
            #pragma unroll
            for (int ni = 0; ni < 8; ni++) {
                O[mi][ni][0] *= al[mi * 2];     O[mi][ni][1] *= al[mi * 2];
                O[mi][ni][2] *= al[mi * 2 + 1]; O[mi][ni][3] *= al[mi * 2 + 1];
            }

        uint32_t pa[2][4][4];
        #pragma unroll
        for (int mi = 0; mi < 2; mi++)
            #pragma unroll
            for (int ni = 0; ni < 8; ni++) {
                float p0 = ex2f(S[mi][ni][0] - mnew[mi * 2]);
                float p1 = ex2f(S[mi][ni][1] - mnew[mi * 2]);
                float p2 = ex2f(S[mi][ni][2] - mnew[mi * 2 + 1]);
                float p3 = ex2f(S[mi][ni][3] - mnew[mi * 2 + 1]);
                lsum[mi * 2]     += p0 + p1;
                lsum[mi * 2 + 1] += p2 + p3;
                int ks = ni >> 1, half = ni & 1;
                pa[mi][ks][half * 2 + 0] = packh2(p0, p1);
                pa[mi][ks][half * 2 + 1] = packh2(p2, p3);
            }

        #pragma unroll
        for (int ks = 0; ks < 4; ks++) {
            #pragma unroll
            for (int nn = 0; nn < 4; nn++) {
                uint32_t vb4[4];
                int key = ks * 16 + (lane & 7) + ((lane >> 3) & 1) * 8;
                int dim = nn * 16 + ((lane >> 4) & 1) * 8;
                ldsm4t(vb4, sb + (O_V[st] + key * FSTR + dim) * 2);
                mma_f16(O[0][2 * nn],     pa[0][ks], &vb4[0]);
                mma_f16(O[0][2 * nn + 1], pa[0][ks], &vb4[2]);
                mma_f16(O[1][2 * nn],     pa[1][ks], &vb4[0]);
                mma_f16(O[1][2 * nn + 1], pa[1][ks], &vb4[2]);
            }
        }
        __syncthreads();
        if (t + 2 < SEQ / 64) issue_kv(t + 2);
    }

    #pragma unroll
    for (int j = 0; j < 4; j++) {
        lsum[j] += __shfl_xor_sync(0xffffffffu, lsum[j], 1);
        lsum[j] += __shfl_xor_sync(0xffffffffu, lsum[j], 2);
        lsum[j] = 1.0f / lsum[j];
    }
    #pragma unroll
    for (int mi = 0; mi < 2; mi++)
        #pragma unroll
        for (int ni = 0; ni < 8; ni++) {
            size_t grow = rowbase + q0 + wm * 32 + mi * 16 + r4;
            int col = h * 64 + ni * 8 + 2 * c2;
            float x00 = O[mi][ni][0] * lsum[mi * 2];
            float x01 = O[mi][ni][1] * lsum[mi * 2];
            float x10 = O[mi][ni][2] * lsum[mi * 2 + 1];
            float x11 = O[mi][ni][3] * lsum[mi * 2 + 1];
            __half h00 = __float2half_rn(x00), h01 = __float2half_rn(x01);
            __half h10 = __float2half_rn(x10), h11 = __float2half_rn(x11);
            *(__half2*)(chi + grow * DMODEL + col) = __half2{h00, h01};
            *(__half2*)(chi + (grow + 8) * DMODEL + col) = __half2{h10, h11};
            __half l00 = __float2half_rn(x00 - __half2float(h00));
            __half l01 = __float2half_rn(x01 - __half2float(h01));
            __half l10 = __float2half_rn(x10 - __half2float(h10));
            __half l11 = __float2half_rn(x11 - __half2float(h11));
            *(__half2*)(clo + grow * DMODEL + col) = __half2{l00, l01};
            *(__half2*)(clo + (grow + 8) * DMODEL + col) = __half2{l10, l11};
        }
}

// ---------------- launch ------------------------------------------------------
extern "C" void kernel_launch(void* const* d_in, const int* in_sizes, int n_in,
                              void* d_out, int out_size)
{
    const float* q    = (const float*)d_in[0];
    const float* k    = (const float*)d_in[1];
    const float* v    = (const float*)d_in[2];
    const void*  mask = d_in[3];
    const float* Wq   = (const float*)d_in[4];
    const float* bq   = (const float*)d_in[5];
    const float* Wk   = (const float*)d_in[6];
    const float* bk   = (const float*)d_in[7];
    const float* Wv   = (const float*)d_in[8];
    const float* bv   = (const float*)d_in[9];
    const float* Wo   = (const float*)d_in[10];
    const float* bo   = (const float*)d_in[11];

    __half *qsh, *qsl, *ksh, *ksl, *vsh, *vsl;
    __half *qhi, *qlo, *khi, *klo, *vhi, *chi, *clo, *w16;
    cudaGetSymbolAddress((void**)&qsh, g_qsh);
    cudaGetSymbolAddress((void**)&qsl, g_qsl);
    cudaGetSymbolAddress((void**)&ksh, g_ksh);
    cudaGetSymbolAddress((void**)&ksl, g_ksl);
    cudaGetSymbolAddress((void**)&vsh, g_vsh);
    cudaGetSymbolAddress((void**)&vsl, g_vsl);
    cudaGetSymbolAddress((void**)&qhi, g_qhi);
    cudaGetSymbolAddress((void**)&qlo, g_qlo);
    cudaGetSymbolAddress((void**)&khi, g_khi);
    cudaGetSymbolAddress((void**)&klo, g_klo);
    cudaGetSymbolAddress((void**)&vhi, g_vhi);
    cudaGetSymbolAddress((void**)&chi, g_chi);
    cudaGetSymbolAddress((void**)&clo, g_clo);
    cudaGetSymbolAddress((void**)&w16, g_w16);

    const int gemm_smem = 3 * STAGE_B;   // 92160
    const int flash_smem = 92160;
    static bool attr_set = false;
    if (!attr_set) {
        cudaFuncSetAttribute(gemm_mma, cudaFuncAttributeMaxDynamicSharedMemorySize, gemm_smem);
        cudaFuncSetAttribute(flash_mma, cudaFuncAttributeMaxDynamicSharedMemorySize, flash_smem);
        attr_set = true;
    }

    const int nACT4 = MROWS * DMODEL / 4;   // 2097152
    const int nW4   = DMODEL * DMODEL / 4;  // 262144
    const float qscale = 0.125f * LOG2E;

    detect_mask<<<1, 256>>>((const unsigned*)mask);
    pack_mask<<<(SEQ * MWORDS) / 256, 256>>>(mask);

    split3_f16<<<dim3(nACT4 / 256, 3), 256>>>((const float4*)q, (const float4*)k,
        (const float4*)v, qsh, qsl, ksh, ksl, vsh, vsl, nACT4);
    convw4_f16<<<dim3(nW4 / 256, 4), 256>>>((const float4*)Wq, (const float4*)Wk,
        (const float4*)Wv, (const float4*)Wo, w16, nW4);

    // merged Q/K/V projections
    Jobs3 pj;
    pj.j[0] = Job{qsh, qsl, w16,                    bq, nullptr, qhi, qlo, 1, qscale};
    pj.j[1] = Job{ksh, ksl, w16 + 1 * DMODEL*DMODEL, bk, nullptr, khi, klo, 1, 1.0f};
    pj.j[2] = Job{vsh, vsl, w16 + 2 * DMODEL*DMODEL, bv, nullptr, vhi, nullptr, 2, 1.0f};
    gemm_mma<<<dim3(8, 64, 3), 256, gemm_smem>>>(pj);

    flash_mma<<<dim3(SEQ / 128, NHEAD, NBATCH), 128, flash_smem>>>(
        qhi, qlo, khi, klo, vhi, chi, clo);

    // output projection
    Jobs3 oj;
    oj.j[0] = Job{chi, clo, w16 + 3 * DMODEL*DMODEL, bo, (float*)d_out, nullptr, nullptr, 0, 1.0f};
    oj.j[1] = oj.j[0];
    oj.j[2] = oj.j[0];
    gemm_mma<<<dim3(8, 64, 1), 256, gemm_smem>>>(oj);
}

// round 6
// speedup vs baseline: 5.1790x; 1.1232x over previous
#include <cuda_runtime.h>
#include <cuda_fp16.h>
#include <cstdint>

#define SEQ    2048
#define DMODEL 1024
#define NHEAD  16
#define DVDIM  64
#define NBATCH 4
#define MROWS  (NBATCH * SEQ)   // 8192
#define MWORDS (SEQ / 32)
#define LOG2E  1.4426950408889634f

// ---------------- scratch (device globals) ----------------------------------
__device__ __align__(16) __half g_qsh[MROWS * DMODEL];
__device__ __align__(16) __half g_qsl[MROWS * DMODEL];
__device__ __align__(16) __half g_ksh[MROWS * DMODEL];
__device__ __align__(16) __half g_ksl[MROWS * DMODEL];
__device__ __align__(16) __half g_vsh[MROWS * DMODEL];
// projected Q/K/V for attention
__device__ __align__(16) __half g_qhi[MROWS * DMODEL];
__device__ __align__(16) __half g_qlo[MROWS * DMODEL];
__device__ __align__(16) __half g_khi[MROWS * DMODEL];
__device__ __align__(16) __half g_vhi[MROWS * DMODEL];
// attention context (A operand of output GEMM, 1-term)
__device__ __align__(16) __half g_chi[MROWS * DMODEL];
// weights fp16 (4 matrices packed)
__device__ __align__(16) __half g_w16[4 * DMODEL * DMODEL];
__device__ unsigned g_mbits[SEQ * MWORDS];
__device__ int g_mode;

// ---------------- PTX helpers (sm_103-safe) ---------------------------------
__device__ __forceinline__ uint32_t smem_u32(const void* p) {
    uint32_t a;
    asm("{ .reg .u64 t; cvta.to.shared.u64 t, %1; cvt.u32.u64 %0, t; }" : "=r"(a) : "l"(p));
    return a;
}
#define CP_ASYNC16(dst, src) \
    asm volatile("cp.async.ca.shared.global [%0], [%1], 16;" :: "r"(dst), "l"(src))
#define CP_COMMIT() asm volatile("cp.async.commit_group;" ::: "memory")
#define CP_WAIT(n)  asm volatile("cp.async.wait_group %0;" :: "n"(n) : "memory")

__device__ __forceinline__ void ldsm4(uint32_t* r, uint32_t addr) {
    asm volatile("ldmatrix.sync.aligned.m8n8.x4.shared.b16 {%0,%1,%2,%3}, [%4];"
                 : "=r"(r[0]), "=r"(r[1]), "=r"(r[2]), "=r"(r[3]) : "r"(addr));
}
__device__ __forceinline__ void ldsm2(uint32_t* r, uint32_t addr) {
    asm volatile("ldmatrix.sync.aligned.m8n8.x2.shared.b16 {%0,%1}, [%2];"
                 : "=r"(r[0]), "=r"(r[1]) : "r"(addr));
}
__device__ __forceinline__ void ldsm4t(uint32_t* r, uint32_t addr) {
    asm volatile("ldmatrix.sync.aligned.m8n8.x4.trans.shared.b16 {%0,%1,%2,%3}, [%4];"
                 : "=r"(r[0]), "=r"(r[1]), "=r"(r[2]), "=r"(r[3]) : "r"(addr));
}
__device__ __forceinline__ void mma_f16(float* d, const uint32_t* a, const uint32_t* b) {
    asm volatile(
        "mma.sync.aligned.m16n8k16.row.col.f32.f16.f16.f32 "
        "{%0,%1,%2,%3}, {%4,%5,%6,%7}, {%8,%9}, {%0,%1,%2,%3};"
        : "+f"(d[0]), "+f"(d[1]), "+f"(d[2]), "+f"(d[3])
        : "r"(a[0]), "r"(a[1]), "r"(a[2]), "r"(a[3]), "r"(b[0]), "r"(b[1]));
}
__device__ __forceinline__ float ex2f(float x) {
    float r; asm("ex2.approx.f32 %0, %1;" : "=f"(r) : "f"(x)); return r;
}
__device__ __forceinline__ uint32_t packh2(float lo, float hi) {
    uint32_t d; asm("cvt.rn.f16x2.f32 %0, %1, %2;" : "=r"(d) : "f"(hi), "f"(lo)); return d;
}

// ---------------- mask handling ----------------------------------------------
__global__ void detect_mask(const unsigned* __restrict__ m) {
    __shared__ int f[4];
    int t = threadIdx.x;
    if (t < 4) f[t] = 0;
    __syncthreads();
    int fu8 = 0, ff16 = 0, fbf16 = 0, ff32 = 0;
    for (int i = t; i < 4096; i += 256) {
        unsigned w = m[i];
        if (w == 0x3F800000u) ff32 = 1;
        if (w == 0x3F803F80u || w == 0x00003F80u) fbf16 = 1;
        if (w == 0x3C003C00u || w == 0x00003C00u || w == 0x3C000000u) ff16 = 1;
        if ((w & 0xFEFEFEFEu) == 0u && w > 1u) fu8 = 1;
    }
    if (fu8)  atomicOr(&f[0], 1);
    if (ff16) atomicOr(&f[1], 1);
    if (fbf16) atomicOr(&f[2], 1);
    if (ff32) atomicOr(&f[3], 1);
    __syncthreads();
    if (t == 0) {
        int mode;
        if (f[1]) mode = 4;
        else if (f[2]) mode = 3;
        else if (f[3]) mode = 2;
        else if (f[0]) mode = 1;
        else mode = 0;
        g_mode = mode;
    }
}

__global__ void pack_mask(const void* __restrict__ mp) {
    int idx = blockIdx.x * blockDim.x + threadIdx.x;
    int mode = g_mode;
    long base = (long)idx * 32;
    unsigned bits = 0;
    if (mode == 0) {
        const int* p = (const int*)mp;
        #pragma unroll 8
        for (int j = 0; j < 32; j++) if (p[base + j] != 0) bits |= 1u << j;
    } else if (mode == 1) {
        const unsigned char* p = (const unsigned char*)mp;
        #pragma unroll 8
        for (int j = 0; j < 32; j++) if (p[base + j] != 0) bits |= 1u << j;
    } else if (mode == 2) {
        const float* p = (const float*)mp;
        #pragma unroll 8
        for (int j = 0; j < 32; j++) if (p[base + j] != 0.0f) bits |= 1u << j;
    } else {
        const unsigned short* p = (const unsigned short*)mp;
        #pragma unroll 8
        for (int j = 0; j < 32; j++) if (p[base + j] != 0) bits |= 1u << j;
    }
    g_mbits[idx] = bits;
}

// ---------------- prep: fp32 -> fp16 splits (q,k: hi+lo; v: hi) --------------
__global__ void split3_f16(const float4* __restrict__ q, const float4* __restrict__ k,
                           const float4* __restrict__ v,
                           __half* __restrict__ qh, __half* __restrict__ ql,
                           __half* __restrict__ kh, __half* __restrict__ kl,
                           __half* __restrict__ vh, int n4)
{
    int i = blockIdx.x * blockDim.x + threadIdx.x;
    if (i >= n4) return;
    int z = blockIdx.y;
    const float4* x = (z == 0) ? q : (z == 1) ? k : v;
    __half* hp = (z == 0) ? qh : (z == 1) ? kh : vh;
    float4 vv = x[i];
    float f[4] = {vv.x, vv.y, vv.z, vv.w};
    __half h[4];
    #pragma unroll
    for (int j = 0; j < 4; j++) h[j] = __float2half_rn(f[j]);
    __half2* hq = (__half2*)hp + 2 * i;
    hq[0] = __half2{h[0], h[1]}; hq[1] = __half2{h[2], h[3]};
    if (z < 2) {
        __half* lp = (z == 0) ? ql : kl;
        __half l[4];
        #pragma unroll
        for (int j = 0; j < 4; j++) l[j] = __float2half_rn(f[j] - __half2float(h[j]));
        __half2* lq = (__half2*)lp + 2 * i;
        lq[0] = __half2{l[0], l[1]}; lq[1] = __half2{l[2], l[3]};
    }
}

// ---------------- prep: weights fp32 -> fp16 (4 matrices) --------------------
__global__ void convw4_f16(const float4* __restrict__ wq, const float4* __restrict__ wk,
                           const float4* __restrict__ wv, const float4* __restrict__ wo,
                           __half* __restrict__ out, int n4)
{
    int i = blockIdx.x * blockDim.x + threadIdx.x;
    if (i >= n4) return;
    int z = blockIdx.y;
    const float4* x = (z == 0) ? wq : (z == 1) ? wk : (z == 2) ? wv : wo;
    float4 vv = x[i];
    __half2* op = (__half2*)(out + (size_t)z * DMODEL * DMODEL) + 2 * i;
    op[0] = __half2{__float2half_rn(vv.x), __float2half_rn(vv.y)};
    op[1] = __half2{__float2half_rn(vv.z), __float2half_rn(vv.w)};
}

// ---------------- mma.sync fp16 GEMM: Y[M,1024] = A @ B^T + bias -------------
// A fp16 1- or 2-term (A2 != null), B fp16. CTA 128x128, BK=32, 3-stage ring.
#define LDA_B   80
#define TILE_B  10240
#define STAGE_B 30720
#define NITER   (DMODEL / 32)

struct Job {
    const __half* A1; const __half* A2; const __half* B1;
    const float* bias;
    float* Yf; __half* H1; __half* H2;
    int mode; float scale;
};
struct Jobs3 { Job j[3]; };

__global__ void __launch_bounds__(256) gemm_mma(Jobs3 jobs)
{
    extern __shared__ char sm[];
    uint32_t smb = smem_u32(sm);
    Job jb = jobs.j[blockIdx.z];
    const bool two = (jb.A2 != nullptr);
    int tid = threadIdx.x, lane = tid & 31, wid = tid >> 5;
    int wm = wid >> 2, wn = wid & 3;
    int m0 = blockIdx.y * 128, n0 = blockIdx.x * 128;

    float acc[4][4][4];
    #pragma unroll
    for (int i = 0; i < 4; i++)
        #pragma unroll
        for (int j = 0; j < 4; j++)
            #pragma unroll
            for (int q = 0; q < 4; q++) acc[i][j][q] = 0.0f;

    int r0 = tid >> 2, c0 = tid & 3;
    int r1 = (tid + 256) >> 2, c1 = (tid + 256) & 3;
    const __half* A1p = jb.A1; const __half* A2p = jb.A2; const __half* B1p = jb.B1;

    auto issue = [&](int t) {
        uint32_t st = smb + (t % 3) * STAGE_B;
        int k0 = t * 32;
        uint32_t d0 = st + r0 * LDA_B + c0 * 16;
        uint32_t d1 = st + r1 * LDA_B + c1 * 16;
        size_t ga0 = (size_t)(m0 + r0) * DMODEL + k0 + c0 * 8;
        size_t ga1 = (size_t)(m0 + r1) * DMODEL + k0 + c1 * 8;
        size_t gb0 = (size_t)(n0 + r0) * DMODEL + k0 + c0 * 8;
        size_t gb1 = (size_t)(n0 + r1) * DMODEL + k0 + c1 * 8;
        CP_ASYNC16(d0,            A1p + ga0);
        CP_ASYNC16(d1,            A1p + ga1);
        if (two) {
            CP_ASYNC16(d0 + TILE_B, A2p + ga0);
            CP_ASYNC16(d1 + TILE_B, A2p + ga1);
        }
        CP_ASYNC16(d0 + 2*TILE_B, B1p + gb0);
        CP_ASYNC16(d1 + 2*TILE_B, B1p + gb1);
        CP_COMMIT();
    };
    issue(0);
    issue(1);

    for (int t = 0; t < NITER; t++) {
        if (t + 1 < NITER) { CP_WAIT(1); } else { CP_WAIT(0); }
        __syncthreads();
        if (t + 2 < NITER) issue(t + 2);

        uint32_t st = smb + (t % 3) * STAGE_B;
        uint32_t aA = st + (wm * 64 + (lane & 15)) * LDA_B + (lane >> 4) * 16;
        uint32_t aB = st + 2 * TILE_B + (wn * 32 + (lane & 7)) * LDA_B + (lane >> 3) * 16;

        uint32_t bh[4][4];
        #pragma unroll
        for (int ni = 0; ni < 4; ni++) ldsm4(bh[ni], aB + ni * 8 * LDA_B);

        #pragma unroll
        for (int ks = 0; ks < 2; ks++) {
            uint32_t ah[4][4], al[4][4];
            #pragma unroll
            for (int mi = 0; mi < 4; mi++) {
                ldsm4(ah[mi], aA + mi * 16 * LDA_B + ks * 32);
                if (two) ldsm4(al[mi], aA + mi * 16 * LDA_B + ks * 32 + TILE_B);
            }
            #pragma unroll
            for (int mi = 0; mi < 4; mi++)
                #pragma unroll
                for (int ni = 0; ni < 4; ni++) {
                    mma_f16(acc[mi][ni], ah[mi], &bh[ni][2 * ks]);
                    if (two) mma_f16(acc[mi][ni], al[mi], &bh[ni][2 * ks]);
                }
        }
    }

    int er = lane >> 2, ec = (lane & 3) * 2;
    #pragma unroll
    for (int mi = 0; mi < 4; mi++) {
        #pragma unroll
        for (int ni = 0; ni < 4; ni++) {
            int row = m0 + wm * 64 + mi * 16 + er;
            int col = n0 + wn * 32 + ni * 8 + ec;
            float b0 = jb.bias[col], b1 = jb.bias[col + 1];
            float x00 = acc[mi][ni][0] + b0, x01 = acc[mi][ni][1] + b1;
            float x10 = acc[mi][ni][2] + b0, x11 = acc[mi][ni][3] + b1;
            if (jb.mode == 0) {
                *(float2*)(jb.Yf + (size_t)row * DMODEL + col) = float2{x00, x01};
                *(float2*)(jb.Yf + (size_t)(row + 8) * DMODEL + col) = float2{x10, x11};
            } else {
                x00 *= jb.scale; x01 *= jb.scale; x10 *= jb.scale; x11 *= jb.scale;
                __half h00 = __float2half_rn(x00), h01 = __float2half_rn(x01);
                __half h10 = __float2half_rn(x10), h11 = __float2half_rn(x11);
                *(__half2*)(jb.H1 + (size_t)row * DMODEL + col) = __half2{h00, h01};
                *(__half2*)(jb.H1 + (size_t)(row + 8) * DMODEL + col) = __half2{h10, h11};
                if (jb.mode == 1) {
                    __half l00 = __float2half_rn(x00 - __half2float(h00));
                    __half l01 = __float2half_rn(x01 - __half2float(h01));
                    __half l10 = __float2half_rn(x10 - __half2float(h10));
                    __half l11 = __float2half_rn(x11 - __half2float(h11));
                    *(__half2*)(jb.H2 + (size_t)row * DMODEL + col) = __half2{l00, l01};
                    *(__half2*)(jb.H2 + (size_t)(row + 8) * DMODEL + col) = __half2{l10, l11};
                }
            }
        }
    }
}

// ---------------- fused MMA flash attention ----------------------------------
// QK^T 2-term: (qhi+qlo)·khi. PV 1-term. ctx out: fp16 hi only.
#define FSTR 72
#define MASKVAL 1.4426950409e-9f

__global__ void __launch_bounds__(128) flash_mma(
    const __half* __restrict__ qhi, const __half* __restrict__ qlo,
    const __half* __restrict__ khi, const __half* __restrict__ vhi,
    __half* __restrict__ chi)
{
    extern __shared__ __half sh[];
    const int O_QHI = 0, O_QLO = 9216;
    const int O_KH[2] = {18432, 23040};
    const int O_V[2]  = {27648, 32256};
    uint32_t sb = smem_u32(sh);

    int tid = threadIdx.x, lane = tid & 31, wm = tid >> 5;
    int q0 = blockIdx.x * 128, h = blockIdx.y, b = blockIdx.z;
    size_t rowbase = (size_t)b * SEQ;
    int r4 = lane >> 2, c2 = lane & 3;

    {
        const __half* qh = qhi + (rowbase + q0) * DMODEL + h * 64;
        const __half* ql = qlo + (rowbase + q0) * DMODEL + h * 64;
        #pragma unroll
        for (int c = tid; c < 1024; c += 128) {
            int r = c >> 3, dc = c & 7;
            CP_ASYNC16(sb + (O_QHI + r * FSTR + dc * 8) * 2, qh + (size_t)r * DMODEL + dc * 8);
            CP_ASYNC16(sb + (O_QLO + r * FSTR + dc * 8) * 2, ql + (size_t)r * DMODEL + dc * 8);
        }
        CP_COMMIT();
    }
    const __half* kbh = khi + rowbase * DMODEL + h * 64;
    const __half* vb  = vhi + rowbase * DMODEL + h * 64;

    auto issue_kv = [&](int t) {
        int st = t & 1;
        int k0 = t * 64;
        #pragma unroll
        for (int c = tid; c < 512; c += 128) {
            int r = c >> 3, dc = c & 7;
            size_t g = (size_t)(k0 + r) * DMODEL + dc * 8;
            CP_ASYNC16(sb + (O_KH[st] + r * FSTR + dc * 8) * 2, kbh + g);
            CP_ASYNC16(sb + (O_V[st]  + r * FSTR + dc * 8) * 2, vb + g);
        }
        CP_COMMIT();
    };
    issue_kv(0);
    issue_kv(1);

    float O[2][8][4];
    #pragma unroll
    for (int mi = 0; mi < 2; mi++)
        #pragma unroll
        for (int ni = 0; ni < 8; ni++)
            #pragma unroll
            for (int q = 0; q < 4; q++) O[mi][ni][q] = 0.0f;
    float lsum[4] = {0.f, 0.f, 0.f, 0.f};
    float mrow[4] = {-1e30f, -1e30f, -1e30f, -1e30f};

    for (int t = 0; t < SEQ / 64; t++) {
        if (t < SEQ / 64 - 2) { CP_WAIT(1); } else { CP_WAIT(0); }
        __syncthreads();
        int st = t & 1;

        uint2 mw[2][2];
        #pragma unroll
        for (int mi = 0; mi < 2; mi++)
            #pragma unroll
            for (int rr = 0; rr < 2; rr++) {
                int grow = q0 + wm * 32 + mi * 16 + r4 + rr * 8;
                mw[mi][rr] = __ldg((const uint2*)&g_mbits[(size_t)grow * MWORDS + 2 * t]);
            }

        float S[2][8][4];
        #pragma unroll
        for (int mi = 0; mi < 2; mi++)
            #pragma unroll
            for (int ni = 0; ni < 8; ni++)
                #pragma unroll
                for (int q = 0; q < 4; q++) S[mi][ni][q] = 0.0f;

        #pragma unroll
        for (int ks = 0; ks < 4; ks++) {
            uint32_t aH[2][4], aL[2][4];
            #pragma unroll
            for (int mi = 0; mi < 2; mi++) {
                uint32_t abase = sb + (((wm * 32 + mi * 16 + (lane & 15)) * FSTR) +
                                       (lane >> 4) * 8 + ks * 16) * 2;
                ldsm4(aH[mi], abase);
                ldsm4(aL[mi], abase + O_QLO * 2);
            }
            uint32_t bH[8][2];
            #pragma unroll
            for (int ni = 0; ni < 8; ni++) {
                uint32_t boff = ((ni * 8 + (lane & 7)) * FSTR + ks * 16 + ((lane >> 3) & 1) * 8) * 2;
                ldsm2(bH[ni], sb + O_KH[st] * 2 + boff);
            }
            #pragma unroll
            for (int mi = 0; mi < 2; mi++)
                #pragma unroll
                for (int ni = 0; ni < 8; ni++) {
                    mma_f16(S[mi][ni], aH[mi], bH[ni]);
                    mma_f16(S[mi][ni], aL[mi], bH[ni]);
                }
        }

        float mnew[4] = {mrow[0], mrow[1], mrow[2], mrow[3]};
        #pragma unroll
        for (int mi = 0; mi < 2; mi++)
            #pragma unroll
            for (int ni = 0; ni < 8; ni++) {
                uint32_t w0 = (ni < 4) ? mw[mi][0].x : mw[mi][0].y;
                uint32_t w1 = (ni < 4) ? mw[mi][1].x : mw[mi][1].y;
                int shf = (ni & 3) * 8 + 2 * c2;
                if ((w0 >> shf) & 1u)       S[mi][ni][0] = MASKVAL;
                if ((w0 >> (shf + 1)) & 1u) S[mi][ni][1] = MASKVAL;
                if ((w1 >> shf) & 1u)       S[mi][ni][2] = MASKVAL;
                if ((w1 >> (shf + 1)) & 1u) S[mi][ni][3] = MASKVAL;
                mnew[mi * 2 + 0] = fmaxf(mnew[mi * 2 + 0], fmaxf(S[mi][ni][0], S[mi][ni][1]));
                mnew[mi * 2 + 1] = fmaxf(mnew[mi * 2 + 1], fmaxf(S[mi][ni][2], S[mi][ni][3]));
            }
        #pragma unroll
        for (int j = 0; j < 4; j++) {
            mnew[j] = fmaxf(mnew[j], __shfl_xor_sync(0xffffffffu, mnew[j], 1));
            mnew[j] = fmaxf(mnew[j], __shfl_xor_sync(0xffffffffu, mnew[j], 2));
        }
        float al[4];
        #pragma unroll
        for (int j = 0; j < 4; j++) {
            al[j] = ex2f(mrow[j] - mnew[j]);
            mrow[j] = mnew[j];
            lsum[j] *= al[j];
        }
        #pragma unroll
        for (int mi = 0; mi < 2; mi++)
            #pragma unroll
            for (int ni = 0; ni < 8; ni++) {
                O[mi][ni][0] *= al[mi * 2];     O[mi][ni][1] *= al[mi * 2];
                O[mi][ni][2] *= al[mi * 2 + 1]; O[mi][ni][3] *= al[mi * 2 + 1];
            }

        uint32_t pa[2][4][4];
        #pragma unroll
        for (int mi = 0; mi < 2; mi++)
            #pragma unroll
            for (int ni = 0; ni < 8; ni++) {
                float p0 = ex2f(S[mi][ni][0] - mnew[mi * 2]);
                float p1 = ex2f(S[mi][ni][1] - mnew[mi * 2]);
                float p2 = ex2f(S[mi][ni][2] - mnew[mi * 2 + 1]);
                float p3 = ex2f(S[mi][ni][3] - mnew[mi * 2 + 1]);
                lsum[mi * 2]     += p0 + p1;
                lsum[mi * 2 + 1] += p2 + p3;
                int ks = ni >> 1, half = ni & 1;
                pa[mi][ks][half * 2 + 0] = packh2(p0, p1);
                pa[mi][ks][half * 2 + 1] = packh2(p2, p3);
            }

        #pragma unroll
        for (int ks = 0; ks < 4; ks++) {
            #pragma unroll
            for (int nn = 0; nn < 4; nn++) {
                uint32_t vb4[4];
                int key = ks * 16 + (lane & 7) + ((lane >> 3) & 1) * 8;
                int dim = nn * 16 + ((lane >> 4) & 1) * 8;
                ldsm4t(vb4, sb + (O_V[st] + key * FSTR + dim) * 2);
                mma_f16(O[0][2 * nn],     pa[0][ks], &vb4[0]);
                mma_f16(O[0][2 * nn + 1], pa[0][ks], &vb4[2]);
                mma_f16(O[1][2 * nn],     pa[1][ks], &vb4[0]);
                mma_f16(O[1][2 * nn + 1], pa[1][ks], &vb4[2]);
            }
        }
        __syncthreads();
        if (t + 2 < SEQ / 64) issue_kv(t + 2);
    }

    #pragma unroll
    for (int j = 0; j < 4; j++) {
        lsum[j] += __shfl_xor_sync(0xffffffffu, lsum[j], 1);
        lsum[j] += __shfl_xor_sync(0xffffffffu, lsum[j], 2);
        lsum[j] = 1.0f / lsum[j];
    }
    #pragma unroll
    for (int mi = 0; mi < 2; mi++)
        #pragma unroll
        for (int ni = 0; ni < 8; ni++) {
            size_t grow = rowbase + q0 + wm * 32 + mi * 16 + r4;
            int col = h * 64 + ni * 8 + 2 * c2;
            float x00 = O[mi][ni][0] * lsum[mi * 2];
            float x01 = O[mi][ni][1] * lsum[mi * 2];
            float x10 = O[mi][ni][2] * lsum[mi * 2 + 1];
            float x11 = O[mi][ni][3] * lsum[mi * 2 + 1];
            *(__half2*)(chi + grow * DMODEL + col) =
                __half2{__float2half_rn(x00), __float2half_rn(x01)};
            *(__half2*)(chi + (grow + 8) * DMODEL + col) =
                __half2{__float2half_rn(x10), __float2half_rn(x11)};
        }
}

// ---------------- launch ------------------------------------------------------
extern "C" void kernel_launch(void* const* d_in, const int* in_sizes, int n_in,
                              void* d_out, int out_size)
{
    const float* q    = (const float*)d_in[0];
    const float* k    = (const float*)d_in[1];
    const float* v    = (const float*)d_in[2];
    const void*  mask = d_in[3];
    const float* Wq   = (const float*)d_in[4];
    const float* bq   = (const float*)d_in[5];
    const float* Wk   = (const float*)d_in[6];
    const float* bk   = (const float*)d_in[7];
    const float* Wv   = (const float*)d_in[8];
    const float* bv   = (const float*)d_in[9];
    const float* Wo   = (const float*)d_in[10];
    const float* bo   = (const float*)d_in[11];

    __half *qsh, *qsl, *ksh, *ksl, *vsh;
    __half *qhi, *qlo, *khi, *vhi, *chi, *w16;
    cudaGetSymbolAddress((void**)&qsh, g_qsh);
    cudaGetSymbolAddress((void**)&qsl, g_qsl);
    cudaGetSymbolAddress((void**)&ksh, g_ksh);
    cudaGetSymbolAddress((void**)&ksl, g_ksl);
    cudaGetSymbolAddress((void**)&vsh, g_vsh);
    cudaGetSymbolAddress((void**)&qhi, g_qhi);
    cudaGetSymbolAddress((void**)&qlo, g_qlo);
    cudaGetSymbolAddress((void**)&khi, g_khi);
    cudaGetSymbolAddress((void**)&vhi, g_vhi);
    cudaGetSymbolAddress((void**)&chi, g_chi);
    cudaGetSymbolAddress((void**)&w16, g_w16);

    const int gemm_smem = 3 * STAGE_B;   // 92160
    const int flash_smem = 36864 * 2;    // 73728
    static bool attr_set = false;
    if (!attr_set) {
        cudaFuncSetAttribute(gemm_mma, cudaFuncAttributeMaxDynamicSharedMemorySize, gemm_smem);
        cudaFuncSetAttribute(flash_mma, cudaFuncAttributeMaxDynamicSharedMemorySize, flash_smem);
        attr_set = true;
    }

    const int nACT4 = MROWS * DMODEL / 4;
    const int nW4   = DMODEL * DMODEL / 4;
    const float qscale = 0.125f * LOG2E;

    detect_mask<<<1, 256>>>((const unsigned*)mask);
    pack_mask<<<(SEQ * MWORDS) / 256, 256>>>(mask);

    split3_f16<<<dim3(nACT4 / 256, 3), 256>>>((const float4*)q, (const float4*)k,
        (const float4*)v, qsh, qsl, ksh, ksl, vsh, nACT4);
    convw4_f16<<<dim3(nW4 / 256, 4), 256>>>((const float4*)Wq, (const float4*)Wk,
        (const float4*)Wv, (const float4*)Wo, w16, nW4);

    // merged Q/K/V projections: Q 2-term->hi/lo, K 2-term->hi, V 1-term->hi
    Jobs3 pj;
    pj.j[0] = Job{qsh, qsl,     w16,                     bq, nullptr, qhi, qlo, 1, qscale};
    pj.j[1] = Job{ksh, ksl,     w16 + 1 * DMODEL*DMODEL, bk, nullptr, khi, nullptr, 2, 1.0f};
    pj.j[2] = Job{vsh, nullptr, w16 + 2 * DMODEL*DMODEL, bv, nullptr, vhi, nullptr, 2, 1.0f};
    gemm_mma<<<dim3(8, 64, 3), 256, gemm_smem>>>(pj);

    flash_mma<<<dim3(SEQ / 128, NHEAD, NBATCH), 128, flash_smem>>>(
        qhi, qlo, khi, vhi, chi);

    // output projection: 1-term A
    Jobs3 oj;
    oj.j[0] = Job{chi, nullptr, w16 + 3 * DMODEL*DMODEL, bo, (float*)d_out, nullptr, nullptr, 0, 1.0f};
    oj.j[1] = oj.j[0];
    oj.j[2] = oj.j[0];
    gemm_mma<<<dim3(8, 64, 1), 256, gemm_smem>>>(oj);
}

// round 7
// speedup vs baseline: 5.3700x; 1.0369x over previous
#include <cuda_runtime.h>
#include <cuda_fp16.h>
#include <cstdint>

#define SEQ    2048
#define DMODEL 1024
#define NHEAD  16
#define DVDIM  64
#define NBATCH 4
#define MROWS  (NBATCH * SEQ)   // 8192
#define MWORDS (SEQ / 32)
#define LOG2E  1.4426950408889634f

// ---------------- scratch (device globals) ----------------------------------
__device__ __align__(16) __half g_qsh[MROWS * DMODEL];
__device__ __align__(16) __half g_qsl[MROWS * DMODEL];
__device__ __align__(16) __half g_ksh[MROWS * DMODEL];
__device__ __align__(16) __half g_vsh[MROWS * DMODEL];
// projected Q/K/V for attention
__device__ __align__(16) __half g_qhi[MROWS * DMODEL];
__device__ __align__(16) __half g_qlo[MROWS * DMODEL];
__device__ __align__(16) __half g_khi[MROWS * DMODEL];
__device__ __align__(16) __half g_vhi[MROWS * DMODEL];
// attention context
__device__ __align__(16) __half g_chi[MROWS * DMODEL];
// weights fp16 (4 matrices packed)
__device__ __align__(16) __half g_w16[4 * DMODEL * DMODEL];
__device__ unsigned g_mbits[SEQ * MWORDS];
__device__ int g_mode;

// ---------------- PTX helpers (sm_103-safe) ---------------------------------
__device__ __forceinline__ uint32_t smem_u32(const void* p) {
    uint32_t a;
    asm("{ .reg .u64 t; cvta.to.shared.u64 t, %1; cvt.u32.u64 %0, t; }" : "=r"(a) : "l"(p));
    return a;
}
#define CP_ASYNC16(dst, src) \
    asm volatile("cp.async.ca.shared.global [%0], [%1], 16;" :: "r"(dst), "l"(src))
#define CP_COMMIT() asm volatile("cp.async.commit_group;" ::: "memory")
#define CP_WAIT(n)  asm volatile("cp.async.wait_group %0;" :: "n"(n) : "memory")

__device__ __forceinline__ void ldsm4(uint32_t* r, uint32_t addr) {
    asm volatile("ldmatrix.sync.aligned.m8n8.x4.shared.b16 {%0,%1,%2,%3}, [%4];"
                 : "=r"(r[0]), "=r"(r[1]), "=r"(r[2]), "=r"(r[3]) : "r"(addr));
}
__device__ __forceinline__ void ldsm2(uint32_t* r, uint32_t addr) {
    asm volatile("ldmatrix.sync.aligned.m8n8.x2.shared.b16 {%0,%1}, [%2];"
                 : "=r"(r[0]), "=r"(r[1]) : "r"(addr));
}
__device__ __forceinline__ void ldsm4t(uint32_t* r, uint32_t addr) {
    asm volatile("ldmatrix.sync.aligned.m8n8.x4.trans.shared.b16 {%0,%1,%2,%3}, [%4];"
                 : "=r"(r[0]), "=r"(r[1]), "=r"(r[2]), "=r"(r[3]) : "r"(addr));
}
__device__ __forceinline__ void mma_f16(float* d, const uint32_t* a, const uint32_t* b) {
    asm volatile(
        "mma.sync.aligned.m16n8k16.row.col.f32.f16.f16.f32 "
        "{%0,%1,%2,%3}, {%4,%5,%6,%7}, {%8,%9}, {%0,%1,%2,%3};"
        : "+f"(d[0]), "+f"(d[1]), "+f"(d[2]), "+f"(d[3])
        : "r"(a[0]), "r"(a[1]), "r"(a[2]), "r"(a[3]), "r"(b[0]), "r"(b[1]));
}
__device__ __forceinline__ float ex2f(float x) {
    float r; asm("ex2.approx.f32 %0, %1;" : "=f"(r) : "f"(x)); return r;
}
__device__ __forceinline__ uint32_t packh2(float lo, float hi) {
    uint32_t d; asm("cvt.rn.f16x2.f32 %0, %1, %2;" : "=r"(d) : "f"(hi), "f"(lo)); return d;
}

// ---------------- mask handling ----------------------------------------------
__global__ void detect_mask(const unsigned* __restrict__ m) {
    __shared__ int f[4];
    int t = threadIdx.x;
    if (t < 4) f[t] = 0;
    __syncthreads();
    int fu8 = 0, ff16 = 0, fbf16 = 0, ff32 = 0;
    for (int i = t; i < 4096; i += 256) {
        unsigned w = m[i];
        if (w == 0x3F800000u) ff32 = 1;
        if (w == 0x3F803F80u || w == 0x00003F80u) fbf16 = 1;
        if (w == 0x3C003C00u || w == 0x00003C00u || w == 0x3C000000u) ff16 = 1;
        if ((w & 0xFEFEFEFEu) == 0u && w > 1u) fu8 = 1;
    }
    if (fu8)  atomicOr(&f[0], 1);
    if (ff16) atomicOr(&f[1], 1);
    if (fbf16) atomicOr(&f[2], 1);
    if (ff32) atomicOr(&f[3], 1);
    __syncthreads();
    if (t == 0) {
        int mode;
        if (f[1]) mode = 4;
        else if (f[2]) mode = 3;
        else if (f[3]) mode = 2;
        else if (f[0]) mode = 1;
        else mode = 0;
        g_mode = mode;
    }
}

__global__ void pack_mask(const void* __restrict__ mp) {
    int idx = blockIdx.x * blockDim.x + threadIdx.x;
    int mode = g_mode;
    long base = (long)idx * 32;
    unsigned bits = 0;
    if (mode == 0) {
        const int* p = (const int*)mp;
        #pragma unroll 8
        for (int j = 0; j < 32; j++) if (p[base + j] != 0) bits |= 1u << j;
    } else if (mode == 1) {
        const unsigned char* p = (const unsigned char*)mp;
        #pragma unroll 8
        for (int j = 0; j < 32; j++) if (p[base + j] != 0) bits |= 1u << j;
    } else if (mode == 2) {
        const float* p = (const float*)mp;
        #pragma unroll 8
        for (int j = 0; j < 32; j++) if (p[base + j] != 0.0f) bits |= 1u << j;
    } else {
        const unsigned short* p = (const unsigned short*)mp;
        #pragma unroll 8
        for (int j = 0; j < 32; j++) if (p[base + j] != 0) bits |= 1u << j;
    }
    g_mbits[idx] = bits;
}

// ---------------- prep: fp32 -> fp16 (q: hi+lo; k,v: hi) ---------------------
__global__ void split3_f16(const float4* __restrict__ q, const float4* __restrict__ k,
                           const float4* __restrict__ v,
                           __half* __restrict__ qh, __half* __restrict__ ql,
                           __half* __restrict__ kh, __half* __restrict__ vh, int n4)
{
    int i = blockIdx.x * blockDim.x + threadIdx.x;
    if (i >= n4) return;
    int z = blockIdx.y;
    const float4* x = (z == 0) ? q : (z == 1) ? k : v;
    __half* hp = (z == 0) ? qh : (z == 1) ? kh : vh;
    float4 vv = x[i];
    float f[4] = {vv.x, vv.y, vv.z, vv.w};
    __half h[4];
    #pragma unroll
    for (int j = 0; j < 4; j++) h[j] = __float2half_rn(f[j]);
    __half2* hq = (__half2*)hp + 2 * i;
    hq[0] = __half2{h[0], h[1]}; hq[1] = __half2{h[2], h[3]};
    if (z == 0) {
        __half l[4];
        #pragma unroll
        for (int j = 0; j < 4; j++) l[j] = __float2half_rn(f[j] - __half2float(h[j]));
        __half2* lq = (__half2*)ql + 2 * i;
        lq[0] = __half2{l[0], l[1]}; lq[1] = __half2{l[2], l[3]};
    }
}

// ---------------- prep: weights fp32 -> fp16 (4 matrices) --------------------
__global__ void convw4_f16(const float4* __restrict__ wq, const float4* __restrict__ wk,
                           const float4* __restrict__ wv, const float4* __restrict__ wo,
                           __half* __restrict__ out, int n4)
{
    int i = blockIdx.x * blockDim.x + threadIdx.x;
    if (i >= n4) return;
    int z = blockIdx.y;
    const float4* x = (z == 0) ? wq : (z == 1) ? wk : (z == 2) ? wv : wo;
    float4 vv = x[i];
    __half2* op = (__half2*)(out + (size_t)z * DMODEL * DMODEL) + 2 * i;
    op[0] = __half2{__float2half_rn(vv.x), __float2half_rn(vv.y)};
    op[1] = __half2{__float2half_rn(vv.z), __float2half_rn(vv.w)};
}

// ---------------- mma.sync fp16 GEMM: Y[M,1024] = A @ B^T + bias -------------
// CTA 128x128, 4 warps (2x2), warp tile 64x64. BK=32, 3-stage cp.async ring.
#define LDA_B   80
#define TILE_B  10240
#define STAGE_B 30720
#define NITER   (DMODEL / 32)

struct Job {
    const __half* A1; const __half* A2; const __half* B1;
    const float* bias;
    float* Yf; __half* H1; __half* H2;
    int mode; float scale;
};
struct Jobs3 { Job j[3]; };

__global__ void __launch_bounds__(128) gemm_mma(Jobs3 jobs)
{
    extern __shared__ char sm[];
    uint32_t smb = smem_u32(sm);
    Job jb = jobs.j[blockIdx.z];
    const bool two = (jb.A2 != nullptr);
    int tid = threadIdx.x, lane = tid & 31, wid = tid >> 5;
    int wm = wid >> 1, wn = wid & 1;          // 2 x 2 warp grid, 64x64 tiles
    int m0 = blockIdx.y * 128, n0 = blockIdx.x * 128;

    float acc[4][8][4];
    #pragma unroll
    for (int i = 0; i < 4; i++)
        #pragma unroll
        for (int j = 0; j < 8; j++)
            #pragma unroll
            for (int q = 0; q < 4; q++) acc[i][j][q] = 0.0f;

    const __half* A1p = jb.A1; const __half* A2p = jb.A2; const __half* B1p = jb.B1;

    // per stage: 512 16B-chunks per tile, 128 threads -> 4 chunks per tile
    auto issue = [&](int t) {
        uint32_t st = smb + (t % 3) * STAGE_B;
        int k0 = t * 32;
        #pragma unroll
        for (int i = 0; i < 4; i++) {
            int idx = tid + i * 128;
            int r = idx >> 2, c = idx & 3;
            uint32_t d = st + r * LDA_B + c * 16;
            size_t ga = (size_t)(m0 + r) * DMODEL + k0 + c * 8;
            size_t gb = (size_t)(n0 + r) * DMODEL + k0 + c * 8;
            CP_ASYNC16(d,            A1p + ga);
            if (two) CP_ASYNC16(d + TILE_B, A2p + ga);
            CP_ASYNC16(d + 2*TILE_B, B1p + gb);
        }
        CP_COMMIT();
    };
    issue(0);
    issue(1);

    for (int t = 0; t < NITER; t++) {
        if (t + 1 < NITER) { CP_WAIT(1); } else { CP_WAIT(0); }
        __syncthreads();
        if (t + 2 < NITER) issue(t + 2);

        uint32_t st = smb + (t % 3) * STAGE_B;
        uint32_t aA = st + (wm * 64 + (lane & 15)) * LDA_B + (lane >> 4) * 16;
        uint32_t aB = st + 2 * TILE_B + (wn * 64 + (lane & 7)) * LDA_B + (lane >> 3) * 16;

        uint32_t bh[8][4];
        #pragma unroll
        for (int ni = 0; ni < 8; ni++) ldsm4(bh[ni], aB + ni * 8 * LDA_B);

        #pragma unroll
        for (int ks = 0; ks < 2; ks++) {
            uint32_t ah[4][4], al[4][4];
            #pragma unroll
            for (int mi = 0; mi < 4; mi++) {
                ldsm4(ah[mi], aA + mi * 16 * LDA_B + ks * 32);
                if (two) ldsm4(al[mi], aA + mi * 16 * LDA_B + ks * 32 + TILE_B);
            }
            #pragma unroll
            for (int mi = 0; mi < 4; mi++)
                #pragma unroll
                for (int ni = 0; ni < 8; ni++) {
                    mma_f16(acc[mi][ni], ah[mi], &bh[ni][2 * ks]);
                    if (two) mma_f16(acc[mi][ni], al[mi], &bh[ni][2 * ks]);
                }
        }
    }

    int er = lane >> 2, ec = (lane & 3) * 2;
    #pragma unroll
    for (int mi = 0; mi < 4; mi++) {
        #pragma unroll
        for (int ni = 0; ni < 8; ni++) {
            int row = m0 + wm * 64 + mi * 16 + er;
            int col = n0 + wn * 64 + ni * 8 + ec;
            float b0 = jb.bias[col], b1 = jb.bias[col + 1];
            float x00 = acc[mi][ni][0] + b0, x01 = acc[mi][ni][1] + b1;
            float x10 = acc[mi][ni][2] + b0, x11 = acc[mi][ni][3] + b1;
            if (jb.mode == 0) {
                *(float2*)(jb.Yf + (size_t)row * DMODEL + col) = float2{x00, x01};
                *(float2*)(jb.Yf + (size_t)(row + 8) * DMODEL + col) = float2{x10, x11};
            } else {
                x00 *= jb.scale; x01 *= jb.scale; x10 *= jb.scale; x11 *= jb.scale;
                __half h00 = __float2half_rn(x00), h01 = __float2half_rn(x01);
                __half h10 = __float2half_rn(x10), h11 = __float2half_rn(x11);
                *(__half2*)(jb.H1 + (size_t)row * DMODEL + col) = __half2{h00, h01};
                *(__half2*)(jb.H1 + (size_t)(row + 8) * DMODEL + col) = __half2{h10, h11};
                if (jb.mode == 1) {
                    __half l00 = __float2half_rn(x00 - __half2float(h00));
                    __half l01 = __float2half_rn(x01 - __half2float(h01));
                    __half l10 = __float2half_rn(x10 - __half2float(h10));
                    __half l11 = __float2half_rn(x11 - __half2float(h11));
                    *(__half2*)(jb.H2 + (size_t)row * DMODEL + col) = __half2{l00, l01};
                    *(__half2*)(jb.H2 + (size_t)(row + 8) * DMODEL + col) = __half2{l10, l11};
                }
            }
        }
    }
}

// ---------------- fused MMA flash attention (unchanged from R6) --------------
#define FSTR 72
#define MASKVAL 1.4426950409e-9f

__global__ void __launch_bounds__(128) flash_mma(
    const __half* __restrict__ qhi, const __half* __restrict__ qlo,
    const __half* __restrict__ khi, const __half* __restrict__ vhi,
    __half* __restrict__ chi)
{
    extern __shared__ __half sh[];
    const int O_QHI = 0, O_QLO = 9216;
    const int O_KH[2] = {18432, 23040};
    const int O_V[2]  = {27648, 32256};
    uint32_t sb = smem_u32(sh);

    int tid = threadIdx.x, lane = tid & 31, wm = tid >> 5;
    int q0 = blockIdx.x * 128, h = blockIdx.y, b = blockIdx.z;
    size_t rowbase = (size_t)b * SEQ;
    int r4 = lane >> 2, c2 = lane & 3;

    {
        const __half* qh = qhi + (rowbase + q0) * DMODEL + h * 64;
        const __half* ql = qlo + (rowbase + q0) * DMODEL + h * 64;
        #pragma unroll
        for (int c = tid; c < 1024; c += 128) {
            int r = c >> 3, dc = c & 7;
            CP_ASYNC16(sb + (O_QHI + r * FSTR + dc * 8) * 2, qh + (size_t)r * DMODEL + dc * 8);
            CP_ASYNC16(sb + (O_QLO + r * FSTR + dc * 8) * 2, ql + (size_t)r * DMODEL + dc * 8);
        }
        CP_COMMIT();
    }
    const __half* kbh = khi + rowbase * DMODEL + h * 64;
    const __half* vb  = vhi + rowbase * DMODEL + h * 64;

    auto issue_kv = [&](int t) {
        int st = t & 1;
        int k0 = t * 64;
        #pragma unroll
        for (int c = tid; c < 512; c += 128) {
            int r = c >> 3, dc = c & 7;
            size_t g = (size_t)(k0 + r) * DMODEL + dc * 8;
            CP_ASYNC16(sb + (O_KH[st] + r * FSTR + dc * 8) * 2, kbh + g);
            CP_ASYNC16(sb + (O_V[st]  + r * FSTR + dc * 8) * 2, vb + g);
        }
        CP_COMMIT();
    };
    issue_kv(0);
    issue_kv(1);

    float O[2][8][4];
    #pragma unroll
    for (int mi = 0; mi < 2; mi++)
        #pragma unroll
        for (int ni = 0; ni < 8; ni++)
            #pragma unroll
            for (int q = 0; q < 4; q++) O[mi][ni][q] = 0.0f;
    float lsum[4] = {0.f, 0.f, 0.f, 0.f};
    float mrow[4] = {-1e30f, -1e30f, -1e30f, -1e30f};

    for (int t = 0; t < SEQ / 64; t++) {
        if (t < SEQ / 64 - 2) { CP_WAIT(1); } else { CP_WAIT(0); }
        __syncthreads();
        int st = t & 1;

        uint2 mw[2][2];
        #pragma unroll
        for (int mi = 0; mi < 2; mi++)
            #pragma unroll
            for (int rr = 0; rr < 2; rr++) {
                int grow = q0 + wm * 32 + mi * 16 + r4 + rr * 8;
                mw[mi][rr] = __ldg((const uint2*)&g_mbits[(size_t)grow * MWORDS + 2 * t]);
            }

        float S[2][8][4];
        #pragma unroll
        for (int mi = 0; mi < 2; mi++)
            #pragma unroll
            for (int ni = 0; ni < 8; ni++)
                #pragma unroll
                for (int q = 0; q < 4; q++) S[mi][ni][q] = 0.0f;

        #pragma unroll
        for (int ks = 0; ks < 4; ks++) {
            uint32_t aH[2][4], aL[2][4];
            #pragma unroll
            for (int mi = 0; mi < 2; mi++) {
                uint32_t abase = sb + (((wm * 32 + mi * 16 + (lane & 15)) * FSTR) +
                                       (lane >> 4) * 8 + ks * 16) * 2;
                ldsm4(aH[mi], abase);
                ldsm4(aL[mi], abase + O_QLO * 2);
            }
            uint32_t bH[8][2];
            #pragma unroll
            for (int ni = 0; ni < 8; ni++) {
                uint32_t boff = ((ni * 8 + (lane & 7)) * FSTR + ks * 16 + ((lane >> 3) & 1) * 8) * 2;
                ldsm2(bH[ni], sb + O_KH[st] * 2 + boff);
            }
            #pragma unroll
            for (int mi = 0; mi < 2; mi++)
                #pragma unroll
                for (int ni = 0; ni < 8; ni++) {
                    mma_f16(S[mi][ni], aH[mi], bH[ni]);
                    mma_f16(S[mi][ni], aL[mi], bH[ni]);
                }
        }

        float mnew[4] = {mrow[0], mrow[1], mrow[2], mrow[3]};
        #pragma unroll
        for (int mi = 0; mi < 2; mi++)
            #pragma unroll
            for (int ni = 0; ni < 8; ni++) {
                uint32_t w0 = (ni < 4) ? mw[mi][0].x : mw[mi][0].y;
                uint32_t w1 = (ni < 4) ? mw[mi][1].x : mw[mi][1].y;
                int shf = (ni & 3) * 8 + 2 * c2;
                if ((w0 >> shf) & 1u)       S[mi][ni][0] = MASKVAL;
                if ((w0 >> (shf + 1)) & 1u) S[mi][ni][1] = MASKVAL;
                if ((w1 >> shf) & 1u)       S[mi][ni][2] = MASKVAL;
                if ((w1 >> (shf + 1)) & 1u) S[mi][ni][3] = MASKVAL;
                mnew[mi * 2 + 0] = fmaxf(mnew[mi * 2 + 0], fmaxf(S[mi][ni][0], S[mi][ni][1]));
                mnew[mi * 2 + 1] = fmaxf(mnew[mi * 2 + 1], fmaxf(S[mi][ni][2], S[mi][ni][3]));
            }
        #pragma unroll
        for (int j = 0; j < 4; j++) {
            mnew[j] = fmaxf(mnew[j], __shfl_xor_sync(0xffffffffu, mnew[j], 1));
            mnew[j] = fmaxf(mnew[j], __shfl_xor_sync(0xffffffffu, mnew[j], 2));
        }
        float al[4];
        #pragma unroll
        for (int j = 0; j < 4; j++) {
            al[j] = ex2f(mrow[j] - mnew[j]);
            mrow[j] = mnew[j];
            lsum[j] *= al[j];
        }
        #pragma unroll
        for (int mi = 0; mi < 2; mi++)
            #pragma unroll
            for (int ni = 0; ni < 8; ni++) {
                O[mi][ni][0] *= al[mi * 2];     O[mi][ni][1] *= al[mi * 2];
                O[mi][ni][2] *= al[mi * 2 + 1]; O[mi][ni][3] *= al[mi * 2 + 1];
            }

        uint32_t pa[2][4][4];
        #pragma unroll
        for (int mi = 0; mi < 2; mi++)
            #pragma unroll
            for (int ni = 0; ni < 8; ni++) {
                float p0 = ex2f(S[mi][ni][0] - mnew[mi * 2]);
                float p1 = ex2f(S[mi][ni][1] - mnew[mi * 2]);
                float p2 = ex2f(S[mi][ni][2] - mnew[mi * 2 + 1]);
                float p3 = ex2f(S[mi][ni][3] - mnew[mi * 2 + 1]);
                lsum[mi * 2]     += p0 + p1;
                lsum[mi * 2 + 1] += p2 + p3;
                int ks = ni >> 1, half = ni & 1;
                pa[mi][ks][half * 2 + 0] = packh2(p0, p1);
                pa[mi][ks][half * 2 + 1] = packh2(p2, p3);
            }

        #pragma unroll
        for (int ks = 0; ks < 4; ks++) {
            #pragma unroll
            for (int nn = 0; nn < 4; nn++) {
                uint32_t vb4[4];
                int key = ks * 16 + (lane & 7) + ((lane >> 3) & 1) * 8;
                int dim = nn * 16 + ((lane >> 4) & 1) * 8;
                ldsm4t(vb4, sb + (O_V[st] + key * FSTR + dim) * 2);
                mma_f16(O[0][2 * nn],     pa[0][ks], &vb4[0]);
                mma_f16(O[0][2 * nn + 1], pa[0][ks], &vb4[2]);
                mma_f16(O[1][2 * nn],     pa[1][ks], &vb4[0]);
                mma_f16(O[1][2 * nn + 1], pa[1][ks], &vb4[2]);
            }
        }
        __syncthreads();
        if (t + 2 < SEQ / 64) issue_kv(t + 2);
    }

    #pragma unroll
    for (int j = 0; j < 4; j++) {
        lsum[j] += __shfl_xor_sync(0xffffffffu, lsum[j], 1);
        lsum[j] += __shfl_xor_sync(0xffffffffu, lsum[j], 2);
        lsum[j] = 1.0f / lsum[j];
    }
    #pragma unroll
    for (int mi = 0; mi < 2; mi++)
        #pragma unroll
        for (int ni = 0; ni < 8; ni++) {
            size_t grow = rowbase + q0 + wm * 32 + mi * 16 + r4;
            int col = h * 64 + ni * 8 + 2 * c2;
            float x00 = O[mi][ni][0] * lsum[mi * 2];
            float x01 = O[mi][ni][1] * lsum[mi * 2];
            float x10 = O[mi][ni][2] * lsum[mi * 2 + 1];
            float x11 = O[mi][ni][3] * lsum[mi * 2 + 1];
            *(__half2*)(chi + grow * DMODEL + col) =
                __half2{__float2half_rn(x00), __float2half_rn(x01)};
            *(__half2*)(chi + (grow + 8) * DMODEL + col) =
                __half2{__float2half_rn(x10), __float2half_rn(x11)};
        }
}

// ---------------- launch ------------------------------------------------------
extern "C" void kernel_launch(void* const* d_in, const int* in_sizes, int n_in,
                              void* d_out, int out_size)
{
    const float* q    = (const float*)d_in[0];
    const float* k    = (const float*)d_in[1];
    const float* v    = (const float*)d_in[2];
    const void*  mask = d_in[3];
    const float* Wq   = (const float*)d_in[4];
    const float* bq   = (const float*)d_in[5];
    const float* Wk   = (const float*)d_in[6];
    const float* bk   = (const float*)d_in[7];
    const float* Wv   = (const float*)d_in[8];
    const float* bv   = (const float*)d_in[9];
    const float* Wo   = (const float*)d_in[10];
    const float* bo   = (const float*)d_in[11];

    __half *qsh, *qsl, *ksh, *vsh;
    __half *qhi, *qlo, *khi, *vhi, *chi, *w16;
    cudaGetSymbolAddress((void**)&qsh, g_qsh);
    cudaGetSymbolAddress((void**)&qsl, g_qsl);
    cudaGetSymbolAddress((void**)&ksh, g_ksh);
    cudaGetSymbolAddress((void**)&vsh, g_vsh);
    cudaGetSymbolAddress((void**)&qhi, g_qhi);
    cudaGetSymbolAddress((void**)&qlo, g_qlo);
    cudaGetSymbolAddress((void**)&khi, g_khi);
    cudaGetSymbolAddress((void**)&vhi, g_vhi);
    cudaGetSymbolAddress((void**)&chi, g_chi);
    cudaGetSymbolAddress((void**)&w16, g_w16);

    const int gemm_smem = 3 * STAGE_B;   // 92160
    const int flash_smem = 36864 * 2;    // 73728
    static bool attr_set = false;
    if (!attr_set) {
        cudaFuncSetAttribute(gemm_mma, cudaFuncAttributeMaxDynamicSharedMemorySize, gemm_smem);
        cudaFuncSetAttribute(flash_mma, cudaFuncAttributeMaxDynamicSharedMemorySize, flash_smem);
        attr_set = true;
    }

    const int nACT4 = MROWS * DMODEL / 4;
    const int nW4   = DMODEL * DMODEL / 4;
    const float qscale = 0.125f * LOG2E;

    detect_mask<<<1, 256>>>((const unsigned*)mask);
    pack_mask<<<(SEQ * MWORDS) / 256, 256>>>(mask);

    split3_f16<<<dim3(nACT4 / 256, 3), 256>>>((const float4*)q, (const float4*)k,
        (const float4*)v, qsh, qsl, ksh, vsh, nACT4);
    convw4_f16<<<dim3(nW4 / 256, 4), 256>>>((const float4*)Wq, (const float4*)Wk,
        (const float4*)Wv, (const float4*)Wo, w16, nW4);

    // merged Q/K/V projections: Q 2-term->hi/lo, K 1-term->hi, V 1-term->hi
    Jobs3 pj;
    pj.j[0] = Job{qsh, qsl,     w16,                     bq, nullptr, qhi, qlo, 1, qscale};
    pj.j[1] = Job{ksh, nullptr, w16 + 1 * DMODEL*DMODEL, bk, nullptr, khi, nullptr, 2, 1.0f};
    pj.j[2] = Job{vsh, nullptr, w16 + 2 * DMODEL*DMODEL, bv, nullptr, vhi, nullptr, 2, 1.0f};
    gemm_mma<<<dim3(8, 64, 3), 128, gemm_smem>>>(pj);

    flash_mma<<<dim3(SEQ / 128, NHEAD, NBATCH), 128, flash_smem>>>(
        qhi, qlo, khi, vhi, chi);

    // output projection: 1-term A
    Jobs3 oj;
    oj.j[0] = Job{chi, nullptr, w16 + 3 * DMODEL*DMODEL, bo, (float*)d_out, nullptr, nullptr, 0, 1.0f};
    oj.j[1] = oj.j[0];
    oj.j[2] = oj.j[0];
    gemm_mma<<<dim3(8, 64, 1), 128, gemm_smem>>>(oj);
}

// round 8
// speedup vs baseline: 7.5350x; 1.4032x over previous
#include <cuda_runtime.h>
#include <cuda_fp16.h>
#include <cstdint>

#define SEQ    2048
#define DMODEL 1024
#define NHEAD  16
#define DVDIM  64
#define NBATCH 4
#define MROWS  (NBATCH * SEQ)   // 8192
#define MWORDS (SEQ / 32)
#define LOG2E  1.4426950408889634f

// ---------------- scratch (device globals) ----------------------------------
__device__ __align__(16) __half g_qsh[MROWS * DMODEL];
__device__ __align__(16) __half g_ksh[MROWS * DMODEL];
__device__ __align__(16) __half g_vsh[MROWS * DMODEL];
// projected Q/K/V for attention (all fp16 hi only)
__device__ __align__(16) __half g_qhi[MROWS * DMODEL];
__device__ __align__(16) __half g_khi[MROWS * DMODEL];
__device__ __align__(16) __half g_vhi[MROWS * DMODEL];
// attention context
__device__ __align__(16) __half g_chi[MROWS * DMODEL];
// weights fp16 (4 matrices packed)
__device__ __align__(16) __half g_w16[4 * DMODEL * DMODEL];
__device__ unsigned g_mbits[SEQ * MWORDS];
__device__ int g_mode;

// ---------------- PTX helpers (sm_103-safe) ---------------------------------
__device__ __forceinline__ uint32_t smem_u32(const void* p) {
    uint32_t a;
    asm("{ .reg .u64 t; cvta.to.shared.u64 t, %1; cvt.u32.u64 %0, t; }" : "=r"(a) : "l"(p));
    return a;
}
#define CP_ASYNC16(dst, src) \
    asm volatile("cp.async.ca.shared.global [%0], [%1], 16;" :: "r"(dst), "l"(src))
#define CP_COMMIT() asm volatile("cp.async.commit_group;" ::: "memory")
#define CP_WAIT(n)  asm volatile("cp.async.wait_group %0;" :: "n"(n) : "memory")

__device__ __forceinline__ void ldsm4(uint32_t* r, uint32_t addr) {
    asm volatile("ldmatrix.sync.aligned.m8n8.x4.shared.b16 {%0,%1,%2,%3}, [%4];"
                 : "=r"(r[0]), "=r"(r[1]), "=r"(r[2]), "=r"(r[3]) : "r"(addr));
}
__device__ __forceinline__ void ldsm2(uint32_t* r, uint32_t addr) {
    asm volatile("ldmatrix.sync.aligned.m8n8.x2.shared.b16 {%0,%1}, [%2];"
                 : "=r"(r[0]), "=r"(r[1]) : "r"(addr));
}
__device__ __forceinline__ void ldsm4t(uint32_t* r, uint32_t addr) {
    asm volatile("ldmatrix.sync.aligned.m8n8.x4.trans.shared.b16 {%0,%1,%2,%3}, [%4];"
                 : "=r"(r[0]), "=r"(r[1]), "=r"(r[2]), "=r"(r[3]) : "r"(addr));
}
__device__ __forceinline__ void mma_f16(float* d, const uint32_t* a, const uint32_t* b) {
    asm volatile(
        "mma.sync.aligned.m16n8k16.row.col.f32.f16.f16.f32 "
        "{%0,%1,%2,%3}, {%4,%5,%6,%7}, {%8,%9}, {%0,%1,%2,%3};"
        : "+f"(d[0]), "+f"(d[1]), "+f"(d[2]), "+f"(d[3])
        : "r"(a[0]), "r"(a[1]), "r"(a[2]), "r"(a[3]), "r"(b[0]), "r"(b[1]));
}
__device__ __forceinline__ float ex2f(float x) {
    float r; asm("ex2.approx.f32 %0, %1;" : "=f"(r) : "f"(x)); return r;
}
__device__ __forceinline__ uint32_t packh2(float lo, float hi) {
    uint32_t d; asm("cvt.rn.f16x2.f32 %0, %1, %2;" : "=r"(d) : "f"(hi), "f"(lo)); return d;
}

// ---------------- mask handling ----------------------------------------------
__global__ void detect_mask(const unsigned* __restrict__ m) {
    __shared__ int f[4];
    int t = threadIdx.x;
    if (t < 4) f[t] = 0;
    __syncthreads();
    int fu8 = 0, ff16 = 0, fbf16 = 0, ff32 = 0;
    for (int i = t; i < 4096; i += 256) {
        unsigned w = m[i];
        if (w == 0x3F800000u) ff32 = 1;
        if (w == 0x3F803F80u || w == 0x00003F80u) fbf16 = 1;
        if (w == 0x3C003C00u || w == 0x00003C00u || w == 0x3C000000u) ff16 = 1;
        if ((w & 0xFEFEFEFEu) == 0u && w > 1u) fu8 = 1;
    }
    if (fu8)  atomicOr(&f[0], 1);
    if (ff16) atomicOr(&f[1], 1);
    if (fbf16) atomicOr(&f[2], 1);
    if (ff32) atomicOr(&f[3], 1);
    __syncthreads();
    if (t == 0) {
        int mode;
        if (f[1]) mode = 4;
        else if (f[2]) mode = 3;
        else if (f[3]) mode = 2;
        else if (f[0]) mode = 1;
        else mode = 0;
        g_mode = mode;
    }
}

__global__ void pack_mask(const void* __restrict__ mp) {
    int idx = blockIdx.x * blockDim.x + threadIdx.x;
    int mode = g_mode;
    long base = (long)idx * 32;
    unsigned bits = 0;
    if (mode == 0) {
        const int* p = (const int*)mp;
        #pragma unroll 8
        for (int j = 0; j < 32; j++) if (p[base + j] != 0) bits |= 1u << j;
    } else if (mode == 1) {
        const unsigned char* p = (const unsigned char*)mp;
        #pragma unroll 8
        for (int j = 0; j < 32; j++) if (p[base + j] != 0) bits |= 1u << j;
    } else if (mode == 2) {
        const float* p = (const float*)mp;
        #pragma unroll 8
        for (int j = 0; j < 32; j++) if (p[base + j] != 0.0f) bits |= 1u << j;
    } else {
        const unsigned short* p = (const unsigned short*)mp;
        #pragma unroll 8
        for (int j = 0; j < 32; j++) if (p[base + j] != 0) bits |= 1u << j;
    }
    g_mbits[idx] = bits;
}

// ---------------- prep: fp32 -> fp16 (3 activations, hi only) ----------------
__global__ void conv3_f16(const float4* __restrict__ q, const float4* __restrict__ k,
                          const float4* __restrict__ v,
                          __half* __restrict__ qh, __half* __restrict__ kh,
                          __half* __restrict__ vh, int n4)
{
    int i = blockIdx.x * blockDim.x + threadIdx.x;
    if (i >= n4) return;
    int z = blockIdx.y;
    const float4* x = (z == 0) ? q : (z == 1) ? k : v;
    __half* hp = (z == 0) ? qh : (z == 1) ? kh : vh;
    float4 vv = x[i];
    __half2* hq = (__half2*)hp + 2 * i;
    hq[0] = __half2{__float2half_rn(vv.x), __float2half_rn(vv.y)};
    hq[1] = __half2{__float2half_rn(vv.z), __float2half_rn(vv.w)};
}

// ---------------- prep: weights fp32 -> fp16 (4 matrices) --------------------
__global__ void convw4_f16(const float4* __restrict__ wq, const float4* __restrict__ wk,
                           const float4* __restrict__ wv, const float4* __restrict__ wo,
                           __half* __restrict__ out, int n4)
{
    int i = blockIdx.x * blockDim.x + threadIdx.x;
    if (i >= n4) return;
    int z = blockIdx.y;
    const float4* x = (z == 0) ? wq : (z == 1) ? wk : (z == 2) ? wv : wo;
    float4 vv = x[i];
    __half2* op = (__half2*)(out + (size_t)z * DMODEL * DMODEL) + 2 * i;
    op[0] = __half2{__float2half_rn(vv.x), __float2half_rn(vv.y)};
    op[1] = __half2{__float2half_rn(vv.z), __float2half_rn(vv.w)};
}

// ---------------- mma.sync fp16 GEMM: Y[M,1024] = A @ B^T + bias -------------
// CTA 128x128, 4 warps (2x2), warp tile 64x64. BK=32, 3-stage cp.async ring.
#define LDA_B   80
#define TILE_B  10240
#define STAGE_B 20480      // A + B (1-term)
#define NITER   (DMODEL / 32)

struct Job {
    const __half* A1; const __half* B1;
    const float* bias;
    float* Yf; __half* H1;
    int mode; float scale;   // mode 0: fp32 out; 2: fp16 out (scaled)
};
struct Jobs3 { Job j[3]; };

__global__ void __launch_bounds__(128) gemm_mma(Jobs3 jobs)
{
    extern __shared__ char sm[];
    uint32_t smb = smem_u32(sm);
    Job jb = jobs.j[blockIdx.z];
    int tid = threadIdx.x, lane = tid & 31, wid = tid >> 5;
    int wm = wid >> 1, wn = wid & 1;
    int m0 = blockIdx.y * 128, n0 = blockIdx.x * 128;

    float acc[4][8][4];
    #pragma unroll
    for (int i = 0; i < 4; i++)
        #pragma unroll
        for (int j = 0; j < 8; j++)
            #pragma unroll
            for (int q = 0; q < 4; q++) acc[i][j][q] = 0.0f;

    const __half* A1p = jb.A1; const __half* B1p = jb.B1;

    auto issue = [&](int t) {
        uint32_t st = smb + (t % 3) * STAGE_B;
        int k0 = t * 32;
        #pragma unroll
        for (int i = 0; i < 4; i++) {
            int idx = tid + i * 128;
            int r = idx >> 2, c = idx & 3;
            uint32_t d = st + r * LDA_B + c * 16;
            size_t ga = (size_t)(m0 + r) * DMODEL + k0 + c * 8;
            size_t gb = (size_t)(n0 + r) * DMODEL + k0 + c * 8;
            CP_ASYNC16(d,          A1p + ga);
            CP_ASYNC16(d + TILE_B, B1p + gb);
        }
        CP_COMMIT();
    };
    issue(0);
    issue(1);

    for (int t = 0; t < NITER; t++) {
        if (t + 1 < NITER) { CP_WAIT(1); } else { CP_WAIT(0); }
        __syncthreads();
        if (t + 2 < NITER) issue(t + 2);

        uint32_t st = smb + (t % 3) * STAGE_B;
        uint32_t aA = st + (wm * 64 + (lane & 15)) * LDA_B + (lane >> 4) * 16;
        uint32_t aB = st + TILE_B + (wn * 64 + (lane & 7)) * LDA_B + (lane >> 3) * 16;

        uint32_t bh[8][4];
        #pragma unroll
        for (int ni = 0; ni < 8; ni++) ldsm4(bh[ni], aB + ni * 8 * LDA_B);

        #pragma unroll
        for (int ks = 0; ks < 2; ks++) {
            uint32_t ah[4][4];
            #pragma unroll
            for (int mi = 0; mi < 4; mi++)
                ldsm4(ah[mi], aA + mi * 16 * LDA_B + ks * 32);
            #pragma unroll
            for (int mi = 0; mi < 4; mi++)
                #pragma unroll
                for (int ni = 0; ni < 8; ni++)
                    mma_f16(acc[mi][ni], ah[mi], &bh[ni][2 * ks]);
        }
    }

    int er = lane >> 2, ec = (lane & 3) * 2;
    #pragma unroll
    for (int mi = 0; mi < 4; mi++) {
        #pragma unroll
        for (int ni = 0; ni < 8; ni++) {
            int row = m0 + wm * 64 + mi * 16 + er;
            int col = n0 + wn * 64 + ni * 8 + ec;
            float b0 = jb.bias[col], b1 = jb.bias[col + 1];
            float x00 = acc[mi][ni][0] + b0, x01 = acc[mi][ni][1] + b1;
            float x10 = acc[mi][ni][2] + b0, x11 = acc[mi][ni][3] + b1;
            if (jb.mode == 0) {
                *(float2*)(jb.Yf + (size_t)row * DMODEL + col) = float2{x00, x01};
                *(float2*)(jb.Yf + (size_t)(row + 8) * DMODEL + col) = float2{x10, x11};
            } else {
                x00 *= jb.scale; x01 *= jb.scale; x10 *= jb.scale; x11 *= jb.scale;
                *(__half2*)(jb.H1 + (size_t)row * DMODEL + col) =
                    __half2{__float2half_rn(x00), __float2half_rn(x01)};
                *(__half2*)(jb.H1 + (size_t)(row + 8) * DMODEL + col) =
                    __half2{__float2half_rn(x10), __float2half_rn(x11)};
            }
        }
    }
}

// ---------------- fused MMA flash attention (1-term QK, 1-term PV) -----------
#define FSTR 72
#define MASKVAL 1.4426950409e-9f

__global__ void __launch_bounds__(128) flash_mma(
    const __half* __restrict__ qhi, const __half* __restrict__ khi,
    const __half* __restrict__ vhi, __half* __restrict__ chi)
{
    extern __shared__ __half sh[];
    const int O_QHI = 0;                      // 128 x 72
    const int O_KH[2] = {9216, 13824};        // 64 x 72 each
    const int O_V[2]  = {18432, 23040};       // 64 x 72 each
    uint32_t sb = smem_u32(sh);

    int tid = threadIdx.x, lane = tid & 31, wm = tid >> 5;
    int q0 = blockIdx.x * 128, h = blockIdx.y, b = blockIdx.z;
    size_t rowbase = (size_t)b * SEQ;
    int r4 = lane >> 2, c2 = lane & 3;

    {
        const __half* qh = qhi + (rowbase + q0) * DMODEL + h * 64;
        #pragma unroll
        for (int c = tid; c < 1024; c += 128) {
            int r = c >> 3, dc = c & 7;
            CP_ASYNC16(sb + (O_QHI + r * FSTR + dc * 8) * 2, qh + (size_t)r * DMODEL + dc * 8);
        }
        CP_COMMIT();
    }
    const __half* kbh = khi + rowbase * DMODEL + h * 64;
    const __half* vb  = vhi + rowbase * DMODEL + h * 64;

    auto issue_kv = [&](int t) {
        int st = t & 1;
        int k0 = t * 64;
        #pragma unroll
        for (int c = tid; c < 512; c += 128) {
            int r = c >> 3, dc = c & 7;
            size_t g = (size_t)(k0 + r) * DMODEL + dc * 8;
            CP_ASYNC16(sb + (O_KH[st] + r * FSTR + dc * 8) * 2, kbh + g);
            CP_ASYNC16(sb + (O_V[st]  + r * FSTR + dc * 8) * 2, vb + g);
        }
        CP_COMMIT();
    };
    issue_kv(0);
    issue_kv(1);

    float O[2][8][4];
    #pragma unroll
    for (int mi = 0; mi < 2; mi++)
        #pragma unroll
        for (int ni = 0; ni < 8; ni++)
            #pragma unroll
            for (int q = 0; q < 4; q++) O[mi][ni][q] = 0.0f;
    float lsum[4] = {0.f, 0.f, 0.f, 0.f};
    float mrow[4] = {-1e30f, -1e30f, -1e30f, -1e30f};

    for (int t = 0; t < SEQ / 64; t++) {
        if (t < SEQ / 64 - 2) { CP_WAIT(1); } else { CP_WAIT(0); }
        __syncthreads();
        int st = t & 1;

        uint2 mw[2][2];
        #pragma unroll
        for (int mi = 0; mi < 2; mi++)
            #pragma unroll
            for (int rr = 0; rr < 2; rr++) {
                int grow = q0 + wm * 32 + mi * 16 + r4 + rr * 8;
                mw[mi][rr] = __ldg((const uint2*)&g_mbits[(size_t)grow * MWORDS + 2 * t]);
            }

        float S[2][8][4];
        #pragma unroll
        for (int mi = 0; mi < 2; mi++)
            #pragma unroll
            for (int ni = 0; ni < 8; ni++)
                #pragma unroll
                for (int q = 0; q < 4; q++) S[mi][ni][q] = 0.0f;

        #pragma unroll
        for (int ks = 0; ks < 4; ks++) {
            uint32_t aH[2][4];
            #pragma unroll
            for (int mi = 0; mi < 2; mi++) {
                uint32_t abase = sb + (((wm * 32 + mi * 16 + (lane & 15)) * FSTR) +
                                       (lane >> 4) * 8 + ks * 16) * 2;
                ldsm4(aH[mi], abase);
            }
            uint32_t bH[8][2];
            #pragma unroll
            for (int ni = 0; ni < 8; ni++) {
                uint32_t boff = ((ni * 8 + (lane & 7)) * FSTR + ks * 16 + ((lane >> 3) & 1) * 8) * 2;
                ldsm2(bH[ni], sb + O_KH[st] * 2 + boff);
            }
            #pragma unroll
            for (int mi = 0; mi < 2; mi++)
                #pragma unroll
                for (int ni = 0; ni < 8; ni++)
                    mma_f16(S[mi][ni], aH[mi], bH[ni]);
        }

        float mnew[4] = {mrow[0], mrow[1], mrow[2], mrow[3]};
        #pragma unroll
        for (int mi = 0; mi < 2; mi++)
            #pragma unroll
            for (int ni = 0; ni < 8; ni++) {
                uint32_t w0 = (ni < 4) ? mw[mi][0].x : mw[mi][0].y;
                uint32_t w1 = (ni < 4) ? mw[mi][1].x : mw[mi][1].y;
                int shf = (ni & 3) * 8 + 2 * c2;
                if ((w0 >> shf) & 1u)       S[mi][ni][0] = MASKVAL;
                if ((w0 >> (shf + 1)) & 1u) S[mi][ni][1] = MASKVAL;
                if ((w1 >> shf) & 1u)       S[mi][ni][2] = MASKVAL;
                if ((w1 >> (shf + 1)) & 1u) S[mi][ni][3] = MASKVAL;
                mnew[mi * 2 + 0] = fmaxf(mnew[mi * 2 + 0], fmaxf(S[mi][ni][0], S[mi][ni][1]));
                mnew[mi * 2 + 1] = fmaxf(mnew[mi * 2 + 1], fmaxf(S[mi][ni][2], S[mi][ni][3]));
            }
        #pragma unroll
        for (int j = 0; j < 4; j++) {
            mnew[j] = fmaxf(mnew[j], __shfl_xor_sync(0xffffffffu, mnew[j], 1));
            mnew[j] = fmaxf(mnew[j], __shfl_xor_sync(0xffffffffu, mnew[j], 2));
        }
        float al[4];
        #pragma unroll
        for (int j = 0; j < 4; j++) {
            al[j] = ex2f(mrow[j] - mnew[j]);
            mrow[j] = mnew[j];
            lsum[j] *= al[j];
        }
        #pragma unroll
        for (int mi = 0; mi < 2; mi++)
            #pragma unroll
            for (int ni = 0; ni < 8; ni++) {
                O[mi][ni][0] *= al[mi * 2];     O[mi][ni][1] *= al[mi * 2];
                O[mi][ni][2] *= al[mi * 2 + 1]; O[mi][ni][3] *= al[mi * 2 + 1];
            }

        uint32_t pa[2][4][4];
        #pragma unroll
        for (int mi = 0; mi < 2; mi++)
            #pragma unroll
            for (int ni = 0; ni < 8; ni++) {
                float p0 = ex2f(S[mi][ni][0] - mnew[mi * 2]);
                float p1 = ex2f(S[mi][ni][1] - mnew[mi * 2]);
                float p2 = ex2f(S[mi][ni][2] - mnew[mi * 2 + 1]);
                float p3 = ex2f(S[mi][ni][3] - mnew[mi * 2 + 1]);
                lsum[mi * 2]     += p0 + p1;
                lsum[mi * 2 + 1] += p2 + p3;
                int ks = ni >> 1, half = ni & 1;
                pa[mi][ks][half * 2 + 0] = packh2(p0, p1);
                pa[mi][ks][half * 2 + 1] = packh2(p2, p3);
            }

        #pragma unroll
        for (int ks = 0; ks < 4; ks++) {
            #pragma unroll
            for (int nn = 0; nn < 4; nn++) {
                uint32_t vb4[4];
                int key = ks * 16 + (lane & 7) + ((lane >> 3) & 1) * 8;
                int dim = nn * 16 + ((lane >> 4) & 1) * 8;
                ldsm4t(vb4, sb + (O_V[st] + key * FSTR + dim) * 2);
                mma_f16(O[0][2 * nn],     pa[0][ks], &vb4[0]);
                mma_f16(O[0][2 * nn + 1], pa[0][ks], &vb4[2]);
                mma_f16(O[1][2 * nn],     pa[1][ks], &vb4[0]);
                mma_f16(O[1][2 * nn + 1], pa[1][ks], &vb4[2]);
            }
        }
        __syncthreads();
        if (t + 2 < SEQ / 64) issue_kv(t + 2);
    }

    #pragma unroll
    for (int j = 0; j < 4; j++) {
        lsum[j] += __shfl_xor_sync(0xffffffffu, lsum[j], 1);
        lsum[j] += __shfl_xor_sync(0xffffffffu, lsum[j], 2);
        lsum[j] = 1.0f / lsum[j];
    }
    #pragma unroll
    for (int mi = 0; mi < 2; mi++)
        #pragma unroll
        for (int ni = 0; ni < 8; ni++) {
            size_t grow = rowbase + q0 + wm * 32 + mi * 16 + r4;
            int col = h * 64 + ni * 8 + 2 * c2;
            float x00 = O[mi][ni][0] * lsum[mi * 2];
            float x01 = O[mi][ni][1] * lsum[mi * 2];
            float x10 = O[mi][ni][2] * lsum[mi * 2 + 1];
            float x11 = O[mi][ni][3] * lsum[mi * 2 + 1];
            *(__half2*)(chi + grow * DMODEL + col) =
                __half2{__float2half_rn(x00), __float2half_rn(x01)};
            *(__half2*)(chi + (grow + 8) * DMODEL + col) =
                __half2{__float2half_rn(x10), __float2half_rn(x11)};
        }
}

// ---------------- launch ------------------------------------------------------
extern "C" void kernel_launch(void* const* d_in, const int* in_sizes, int n_in,
                              void* d_out, int out_size)
{
    const float* q    = (const float*)d_in[0];
    const float* k    = (const float*)d_in[1];
    const float* v    = (const float*)d_in[2];
    const void*  mask = d_in[3];
    const float* Wq   = (const float*)d_in[4];
    const float* bq   = (const float*)d_in[5];
    const float* Wk   = (const float*)d_in[6];
    const float* bk   = (const float*)d_in[7];
    const float* Wv   = (const float*)d_in[8];
    const float* bv   = (const float*)d_in[9];
    const float* Wo   = (const float*)d_in[10];
    const float* bo   = (const float*)d_in[11];

    __half *qsh, *ksh, *vsh, *qhi, *khi, *vhi, *chi, *w16;
    cudaGetSymbolAddress((void**)&qsh, g_qsh);
    cudaGetSymbolAddress((void**)&ksh, g_ksh);
    cudaGetSymbolAddress((void**)&vsh, g_vsh);
    cudaGetSymbolAddress((void**)&qhi, g_qhi);
    cudaGetSymbolAddress((void**)&khi, g_khi);
    cudaGetSymbolAddress((void**)&vhi, g_vhi);
    cudaGetSymbolAddress((void**)&chi, g_chi);
    cudaGetSymbolAddress((void**)&w16, g_w16);

    const int gemm_smem = 3 * STAGE_B;    // 61440
    const int flash_smem = 27648 * 2;     // 55296
    static bool attr_set = false;
    if (!attr_set) {
        cudaFuncSetAttribute(gemm_mma, cudaFuncAttributeMaxDynamicSharedMemorySize, gemm_smem);
        cudaFuncSetAttribute(flash_mma, cudaFuncAttributeMaxDynamicSharedMemorySize, flash_smem);
        attr_set = true;
    }

    const int nACT4 = MROWS * DMODEL / 4;
    const int nW4   = DMODEL * DMODEL / 4;
    const float qscale = 0.125f * LOG2E;

    detect_mask<<<1, 256>>>((const unsigned*)mask);
    pack_mask<<<(SEQ * MWORDS) / 256, 256>>>(mask);

    conv3_f16<<<dim3(nACT4 / 256, 3), 256>>>((const float4*)q, (const float4*)k,
        (const float4*)v, qsh, ksh, vsh, nACT4);
    convw4_f16<<<dim3(nW4 / 256, 4), 256>>>((const float4*)Wq, (const float4*)Wk,
        (const float4*)Wv, (const float4*)Wo, w16, nW4);

    // merged Q/K/V projections, all 1-term fp16
    Jobs3 pj;
    pj.j[0] = Job{qsh, w16,                     bq, nullptr, qhi, 2, qscale};
    pj.j[1] = Job{ksh, w16 + 1 * DMODEL*DMODEL, bk, nullptr, khi, 2, 1.0f};
    pj.j[2] = Job{vsh, w16 + 2 * DMODEL*DMODEL, bv, nullptr, vhi, 2, 1.0f};
    gemm_mma<<<dim3(8, 64, 3), 128, gemm_smem>>>(pj);

    flash_mma<<<dim3(SEQ / 128, NHEAD, NBATCH), 128, flash_smem>>>(qhi, khi, vhi, chi);

    // output projection (1-term, fp32 out)
    Jobs3 oj;
    oj.j[0] = Job{chi, w16 + 3 * DMODEL*DMODEL, bo, (float*)d_out, nullptr, 0, 1.0f};
    oj.j[1] = oj.j[0];
    oj.j[2] = oj.j[0];
    gemm_mma<<<dim3(8, 64, 1), 128, gemm_smem>>>(oj);
}

// round 9
// speedup vs baseline: 7.5913x; 1.0075x over previous
#include <cuda_runtime.h>
#include <cuda_fp16.h>
#include <cstdint>

#define SEQ    2048
#define DMODEL 1024
#define NHEAD  16
#define DVDIM  64
#define NBATCH 4
#define MROWS  (NBATCH * SEQ)   // 8192
#define MWORDS (SEQ / 32)
#define LOG2E  1.4426950408889634f

// ---------------- scratch (device globals) ----------------------------------
__device__ __align__(16) __half g_qsh[MROWS * DMODEL];
__device__ __align__(16) __half g_ksh[MROWS * DMODEL];
__device__ __align__(16) __half g_vsh[MROWS * DMODEL];
__device__ __align__(16) __half g_qhi[MROWS * DMODEL];
__device__ __align__(16) __half g_khi[MROWS * DMODEL];
__device__ __align__(16) __half g_vhi[MROWS * DMODEL];
__device__ __align__(16) __half g_chi[MROWS * DMODEL];
__device__ __align__(16) __half g_w16[4 * DMODEL * DMODEL];
__device__ unsigned g_mbits[SEQ * MWORDS];
__device__ int g_mode;

// ---------------- PTX helpers (sm_103-safe) ---------------------------------
__device__ __forceinline__ uint32_t smem_u32(const void* p) {
    uint32_t a;
    asm("{ .reg .u64 t; cvta.to.shared.u64 t, %1; cvt.u32.u64 %0, t; }" : "=r"(a) : "l"(p));
    return a;
}
#define CP_ASYNC16(dst, src) \
    asm volatile("cp.async.ca.shared.global [%0], [%1], 16;" :: "r"(dst), "l"(src))
#define CP_COMMIT() asm volatile("cp.async.commit_group;" ::: "memory")
#define CP_WAIT(n)  asm volatile("cp.async.wait_group %0;" :: "n"(n) : "memory")

__device__ __forceinline__ void ldsm4(uint32_t* r, uint32_t addr) {
    asm volatile("ldmatrix.sync.aligned.m8n8.x4.shared.b16 {%0,%1,%2,%3}, [%4];"
                 : "=r"(r[0]), "=r"(r[1]), "=r"(r[2]), "=r"(r[3]) : "r"(addr));
}
__device__ __forceinline__ void ldsm4t(uint32_t* r, uint32_t addr) {
    asm volatile("ldmatrix.sync.aligned.m8n8.x4.trans.shared.b16 {%0,%1,%2,%3}, [%4];"
                 : "=r"(r[0]), "=r"(r[1]), "=r"(r[2]), "=r"(r[3]) : "r"(addr));
}
__device__ __forceinline__ void mma_f16(float* d, const uint32_t* a, const uint32_t* b) {
    asm volatile(
        "mma.sync.aligned.m16n8k16.row.col.f32.f16.f16.f32 "
        "{%0,%1,%2,%3}, {%4,%5,%6,%7}, {%8,%9}, {%0,%1,%2,%3};"
        : "+f"(d[0]), "+f"(d[1]), "+f"(d[2]), "+f"(d[3])
        : "r"(a[0]), "r"(a[1]), "r"(a[2]), "r"(a[3]), "r"(b[0]), "r"(b[1]));
}
// fp16-accumulator variant (packed half2 x2)
__device__ __forceinline__ void mma_f16h(uint32_t* d, const uint32_t* a, const uint32_t* b) {
    asm volatile(
        "mma.sync.aligned.m16n8k16.row.col.f16.f16.f16.f16 "
        "{%0,%1}, {%2,%3,%4,%5}, {%6,%7}, {%0,%1};"
        : "+r"(d[0]), "+r"(d[1])
        : "r"(a[0]), "r"(a[1]), "r"(a[2]), "r"(a[3]), "r"(b[0]), "r"(b[1]));
}
__device__ __forceinline__ float ex2f(float x) {
    float r; asm("ex2.approx.f32 %0, %1;" : "=f"(r) : "f"(x)); return r;
}
__device__ __forceinline__ uint32_t packh2(float lo, float hi) {
    uint32_t d; asm("cvt.rn.f16x2.f32 %0, %1, %2;" : "=r"(d) : "f"(hi), "f"(lo)); return d;
}

// ---------------- mask handling ----------------------------------------------
__global__ void detect_mask(const unsigned* __restrict__ m) {
    __shared__ int f[4];
    int t = threadIdx.x;
    if (t < 4) f[t] = 0;
    __syncthreads();
    int fu8 = 0, ff16 = 0, fbf16 = 0, ff32 = 0;
    for (int i = t; i < 4096; i += 256) {
        unsigned w = m[i];
        if (w == 0x3F800000u) ff32 = 1;
        if (w == 0x3F803F80u || w == 0x00003F80u) fbf16 = 1;
        if (w == 0x3C003C00u || w == 0x00003C00u || w == 0x3C000000u) ff16 = 1;
        if ((w & 0xFEFEFEFEu) == 0u && w > 1u) fu8 = 1;
    }
    if (fu8)  atomicOr(&f[0], 1);
    if (ff16) atomicOr(&f[1], 1);
    if (fbf16) atomicOr(&f[2], 1);
    if (ff32) atomicOr(&f[3], 1);
    __syncthreads();
    if (t == 0) {
        int mode;
        if (f[1]) mode = 4;
        else if (f[2]) mode = 3;
        else if (f[3]) mode = 2;
        else if (f[0]) mode = 1;
        else mode = 0;
        g_mode = mode;
    }
}

__global__ void pack_mask(const void* __restrict__ mp) {
    int idx = blockIdx.x * blockDim.x + threadIdx.x;
    int mode = g_mode;
    long base = (long)idx * 32;
    unsigned bits = 0;
    if (mode == 0) {
        const int* p = (const int*)mp;
        #pragma unroll 8
        for (int j = 0; j < 32; j++) if (p[base + j] != 0) bits |= 1u << j;
    } else if (mode == 1) {
        const unsigned char* p = (const unsigned char*)mp;
        #pragma unroll 8
        for (int j = 0; j < 32; j++) if (p[base + j] != 0) bits |= 1u << j;
    } else if (mode == 2) {
        const float* p = (const float*)mp;
        #pragma unroll 8
        for (int j = 0; j < 32; j++) if (p[base + j] != 0.0f) bits |= 1u << j;
    } else {
        const unsigned short* p = (const unsigned short*)mp;
        #pragma unroll 8
        for (int j = 0; j < 32; j++) if (p[base + j] != 0) bits |= 1u << j;
    }
    g_mbits[idx] = bits;
}

// ---------------- prep: fused fp32 -> fp16 conversion (7 jobs) ---------------
// z 0..2: activations (8 floats/thread); z 3..6: weights. uint4 stores.
#define NACT8 (MROWS * DMODEL / 8)   // 1048576
#define NW8   (DMODEL * DMODEL / 8)  // 131072

__global__ void conv_all(const float4* __restrict__ q, const float4* __restrict__ k,
                         const float4* __restrict__ v,
                         const float4* __restrict__ wq, const float4* __restrict__ wk,
                         const float4* __restrict__ wv, const float4* __restrict__ wo,
                         __half* __restrict__ qh, __half* __restrict__ kh,
                         __half* __restrict__ vh, __half* __restrict__ w16)
{
    int z = blockIdx.y;
    int i = blockIdx.x * blockDim.x + threadIdx.x;
    const float4* src;
    __half* dst;
    if (z < 3) {
        src = (z == 0) ? q : (z == 1) ? k : v;
        dst = (z == 0) ? qh : (z == 1) ? kh : vh;
        if (i >= NACT8) return;
    } else {
        int w = z - 3;
        src = (w == 0) ? wq : (w == 1) ? wk : (w == 2) ? wv : wo;
        dst = w16 + (size_t)w * DMODEL * DMODEL;
        if (i >= NW8) return;
    }
    float4 a = src[2 * i], b = src[2 * i + 1];
    uint4 o;
    o.x = packh2(a.x, a.y); o.y = packh2(a.z, a.w);
    o.z = packh2(b.x, b.y); o.w = packh2(b.z, b.w);
    *((uint4*)dst + i) = o;
}

// ---------------- mma.sync fp16 GEMM: Y[M,1024] = A @ B^T + bias -------------
#define LDA_B   80
#define TILE_B  10240
#define STAGE_B 20480
#define NITER   (DMODEL / 32)

struct Job {
    const __half* A1; const __half* B1;
    const float* bias;
    float* Yf; __half* H1;
    int mode; float scale;
};
struct Jobs3 { Job j[3]; };

__global__ void __launch_bounds__(128) gemm_mma(Jobs3 jobs)
{
    extern __shared__ char sm[];
    uint32_t smb = smem_u32(sm);
    Job jb = jobs.j[blockIdx.z];
    int tid = threadIdx.x, lane = tid & 31, wid = tid >> 5;
    int wm = wid >> 1, wn = wid & 1;
    int m0 = blockIdx.y * 128, n0 = blockIdx.x * 128;

    float acc[4][8][4];
    #pragma unroll
    for (int i = 0; i < 4; i++)
        #pragma unroll
        for (int j = 0; j < 8; j++)
            #pragma unroll
            for (int q = 0; q < 4; q++) acc[i][j][q] = 0.0f;

    const __half* A1p = jb.A1; const __half* B1p = jb.B1;

    auto issue = [&](int t) {
        uint32_t st = smb + (t % 3) * STAGE_B;
        int k0 = t * 32;
        #pragma unroll
        for (int i = 0; i < 4; i++) {
            int idx = tid + i * 128;
            int r = idx >> 2, c = idx & 3;
            uint32_t d = st + r * LDA_B + c * 16;
            size_t ga = (size_t)(m0 + r) * DMODEL + k0 + c * 8;
            size_t gb = (size_t)(n0 + r) * DMODEL + k0 + c * 8;
            CP_ASYNC16(d,          A1p + ga);
            CP_ASYNC16(d + TILE_B, B1p + gb);
        }
        CP_COMMIT();
    };
    issue(0);
    issue(1);

    for (int t = 0; t < NITER; t++) {
        if (t + 1 < NITER) { CP_WAIT(1); } else { CP_WAIT(0); }
        __syncthreads();
        if (t + 2 < NITER) issue(t + 2);

        uint32_t st = smb + (t % 3) * STAGE_B;
        uint32_t aA = st + (wm * 64 + (lane & 15)) * LDA_B + (lane >> 4) * 16;
        uint32_t aB = st + TILE_B + (wn * 64 + (lane & 7)) * LDA_B + (lane >> 3) * 16;

        uint32_t bh[8][4];
        #pragma unroll
        for (int ni = 0; ni < 8; ni++) ldsm4(bh[ni], aB + ni * 8 * LDA_B);

        #pragma unroll
        for (int ks = 0; ks < 2; ks++) {
            uint32_t ah[4][4];
            #pragma unroll
            for (int mi = 0; mi < 4; mi++)
                ldsm4(ah[mi], aA + mi * 16 * LDA_B + ks * 32);
            #pragma unroll
            for (int mi = 0; mi < 4; mi++)
                #pragma unroll
                for (int ni = 0; ni < 8; ni++)
                    mma_f16(acc[mi][ni], ah[mi], &bh[ni][2 * ks]);
        }
    }

    int er = lane >> 2, ec = (lane & 3) * 2;
    #pragma unroll
    for (int mi = 0; mi < 4; mi++) {
        #pragma unroll
        for (int ni = 0; ni < 8; ni++) {
            int row = m0 + wm * 64 + mi * 16 + er;
            int col = n0 + wn * 64 + ni * 8 + ec;
            float b0 = jb.bias[col], b1 = jb.bias[col + 1];
            float x00 = acc[mi][ni][0] + b0, x01 = acc[mi][ni][1] + b1;
            float x10 = acc[mi][ni][2] + b0, x11 = acc[mi][ni][3] + b1;
            if (jb.mode == 0) {
                *(float2*)(jb.Yf + (size_t)row * DMODEL + col) = float2{x00, x01};
                *(float2*)(jb.Yf + (size_t)(row + 8) * DMODEL + col) = float2{x10, x11};
            } else {
                x00 *= jb.scale; x01 *= jb.scale; x10 *= jb.scale; x11 *= jb.scale;
                *(__half2*)(jb.H1 + (size_t)row * DMODEL + col) =
                    __half2{__float2half_rn(x00), __float2half_rn(x01)};
                *(__half2*)(jb.H1 + (size_t)(row + 8) * DMODEL + col) =
                    __half2{__float2half_rn(x10), __float2half_rn(x11)};
            }
        }
    }
}

// ---------------- fused MMA flash attention -----------------------------------
// QK^T fp16-accumulator mma; PV fp32-accum. 1-term fp16 operands throughout.
#define FSTR 72
#define MASKVAL 1.4426950409e-9f

__global__ void __launch_bounds__(128) flash_mma(
    const __half* __restrict__ qhi, const __half* __restrict__ khi,
    const __half* __restrict__ vhi, __half* __restrict__ chi)
{
    extern __shared__ __half sh[];
    const int O_QHI = 0;                      // 128 x 72
    const int O_KH[2] = {9216, 13824};
    const int O_V[2]  = {18432, 23040};
    uint32_t sb = smem_u32(sh);

    int tid = threadIdx.x, lane = tid & 31, wm = tid >> 5;
    int q0 = blockIdx.x * 128, h = blockIdx.y, b = blockIdx.z;
    size_t rowbase = (size_t)b * SEQ;
    int r4 = lane >> 2, c2 = lane & 3;

    {
        const __half* qh = qhi + (rowbase + q0) * DMODEL + h * 64;
        #pragma unroll
        for (int c = tid; c < 1024; c += 128) {
            int r = c >> 3, dc = c & 7;
            CP_ASYNC16(sb + (O_QHI + r * FSTR + dc * 8) * 2, qh + (size_t)r * DMODEL + dc * 8);
        }
        CP_COMMIT();
    }
    const __half* kbh = khi + rowbase * DMODEL + h * 64;
    const __half* vb  = vhi + rowbase * DMODEL + h * 64;

    auto issue_kv = [&](int t) {
        int st = t & 1;
        int k0 = t * 64;
        #pragma unroll
        for (int c = tid; c < 512; c += 128) {
            int r = c >> 3, dc = c & 7;
            size_t g = (size_t)(k0 + r) * DMODEL + dc * 8;
            CP_ASYNC16(sb + (O_KH[st] + r * FSTR + dc * 8) * 2, kbh + g);
            CP_ASYNC16(sb + (O_V[st]  + r * FSTR + dc * 8) * 2, vb + g);
        }
        CP_COMMIT();
    };
    issue_kv(0);
    issue_kv(1);

    float O[2][8][4];
    #pragma unroll
    for (int mi = 0; mi < 2; mi++)
        #pragma unroll
        for (int ni = 0; ni < 8; ni++)
            #pragma unroll
            for (int q = 0; q < 4; q++) O[mi][ni][q] = 0.0f;
    float lsum[4] = {0.f, 0.f, 0.f, 0.f};
    float mrow[4] = {-1e30f, -1e30f, -1e30f, -1e30f};

    for (int t = 0; t < SEQ / 64; t++) {
        if (t < SEQ / 64 - 2) { CP_WAIT(1); } else { CP_WAIT(0); }
        __syncthreads();
        int st = t & 1;

        uint2 mw[2][2];
        #pragma unroll
        for (int mi = 0; mi < 2; mi++)
            #pragma unroll
            for (int rr = 0; rr < 2; rr++) {
                int grow = q0 + wm * 32 + mi * 16 + r4 + rr * 8;
                mw[mi][rr] = __ldg((const uint2*)&g_mbits[(size_t)grow * MWORDS + 2 * t]);
            }

        // ---- QK^T with fp16 accumulators ----
        uint32_t Sh[2][8][2];
        #pragma unroll
        for (int mi = 0; mi < 2; mi++)
            #pragma unroll
            for (int ni = 0; ni < 8; ni++) { Sh[mi][ni][0] = 0u; Sh[mi][ni][1] = 0u; }

        #pragma unroll
        for (int ks = 0; ks < 4; ks++) {
            uint32_t aH[2][4];
            #pragma unroll
            for (int mi = 0; mi < 2; mi++) {
                uint32_t abase = sb + (((wm * 32 + mi * 16 + (lane & 15)) * FSTR) +
                                       (lane >> 4) * 8 + ks * 16) * 2;
                ldsm4(aH[mi], abase);
            }
            uint32_t bH[8][2];
            #pragma unroll
            for (int np = 0; np < 4; np++) {
                // ldsm4 covering two n8 blocks: lanes 0-7 mat0(rows,k0), 8-15 mat1(rows,k8),
                // 16-23 mat2(rows+8,k0), 24-31 mat3(rows+8,k8)
                uint32_t r4v[4];
                uint32_t boff = ((np * 16 + (lane & 7) + ((lane >> 4) & 1) * 8) * FSTR +
                                 ks * 16 + ((lane >> 3) & 1) * 8) * 2;
                ldsm4(r4v, sb + O_KH[st] * 2 + boff);
                bH[2 * np][0] = r4v[0];     bH[2 * np][1] = r4v[1];
                bH[2 * np + 1][0] = r4v[2]; bH[2 * np + 1][1] = r4v[3];
            }
            #pragma unroll
            for (int mi = 0; mi < 2; mi++)
                #pragma unroll
                for (int ni = 0; ni < 8; ni++)
                    mma_f16h(Sh[mi][ni], aH[mi], bH[ni]);
        }

        // unpack to fp32 scores
        float S[2][8][4];
        #pragma unroll
        for (int mi = 0; mi < 2; mi++)
            #pragma unroll
            for (int ni = 0; ni < 8; ni++) {
                float2 f01 = __half22float2(*(__half2*)&Sh[mi][ni][0]);
                float2 f23 = __half22float2(*(__half2*)&Sh[mi][ni][1]);
                S[mi][ni][0] = f01.x; S[mi][ni][1] = f01.y;
                S[mi][ni][2] = f23.x; S[mi][ni][3] = f23.y;
            }

        float mnew[4] = {mrow[0], mrow[1], mrow[2], mrow[3]};
        #pragma unroll
        for (int mi = 0; mi < 2; mi++)
            #pragma unroll
            for (int ni = 0; ni < 8; ni++) {
                uint32_t w0 = (ni < 4) ? mw[mi][0].x : mw[mi][0].y;
                uint32_t w1 = (ni < 4) ? mw[mi][1].x : mw[mi][1].y;
                int shf = (ni & 3) * 8 + 2 * c2;
                if ((w0 >> shf) & 1u)       S[mi][ni][0] = MASKVAL;
                if ((w0 >> (shf + 1)) & 1u) S[mi][ni][1] = MASKVAL;
                if ((w1 >> shf) & 1u)       S[mi][ni][2] = MASKVAL;
                if ((w1 >> (shf + 1)) & 1u) S[mi][ni][3] = MASKVAL;
                mnew[mi * 2 + 0] = fmaxf(mnew[mi * 2 + 0], fmaxf(S[mi][ni][0], S[mi][ni][1]));
                mnew[mi * 2 + 1] = fmaxf(mnew[mi * 2 + 1], fmaxf(S[mi][ni][2], S[mi][ni][3]));
            }
        #pragma unroll
        for (int j = 0; j < 4; j++) {
            mnew[j] = fmaxf(mnew[j], __shfl_xor_sync(0xffffffffu, mnew[j], 1));
            mnew[j] = fmaxf(mnew[j], __shfl_xor_sync(0xffffffffu, mnew[j], 2));
        }
        float al[4];
        #pragma unroll
        for (int j = 0; j < 4; j++) {
            al[j] = ex2f(mrow[j] - mnew[j]);
            mrow[j] = mnew[j];
            lsum[j] *= al[j];
        }
        #pragma unroll
        for (int mi = 0; mi < 2; mi++)
            #pragma unroll
            for (int ni = 0; ni < 8; ni++) {
                O[mi][ni][0] *= al[mi * 2];     O[mi][ni][1] *= al[mi * 2];
                O[mi][ni][2] *= al[mi * 2 + 1]; O[mi][ni][3] *= al[mi * 2 + 1];
            }

        uint32_t pa[2][4][4];
        #pragma unroll
        for (int mi = 0; mi < 2; mi++)
            #pragma unroll
            for (int ni = 0; ni < 8; ni++) {
                float p0 = ex2f(S[mi][ni][0] - mnew[mi * 2]);
                float p1 = ex2f(S[mi][ni][1] - mnew[mi * 2]);
                float p2 = ex2f(S[mi][ni][2] - mnew[mi * 2 + 1]);
                float p3 = ex2f(S[mi][ni][3] - mnew[mi * 2 + 1]);
                lsum[mi * 2]     += p0 + p1;
                lsum[mi * 2 + 1] += p2 + p3;
                int ks = ni >> 1, half = ni & 1;
                pa[mi][ks][half * 2 + 0] = packh2(p0, p1);
                pa[mi][ks][half * 2 + 1] = packh2(p2, p3);
            }

        #pragma unroll
        for (int ks = 0; ks < 4; ks++) {
            #pragma unroll
            for (int nn = 0; nn < 4; nn++) {
                uint32_t vb4[4];
                int key = ks * 16 + (lane & 7) + ((lane >> 3) & 1) * 8;
                int dim = nn * 16 + ((lane >> 4) & 1) * 8;
                ldsm4t(vb4, sb + (O_V[st] + key * FSTR + dim) * 2);
                mma_f16(O[0][2 * nn],     pa[0][ks], &vb4[0]);
                mma_f16(O[0][2 * nn + 1], pa[0][ks], &vb4[2]);
                mma_f16(O[1][2 * nn],     pa[1][ks], &vb4[0]);
                mma_f16(O[1][2 * nn + 1], pa[1][ks], &vb4[2]);
            }
        }
        __syncthreads();
        if (t + 2 < SEQ / 64) issue_kv(t + 2);
    }

    #pragma unroll
    for (int j = 0; j < 4; j++) {
        lsum[j] += __shfl_xor_sync(0xffffffffu, lsum[j], 1);
        lsum[j] += __shfl_xor_sync(0xffffffffu, lsum[j], 2);
        lsum[j] = 1.0f / lsum[j];
    }
    #pragma unroll
    for (int mi = 0; mi < 2; mi++)
        #pragma unroll
        for (int ni = 0; ni < 8; ni++) {
            size_t grow = rowbase + q0 + wm * 32 + mi * 16 + r4;
            int col = h * 64 + ni * 8 + 2 * c2;
            float x00 = O[mi][ni][0] * lsum[mi * 2];
            float x01 = O[mi][ni][1] * lsum[mi * 2];
            float x10 = O[mi][ni][2] * lsum[mi * 2 + 1];
            float x11 = O[mi][ni][3] * lsum[mi * 2 + 1];
            *(__half2*)(chi + grow * DMODEL + col) =
                __half2{__float2half_rn(x00), __float2half_rn(x01)};
            *(__half2*)(chi + (grow + 8) * DMODEL + col) =
                __half2{__float2half_rn(x10), __float2half_rn(x11)};
        }
}

// ---------------- launch ------------------------------------------------------
extern "C" void kernel_launch(void* const* d_in, const int* in_sizes, int n_in,
                              void* d_out, int out_size)
{
    const float* q    = (const float*)d_in[0];
    const float* k    = (const float*)d_in[1];
    const float* v    = (const float*)d_in[2];
    const void*  mask = d_in[3];
    const float* Wq   = (const float*)d_in[4];
    const float* bq   = (const float*)d_in[5];
    const float* Wk   = (const float*)d_in[6];
    const float* bk   = (const float*)d_in[7];
    const float* Wv   = (const float*)d_in[8];
    const float* bv   = (const float*)d_in[9];
    const float* Wo   = (const float*)d_in[10];
    const float* bo   = (const float*)d_in[11];

    __half *qsh, *ksh, *vsh, *qhi, *khi, *vhi, *chi, *w16;
    cudaGetSymbolAddress((void**)&qsh, g_qsh);
    cudaGetSymbolAddress((void**)&ksh, g_ksh);
    cudaGetSymbolAddress((void**)&vsh, g_vsh);
    cudaGetSymbolAddress((void**)&qhi, g_qhi);
    cudaGetSymbolAddress((void**)&khi, g_khi);
    cudaGetSymbolAddress((void**)&vhi, g_vhi);
    cudaGetSymbolAddress((void**)&chi, g_chi);
    cudaGetSymbolAddress((void**)&w16, g_w16);

    const int gemm_smem = 3 * STAGE_B;    // 61440
    const int flash_smem = 27648 * 2;     // 55296
    static bool attr_set = false;
    if (!attr_set) {
        cudaFuncSetAttribute(gemm_mma, cudaFuncAttributeMaxDynamicSharedMemorySize, gemm_smem);
        cudaFuncSetAttribute(flash_mma, cudaFuncAttributeMaxDynamicSharedMemorySize, flash_smem);
        attr_set = true;
    }

    const float qscale = 0.125f * LOG2E;

    detect_mask<<<1, 256>>>((const unsigned*)mask);
    pack_mask<<<(SEQ * MWORDS) / 256, 256>>>(mask);

    conv_all<<<dim3(NACT8 / 256, 7), 256>>>(
        (const float4*)q, (const float4*)k, (const float4*)v,
        (const float4*)Wq, (const float4*)Wk, (const float4*)Wv, (const float4*)Wo,
        qsh, ksh, vsh, w16);

    Jobs3 pj;
    pj.j[0] = Job{qsh, w16,                     bq, nullptr, qhi, 2, qscale};
    pj.j[1] = Job{ksh, w16 + 1 * DMODEL*DMODEL, bk, nullptr, khi, 2, 1.0f};
    pj.j[2] = Job{vsh, w16 + 2 * DMODEL*DMODEL, bv, nullptr, vhi, 2, 1.0f};
    gemm_mma<<<dim3(8, 64, 3), 128, gemm_smem>>>(pj);

    flash_mma<<<dim3(SEQ / 128, NHEAD, NBATCH), 128, flash_smem>>>(qhi, khi, vhi, chi);

    Jobs3 oj;
    oj.j[0] = Job{chi, w16 + 3 * DMODEL*DMODEL, bo, (float*)d_out, nullptr, 0, 1.0f};
    oj.j[1] = oj.j[0];
    oj.j[2] = oj.j[0];
    gemm_mma<<<dim3(8, 64, 1), 128, gemm_smem>>>(oj);
}

// round 10
// speedup vs baseline: 7.7541x; 1.0214x over previous
#include <cuda_runtime.h>
#include <cuda_fp16.h>
#include <cstdint>

#define SEQ    2048
#define DMODEL 1024
#define NHEAD  16
#define DVDIM  64
#define NBATCH 4
#define MROWS  (NBATCH * SEQ)   // 8192
#define MWORDS (SEQ / 32)
#define LOG2E  1.4426950408889634f

// ---------------- scratch (device globals) ----------------------------------
__device__ __align__(16) __half g_qsh[MROWS * DMODEL];
__device__ __align__(16) __half g_ksh[MROWS * DMODEL];
__device__ __align__(16) __half g_vsh[MROWS * DMODEL];
__device__ __align__(16) __half g_qhi[MROWS * DMODEL];
__device__ __align__(16) __half g_khi[MROWS * DMODEL];
__device__ __align__(16) __half g_vhi[MROWS * DMODEL];
__device__ __align__(16) __half g_chi[MROWS * DMODEL];
__device__ __align__(16) __half g_w16[4 * DMODEL * DMODEL];
__device__ unsigned g_mbits[SEQ * MWORDS];
__device__ int g_mode;

// ---------------- PTX helpers (sm_103-safe) ---------------------------------
__device__ __forceinline__ uint32_t smem_u32(const void* p) {
    uint32_t a;
    asm("{ .reg .u64 t; cvta.to.shared.u64 t, %1; cvt.u32.u64 %0, t; }" : "=r"(a) : "l"(p));
    return a;
}
#define CP_ASYNC16(dst, src) \
    asm volatile("cp.async.ca.shared.global [%0], [%1], 16;" :: "r"(dst), "l"(src))
#define CP_COMMIT() asm volatile("cp.async.commit_group;" ::: "memory")
#define CP_WAIT(n)  asm volatile("cp.async.wait_group %0;" :: "n"(n) : "memory")

__device__ __forceinline__ void ldsm4(uint32_t* r, uint32_t addr) {
    asm volatile("ldmatrix.sync.aligned.m8n8.x4.shared.b16 {%0,%1,%2,%3}, [%4];"
                 : "=r"(r[0]), "=r"(r[1]), "=r"(r[2]), "=r"(r[3]) : "r"(addr));
}
__device__ __forceinline__ void ldsm4t(uint32_t* r, uint32_t addr) {
    asm volatile("ldmatrix.sync.aligned.m8n8.x4.trans.shared.b16 {%0,%1,%2,%3}, [%4];"
                 : "=r"(r[0]), "=r"(r[1]), "=r"(r[2]), "=r"(r[3]) : "r"(addr));
}
__device__ __forceinline__ void mma_f16(float* d, const uint32_t* a, const uint32_t* b) {
    asm volatile(
        "mma.sync.aligned.m16n8k16.row.col.f32.f16.f16.f32 "
        "{%0,%1,%2,%3}, {%4,%5,%6,%7}, {%8,%9}, {%0,%1,%2,%3};"
        : "+f"(d[0]), "+f"(d[1]), "+f"(d[2]), "+f"(d[3])
        : "r"(a[0]), "r"(a[1]), "r"(a[2]), "r"(a[3]), "r"(b[0]), "r"(b[1]));
}
__device__ __forceinline__ float ex2f(float x) {
    float r; asm("ex2.approx.f32 %0, %1;" : "=f"(r) : "f"(x)); return r;
}
__device__ __forceinline__ uint32_t packh2(float lo, float hi) {
    uint32_t d; asm("cvt.rn.f16x2.f32 %0, %1, %2;" : "=r"(d) : "f"(hi), "f"(lo)); return d;
}

// ---------------- mask handling ----------------------------------------------
__global__ void detect_mask(const unsigned* __restrict__ m) {
    __shared__ int f[4];
    int t = threadIdx.x;
    if (t < 4) f[t] = 0;
    __syncthreads();
    int fu8 = 0, ff16 = 0, fbf16 = 0, ff32 = 0;
    for (int i = t; i < 4096; i += 256) {
        unsigned w = m[i];
        if (w == 0x3F800000u) ff32 = 1;
        if (w == 0x3F803F80u || w == 0x00003F80u) fbf16 = 1;
        if (w == 0x3C003C00u || w == 0x00003C00u || w == 0x3C000000u) ff16 = 1;
        if ((w & 0xFEFEFEFEu) == 0u && w > 1u) fu8 = 1;
    }
    if (fu8)  atomicOr(&f[0], 1);
    if (ff16) atomicOr(&f[1], 1);
    if (fbf16) atomicOr(&f[2], 1);
    if (ff32) atomicOr(&f[3], 1);
    __syncthreads();
    if (t == 0) {
        int mode;
        if (f[1]) mode = 4;
        else if (f[2]) mode = 3;
        else if (f[3]) mode = 2;
        else if (f[0]) mode = 1;
        else mode = 0;
        g_mode = mode;
    }
}

__global__ void pack_mask(const void* __restrict__ mp) {
    int idx = blockIdx.x * blockDim.x + threadIdx.x;
    int mode = g_mode;
    long base = (long)idx * 32;
    unsigned bits = 0;
    if (mode == 0) {
        const int* p = (const int*)mp;
        #pragma unroll 8
        for (int j = 0; j < 32; j++) if (p[base + j] != 0) bits |= 1u << j;
    } else if (mode == 1) {
        const unsigned char* p = (const unsigned char*)mp;
        #pragma unroll 8
        for (int j = 0; j < 32; j++) if (p[base + j] != 0) bits |= 1u << j;
    } else if (mode == 2) {
        const float* p = (const float*)mp;
        #pragma unroll 8
        for (int j = 0; j < 32; j++) if (p[base + j] != 0.0f) bits |= 1u << j;
    } else {
        const unsigned short* p = (const unsigned short*)mp;
        #pragma unroll 8
        for (int j = 0; j < 32; j++) if (p[base + j] != 0) bits |= 1u << j;
    }
    g_mbits[idx] = bits;
}

// ---------------- prep: fused fp32 -> fp16 conversion (7 jobs) ---------------
#define NACT8 (MROWS * DMODEL / 8)   // 1048576
#define NW8   (DMODEL * DMODEL / 8)  // 131072

__global__ void conv_all(const float4* __restrict__ q, const float4* __restrict__ k,
                         const float4* __restrict__ v,
                         const float4* __restrict__ wq, const float4* __restrict__ wk,
                         const float4* __restrict__ wv, const float4* __restrict__ wo,
                         __half* __restrict__ qh, __half* __restrict__ kh,
                         __half* __restrict__ vh, __half* __restrict__ w16)
{
    int z = blockIdx.y;
    int i = blockIdx.x * blockDim.x + threadIdx.x;
    const float4* src;
    __half* dst;
    if (z < 3) {
        src = (z == 0) ? q : (z == 1) ? k : v;
        dst = (z == 0) ? qh : (z == 1) ? kh : vh;
        if (i >= NACT8) return;
    } else {
        int w = z - 3;
        src = (w == 0) ? wq : (w == 1) ? wk : (w == 2) ? wv : wo;
        dst = w16 + (size_t)w * DMODEL * DMODEL;
        if (i >= NW8) return;
    }
    float4 a = src[2 * i], b = src[2 * i + 1];
    uint4 o;
    o.x = packh2(a.x, a.y); o.y = packh2(a.z, a.w);
    o.z = packh2(b.x, b.y); o.w = packh2(b.z, b.w);
    *((uint4*)dst + i) = o;
}

// ---------------- mma.sync fp16 GEMM (unchanged: at HMMA floor) --------------
#define LDA_B   80
#define TILE_B  10240
#define STAGE_B 20480
#define NITER   (DMODEL / 32)

struct Job {
    const __half* A1; const __half* B1;
    const float* bias;
    float* Yf; __half* H1;
    int mode; float scale;
};
struct Jobs3 { Job j[3]; };

__global__ void __launch_bounds__(128) gemm_mma(Jobs3 jobs)
{
    extern __shared__ char sm[];
    uint32_t smb = smem_u32(sm);
    Job jb = jobs.j[blockIdx.z];
    int tid = threadIdx.x, lane = tid & 31, wid = tid >> 5;
    int wm = wid >> 1, wn = wid & 1;
    int m0 = blockIdx.y * 128, n0 = blockIdx.x * 128;

    float acc[4][8][4];
    #pragma unroll
    for (int i = 0; i < 4; i++)
        #pragma unroll
        for (int j = 0; j < 8; j++)
            #pragma unroll
            for (int q = 0; q < 4; q++) acc[i][j][q] = 0.0f;

    const __half* A1p = jb.A1; const __half* B1p = jb.B1;

    auto issue = [&](int t) {
        uint32_t st = smb + (t % 3) * STAGE_B;
        int k0 = t * 32;
        #pragma unroll
        for (int i = 0; i < 4; i++) {
            int idx = tid + i * 128;
            int r = idx >> 2, c = idx & 3;
            uint32_t d = st + r * LDA_B + c * 16;
            size_t ga = (size_t)(m0 + r) * DMODEL + k0 + c * 8;
            size_t gb = (size_t)(n0 + r) * DMODEL + k0 + c * 8;
            CP_ASYNC16(d,          A1p + ga);
            CP_ASYNC16(d + TILE_B, B1p + gb);
        }
        CP_COMMIT();
    };
    issue(0);
    issue(1);

    for (int t = 0; t < NITER; t++) {
        if (t + 1 < NITER) { CP_WAIT(1); } else { CP_WAIT(0); }
        __syncthreads();
        if (t + 2 < NITER) issue(t + 2);

        uint32_t st = smb + (t % 3) * STAGE_B;
        uint32_t aA = st + (wm * 64 + (lane & 15)) * LDA_B + (lane >> 4) * 16;
        uint32_t aB = st + TILE_B + (wn * 64 + (lane & 7)) * LDA_B + (lane >> 3) * 16;

        uint32_t bh[8][4];
        #pragma unroll
        for (int ni = 0; ni < 8; ni++) ldsm4(bh[ni], aB + ni * 8 * LDA_B);

        #pragma unroll
        for (int ks = 0; ks < 2; ks++) {
            uint32_t ah[4][4];
            #pragma unroll
            for (int mi = 0; mi < 4; mi++)
                ldsm4(ah[mi], aA + mi * 16 * LDA_B + ks * 32);
            #pragma unroll
            for (int mi = 0; mi < 4; mi++)
                #pragma unroll
                for (int ni = 0; ni < 8; ni++)
                    mma_f16(acc[mi][ni], ah[mi], &bh[ni][2 * ks]);
        }
    }

    int er = lane >> 2, ec = (lane & 3) * 2;
    #pragma unroll
    for (int mi = 0; mi < 4; mi++) {
        #pragma unroll
        for (int ni = 0; ni < 8; ni++) {
            int row = m0 + wm * 64 + mi * 16 + er;
            int col = n0 + wn * 64 + ni * 8 + ec;
            float b0 = jb.bias[col], b1 = jb.bias[col + 1];
            float x00 = acc[mi][ni][0] + b0, x01 = acc[mi][ni][1] + b1;
            float x10 = acc[mi][ni][2] + b0, x11 = acc[mi][ni][3] + b1;
            if (jb.mode == 0) {
                *(float2*)(jb.Yf + (size_t)row * DMODEL + col) = float2{x00, x01};
                *(float2*)(jb.Yf + (size_t)(row + 8) * DMODEL + col) = float2{x10, x11};
            } else {
                x00 *= jb.scale; x01 *= jb.scale; x10 *= jb.scale; x11 *= jb.scale;
                *(__half2*)(jb.H1 + (size_t)row * DMODEL + col) =
                    __half2{__float2half_rn(x00), __float2half_rn(x01)};
                *(__half2*)(jb.H1 + (size_t)(row + 8) * DMODEL + col) =
                    __half2{__float2half_rn(x10), __float2half_rn(x11)};
            }
        }
    }
}

// ---------------- fused MMA flash attention -----------------------------------
// f32-accum QK (reverted). 256 threads, 8 warps x 16 q-rows, 2 CTAs/SM target.
#define FSTR 72
#define MASKVAL 1.4426950409e-9f

__global__ void __launch_bounds__(256, 2) flash_mma(
    const __half* __restrict__ qhi, const __half* __restrict__ khi,
    const __half* __restrict__ vhi, __half* __restrict__ chi)
{
    extern __shared__ __half sh[];
    const int O_QHI = 0;                      // 128 x 72
    const int O_KH[2] = {9216, 13824};
    const int O_V[2]  = {18432, 23040};
    uint32_t sb = smem_u32(sh);

    int tid = threadIdx.x, lane = tid & 31, wm = tid >> 5;   // 8 warps
    int q0 = blockIdx.x * 128, h = blockIdx.y, b = blockIdx.z;
    size_t rowbase = (size_t)b * SEQ;
    int r4 = lane >> 2, c2 = lane & 3;

    {
        const __half* qh = qhi + (rowbase + q0) * DMODEL + h * 64;
        #pragma unroll
        for (int c = tid; c < 1024; c += 256) {
            int r = c >> 3, dc = c & 7;
            CP_ASYNC16(sb + (O_QHI + r * FSTR + dc * 8) * 2, qh + (size_t)r * DMODEL + dc * 8);
        }
        CP_COMMIT();
    }
    const __half* kbh = khi + rowbase * DMODEL + h * 64;
    const __half* vb  = vhi + rowbase * DMODEL + h * 64;

    auto issue_kv = [&](int t) {
        int st = t & 1;
        int k0 = t * 64;
        #pragma unroll
        for (int c = tid; c < 512; c += 256) {
            int r = c >> 3, dc = c & 7;
            size_t g = (size_t)(k0 + r) * DMODEL + dc * 8;
            CP_ASYNC16(sb + (O_KH[st] + r * FSTR + dc * 8) * 2, kbh + g);
            CP_ASYNC16(sb + (O_V[st]  + r * FSTR + dc * 8) * 2, vb + g);
        }
        CP_COMMIT();
    };
    issue_kv(0);
    issue_kv(1);

    float O[8][4];
    #pragma unroll
    for (int ni = 0; ni < 8; ni++)
        #pragma unroll
        for (int q = 0; q < 4; q++) O[ni][q] = 0.0f;
    float lsum[2] = {0.f, 0.f};
    float mrow[2] = {-1e30f, -1e30f};

    for (int t = 0; t < SEQ / 64; t++) {
        if (t < SEQ / 64 - 2) { CP_WAIT(1); } else { CP_WAIT(0); }
        __syncthreads();
        int st = t & 1;

        uint2 mw[2];
        #pragma unroll
        for (int rr = 0; rr < 2; rr++) {
            int grow = q0 + wm * 16 + r4 + rr * 8;
            mw[rr] = __ldg((const uint2*)&g_mbits[(size_t)grow * MWORDS + 2 * t]);
        }

        float S[8][4];
        #pragma unroll
        for (int ni = 0; ni < 8; ni++)
            #pragma unroll
            for (int q = 0; q < 4; q++) S[ni][q] = 0.0f;

        #pragma unroll
        for (int ks = 0; ks < 4; ks++) {
            uint32_t aH[4];
            {
                uint32_t abase = sb + (((wm * 16 + (lane & 15)) * FSTR) +
                                       (lane >> 4) * 8 + ks * 16) * 2;
                ldsm4(aH, abase);
            }
            uint32_t bH[8][2];
            #pragma unroll
            for (int np = 0; np < 4; np++) {
                uint32_t r4v[4];
                uint32_t boff = ((np * 16 + (lane & 7) + ((lane >> 4) & 1) * 8) * FSTR +
                                 ks * 16 + ((lane >> 3) & 1) * 8) * 2;
                ldsm4(r4v, sb + O_KH[st] * 2 + boff);
                bH[2 * np][0] = r4v[0];     bH[2 * np][1] = r4v[1];
                bH[2 * np + 1][0] = r4v[2]; bH[2 * np + 1][1] = r4v[3];
            }
            #pragma unroll
            for (int ni = 0; ni < 8; ni++)
                mma_f16(S[ni], aH, bH[ni]);
        }

        float mnew[2] = {mrow[0], mrow[1]};
        #pragma unroll
        for (int ni = 0; ni < 8; ni++) {
            uint32_t w0 = (ni < 4) ? mw[0].x : mw[0].y;
            uint32_t w1 = (ni < 4) ? mw[1].x : mw[1].y;
            int shf = (ni & 3) * 8 + 2 * c2;
            if ((w0 >> shf) & 1u)       S[ni][0] = MASKVAL;
            if ((w0 >> (shf + 1)) & 1u) S[ni][1] = MASKVAL;
            if ((w1 >> shf) & 1u)       S[ni][2] = MASKVAL;
            if ((w1 >> (shf + 1)) & 1u) S[ni][3] = MASKVAL;
            mnew[0] = fmaxf(mnew[0], fmaxf(S[ni][0], S[ni][1]));
            mnew[1] = fmaxf(mnew[1], fmaxf(S[ni][2], S[ni][3]));
        }
        #pragma unroll
        for (int j = 0; j < 2; j++) {
            mnew[j] = fmaxf(mnew[j], __shfl_xor_sync(0xffffffffu, mnew[j], 1));
            mnew[j] = fmaxf(mnew[j], __shfl_xor_sync(0xffffffffu, mnew[j], 2));
        }
        float al[2];
        #pragma unroll
        for (int j = 0; j < 2; j++) {
            al[j] = ex2f(mrow[j] - mnew[j]);
            mrow[j] = mnew[j];
            lsum[j] *= al[j];
        }
        #pragma unroll
        for (int ni = 0; ni < 8; ni++) {
            O[ni][0] *= al[0]; O[ni][1] *= al[0];
            O[ni][2] *= al[1]; O[ni][3] *= al[1];
        }

        uint32_t pa[4][4];
        #pragma unroll
        for (int ni = 0; ni < 8; ni++) {
            float p0 = ex2f(S[ni][0] - mnew[0]);
            float p1 = ex2f(S[ni][1] - mnew[0]);
            float p2 = ex2f(S[ni][2] - mnew[1]);
            float p3 = ex2f(S[ni][3] - mnew[1]);
            lsum[0] += p0 + p1;
            lsum[1] += p2 + p3;
            int ks = ni >> 1, half = ni & 1;
            pa[ks][half * 2 + 0] = packh2(p0, p1);
            pa[ks][half * 2 + 1] = packh2(p2, p3);
        }

        #pragma unroll
        for (int ks = 0; ks < 4; ks++) {
            #pragma unroll
            for (int nn = 0; nn < 4; nn++) {
                uint32_t vb4[4];
                int key = ks * 16 + (lane & 7) + ((lane >> 3) & 1) * 8;
                int dim = nn * 16 + ((lane >> 4) & 1) * 8;
                ldsm4t(vb4, sb + (O_V[st] + key * FSTR + dim) * 2);
                mma_f16(O[2 * nn],     pa[ks], &vb4[0]);
                mma_f16(O[2 * nn + 1], pa[ks], &vb4[2]);
            }
        }
        __syncthreads();
        if (t + 2 < SEQ / 64) issue_kv(t + 2);
    }

    #pragma unroll
    for (int j = 0; j < 2; j++) {
        lsum[j] += __shfl_xor_sync(0xffffffffu, lsum[j], 1);
        lsum[j] += __shfl_xor_sync(0xffffffffu, lsum[j], 2);
        lsum[j] = 1.0f / lsum[j];
    }
    #pragma unroll
    for (int ni = 0; ni < 8; ni++) {
        size_t grow = rowbase + q0 + wm * 16 + r4;
        int col = h * 64 + ni * 8 + 2 * c2;
        float x00 = O[ni][0] * lsum[0];
        float x01 = O[ni][1] * lsum[0];
        float x10 = O[ni][2] * lsum[1];
        float x11 = O[ni][3] * lsum[1];
        *(__half2*)(chi + grow * DMODEL + col) =
            __half2{__float2half_rn(x00), __float2half_rn(x01)};
        *(__half2*)(chi + (grow + 8) * DMODEL + col) =
            __half2{__float2half_rn(x10), __float2half_rn(x11)};
    }
}

// ---------------- launch ------------------------------------------------------
extern "C" void kernel_launch(void* const* d_in, const int* in_sizes, int n_in,
                              void* d_out, int out_size)
{
    const float* q    = (const float*)d_in[0];
    const float* k    = (const float*)d_in[1];
    const float* v    = (const float*)d_in[2];
    const void*  mask = d_in[3];
    const float* Wq   = (const float*)d_in[4];
    const float* bq   = (const float*)d_in[5];
    const float* Wk   = (const float*)d_in[6];
    const float* bk   = (const float*)d_in[7];
    const float* Wv   = (const float*)d_in[8];
    const float* bv   = (const float*)d_in[9];
    const float* Wo   = (const float*)d_in[10];
    const float* bo   = (const float*)d_in[11];

    __half *qsh, *ksh, *vsh, *qhi, *khi, *vhi, *chi, *w16;
    cudaGetSymbolAddress((void**)&qsh, g_qsh);
    cudaGetSymbolAddress((void**)&ksh, g_ksh);
    cudaGetSymbolAddress((void**)&vsh, g_vsh);
    cudaGetSymbolAddress((void**)&qhi, g_qhi);
    cudaGetSymbolAddress((void**)&khi, g_khi);
    cudaGetSymbolAddress((void**)&vhi, g_vhi);
    cudaGetSymbolAddress((void**)&chi, g_chi);
    cudaGetSymbolAddress((void**)&w16, g_w16);

    const int gemm_smem = 3 * STAGE_B;    // 61440
    const int flash_smem = 27648 * 2;     // 55296
    static bool attr_set = false;
    if (!attr_set) {
        cudaFuncSetAttribute(gemm_mma, cudaFuncAttributeMaxDynamicSharedMemorySize, gemm_smem);
        cudaFuncSetAttribute(flash_mma, cudaFuncAttributeMaxDynamicSharedMemorySize, flash_smem);
        attr_set = true;
    }

    const float qscale = 0.125f * LOG2E;

    detect_mask<<<1, 256>>>((const unsigned*)mask);
    pack_mask<<<(SEQ * MWORDS) / 256, 256>>>(mask);

    conv_all<<<dim3(NACT8 / 256, 7), 256>>>(
        (const float4*)q, (const float4*)k, (const float4*)v,
        (const float4*)Wq, (const float4*)Wk, (const float4*)Wv, (const float4*)Wo,
        qsh, ksh, vsh, w16);

    Jobs3 pj;
    pj.j[0] = Job{qsh, w16,                     bq, nullptr, qhi, 2, qscale};
    pj.j[1] = Job{ksh, w16 + 1 * DMODEL*DMODEL, bk, nullptr, khi, 2, 1.0f};
    pj.j[2] = Job{vsh, w16 + 2 * DMODEL*DMODEL, bv, nullptr, vhi, 2, 1.0f};
    gemm_mma<<<dim3(8, 64, 3), 128, gemm_smem>>>(pj);

    flash_mma<<<dim3(SEQ / 128, NHEAD, NBATCH), 256, flash_smem>>>(qhi, khi, vhi, chi);

    Jobs3 oj;
    oj.j[0] = Job{chi, w16 + 3 * DMODEL*DMODEL, bo, (float*)d_out, nullptr, 0, 1.0f};
    oj.j[1] = oj.j[0];
    oj.j[2] = oj.j[0];
    gemm_mma<<<dim3(8, 64, 1), 128, gemm_smem>>>(oj);
}

// round 11
// speedup vs baseline: 8.0803x; 1.0421x over previous
#include <cuda_runtime.h>
#include <cuda_fp16.h>
#include <cstdint>

#define SEQ    2048
#define DMODEL 1024
#define NHEAD  16
#define DVDIM  64
#define NBATCH 4
#define MROWS  (NBATCH * SEQ)   // 8192
#define MWORDS (SEQ / 32)
#define LOG2E  1.4426950408889634f

// ---------------- scratch (device globals) ----------------------------------
__device__ __align__(16) __half g_qsh[MROWS * DMODEL];
__device__ __align__(16) __half g_ksh[MROWS * DMODEL];
__device__ __align__(16) __half g_vsh[MROWS * DMODEL];
__device__ __align__(16) __half g_qhi[MROWS * DMODEL];
__device__ __align__(16) __half g_khi[MROWS * DMODEL];
__device__ __align__(16) __half g_vhi[MROWS * DMODEL];
__device__ __align__(16) __half g_chi[MROWS * DMODEL];
__device__ __align__(16) __half g_w16[4 * DMODEL * DMODEL];
__device__ unsigned g_mbits[SEQ * MWORDS];
__device__ int g_mode;

// ---------------- PTX helpers (sm_103-safe) ---------------------------------
__device__ __forceinline__ uint32_t smem_u32(const void* p) {
    uint32_t a;
    asm("{ .reg .u64 t; cvta.to.shared.u64 t, %1; cvt.u32.u64 %0, t; }" : "=r"(a) : "l"(p));
    return a;
}
#define CP_ASYNC16(dst, src) \
    asm volatile("cp.async.ca.shared.global [%0], [%1], 16;" :: "r"(dst), "l"(src))
#define CP_COMMIT() asm volatile("cp.async.commit_group;" ::: "memory")
#define CP_WAIT(n)  asm volatile("cp.async.wait_group %0;" :: "n"(n) : "memory")

__device__ __forceinline__ void ldsm4(uint32_t* r, uint32_t addr) {
    asm volatile("ldmatrix.sync.aligned.m8n8.x4.shared.b16 {%0,%1,%2,%3}, [%4];"
                 : "=r"(r[0]), "=r"(r[1]), "=r"(r[2]), "=r"(r[3]) : "r"(addr));
}
__device__ __forceinline__ void ldsm4t(uint32_t* r, uint32_t addr) {
    asm volatile("ldmatrix.sync.aligned.m8n8.x4.trans.shared.b16 {%0,%1,%2,%3}, [%4];"
                 : "=r"(r[0]), "=r"(r[1]), "=r"(r[2]), "=r"(r[3]) : "r"(addr));
}
__device__ __forceinline__ void mma_f16(float* d, const uint32_t* a, const uint32_t* b) {
    asm volatile(
        "mma.sync.aligned.m16n8k16.row.col.f32.f16.f16.f32 "
        "{%0,%1,%2,%3}, {%4,%5,%6,%7}, {%8,%9}, {%0,%1,%2,%3};"
        : "+f"(d[0]), "+f"(d[1]), "+f"(d[2]), "+f"(d[3])
        : "r"(a[0]), "r"(a[1]), "r"(a[2]), "r"(a[3]), "r"(b[0]), "r"(b[1]));
}
__device__ __forceinline__ float ex2f(float x) {
    float r; asm("ex2.approx.f32 %0, %1;" : "=f"(r) : "f"(x)); return r;
}
__device__ __forceinline__ uint32_t packh2(float lo, float hi) {
    uint32_t d; asm("cvt.rn.f16x2.f32 %0, %1, %2;" : "=r"(d) : "f"(hi), "f"(lo)); return d;
}

// ---------------- mask handling ----------------------------------------------
__global__ void detect_mask(const unsigned* __restrict__ m) {
    __shared__ int f[4];
    int t = threadIdx.x;
    if (t < 4) f[t] = 0;
    __syncthreads();
    int fu8 = 0, ff16 = 0, fbf16 = 0, ff32 = 0;
    for (int i = t; i < 4096; i += 256) {
        unsigned w = m[i];
        if (w == 0x3F800000u) ff32 = 1;
        if (w == 0x3F803F80u || w == 0x00003F80u) fbf16 = 1;
        if (w == 0x3C003C00u || w == 0x00003C00u || w == 0x3C000000u) ff16 = 1;
        if ((w & 0xFEFEFEFEu) == 0u && w > 1u) fu8 = 1;
    }
    if (fu8)  atomicOr(&f[0], 1);
    if (ff16) atomicOr(&f[1], 1);
    if (fbf16) atomicOr(&f[2], 1);
    if (ff32) atomicOr(&f[3], 1);
    __syncthreads();
    if (t == 0) {
        int mode;
        if (f[1]) mode = 4;
        else if (f[2]) mode = 3;
        else if (f[3]) mode = 2;
        else if (f[0]) mode = 1;
        else mode = 0;
        g_mode = mode;
    }
}

__global__ void pack_mask(const void* __restrict__ mp) {
    int idx = blockIdx.x * blockDim.x + threadIdx.x;
    int mode = g_mode;
    long base = (long)idx * 32;
    unsigned bits = 0;
    if (mode == 0) {
        const int* p = (const int*)mp;
        #pragma unroll 8
        for (int j = 0; j < 32; j++) if (p[base + j] != 0) bits |= 1u << j;
    } else if (mode == 1) {
        const unsigned char* p = (const unsigned char*)mp;
        #pragma unroll 8
        for (int j = 0; j < 32; j++) if (p[base + j] != 0) bits |= 1u << j;
    } else if (mode == 2) {
        const float* p = (const float*)mp;
        #pragma unroll 8
        for (int j = 0; j < 32; j++) if (p[base + j] != 0.0f) bits |= 1u << j;
    } else {
        const unsigned short* p = (const unsigned short*)mp;
        #pragma unroll 8
        for (int j = 0; j < 32; j++) if (p[base + j] != 0) bits |= 1u << j;
    }
    g_mbits[idx] = bits;
}

// ---------------- prep: fused fp32 -> fp16 conversion (7 jobs) ---------------
#define NACT8 (MROWS * DMODEL / 8)   // 1048576
#define NW8   (DMODEL * DMODEL / 8)  // 131072

__global__ void conv_all(const float4* __restrict__ q, const float4* __restrict__ k,
                         const float4* __restrict__ v,
                         const float4* __restrict__ wq, const float4* __restrict__ wk,
                         const float4* __restrict__ wv, const float4* __restrict__ wo,
                         __half* __restrict__ qh, __half* __restrict__ kh,
                         __half* __restrict__ vh, __half* __restrict__ w16)
{
    int z = blockIdx.y;
    int i = blockIdx.x * blockDim.x + threadIdx.x;
    const float4* src;
    __half* dst;
    if (z < 3) {
        src = (z == 0) ? q : (z == 1) ? k : v;
        dst = (z == 0) ? qh : (z == 1) ? kh : vh;
        if (i >= NACT8) return;
    } else {
        int w = z - 3;
        src = (w == 0) ? wq : (w == 1) ? wk : (w == 2) ? wv : wo;
        dst = w16 + (size_t)w * DMODEL * DMODEL;
        if (i >= NW8) return;
    }
    float4 a = src[2 * i], b = src[2 * i + 1];
    uint4 o;
    o.x = packh2(a.x, a.y); o.y = packh2(a.z, a.w);
    o.z = packh2(b.x, b.y); o.w = packh2(b.z, b.w);
    *((uint4*)dst + i) = o;
}

// ---------------- mma.sync fp16 GEMM (unchanged: at HMMA floor) --------------
#define LDA_B   80
#define TILE_B  10240
#define STAGE_B 20480
#define NITER   (DMODEL / 32)

struct Job {
    const __half* A1; const __half* B1;
    const float* bias;
    float* Yf; __half* H1;
    int mode; float scale;
};
struct Jobs3 { Job j[3]; };

__global__ void __launch_bounds__(128) gemm_mma(Jobs3 jobs)
{
    extern __shared__ char sm[];
    uint32_t smb = smem_u32(sm);
    Job jb = jobs.j[blockIdx.z];
    int tid = threadIdx.x, lane = tid & 31, wid = tid >> 5;
    int wm = wid >> 1, wn = wid & 1;
    int m0 = blockIdx.y * 128, n0 = blockIdx.x * 128;

    float acc[4][8][4];
    #pragma unroll
    for (int i = 0; i < 4; i++)
        #pragma unroll
        for (int j = 0; j < 8; j++)
            #pragma unroll
            for (int q = 0; q < 4; q++) acc[i][j][q] = 0.0f;

    const __half* A1p = jb.A1; const __half* B1p = jb.B1;

    auto issue = [&](int t) {
        uint32_t st = smb + (t % 3) * STAGE_B;
        int k0 = t * 32;
        #pragma unroll
        for (int i = 0; i < 4; i++) {
            int idx = tid + i * 128;
            int r = idx >> 2, c = idx & 3;
            uint32_t d = st + r * LDA_B + c * 16;
            size_t ga = (size_t)(m0 + r) * DMODEL + k0 + c * 8;
            size_t gb = (size_t)(n0 + r) * DMODEL + k0 + c * 8;
            CP_ASYNC16(d,          A1p + ga);
            CP_ASYNC16(d + TILE_B, B1p + gb);
        }
        CP_COMMIT();
    };
    issue(0);
    issue(1);

    for (int t = 0; t < NITER; t++) {
        if (t + 1 < NITER) { CP_WAIT(1); } else { CP_WAIT(0); }
        __syncthreads();
        if (t + 2 < NITER) issue(t + 2);

        uint32_t st = smb + (t % 3) * STAGE_B;
        uint32_t aA = st + (wm * 64 + (lane & 15)) * LDA_B + (lane >> 4) * 16;
        uint32_t aB = st + TILE_B + (wn * 64 + (lane & 7)) * LDA_B + (lane >> 3) * 16;

        uint32_t bh[8][4];
        #pragma unroll
        for (int ni = 0; ni < 8; ni++) ldsm4(bh[ni], aB + ni * 8 * LDA_B);

        #pragma unroll
        for (int ks = 0; ks < 2; ks++) {
            uint32_t ah[4][4];
            #pragma unroll
            for (int mi = 0; mi < 4; mi++)
                ldsm4(ah[mi], aA + mi * 16 * LDA_B + ks * 32);
            #pragma unroll
            for (int mi = 0; mi < 4; mi++)
                #pragma unroll
                for (int ni = 0; ni < 8; ni++)
                    mma_f16(acc[mi][ni], ah[mi], &bh[ni][2 * ks]);
        }
    }

    int er = lane >> 2, ec = (lane & 3) * 2;
    #pragma unroll
    for (int mi = 0; mi < 4; mi++) {
        #pragma unroll
        for (int ni = 0; ni < 8; ni++) {
            int row = m0 + wm * 64 + mi * 16 + er;
            int col = n0 + wn * 64 + ni * 8 + ec;
            float b0 = jb.bias[col], b1 = jb.bias[col + 1];
            float x00 = acc[mi][ni][0] + b0, x01 = acc[mi][ni][1] + b1;
            float x10 = acc[mi][ni][2] + b0, x11 = acc[mi][ni][3] + b1;
            if (jb.mode == 0) {
                *(float2*)(jb.Yf + (size_t)row * DMODEL + col) = float2{x00, x01};
                *(float2*)(jb.Yf + (size_t)(row + 8) * DMODEL + col) = float2{x10, x11};
            } else {
                x00 *= jb.scale; x01 *= jb.scale; x10 *= jb.scale; x11 *= jb.scale;
                *(__half2*)(jb.H1 + (size_t)row * DMODEL + col) =
                    __half2{__float2half_rn(x00), __float2half_rn(x01)};
                *(__half2*)(jb.H1 + (size_t)(row + 8) * DMODEL + col) =
                    __half2{__float2half_rn(x10), __float2half_rn(x11)};
            }
        }
    }
}

// ---------------- fused MMA flash attention -----------------------------------
// 3-stage KV ring, ONE __syncthreads per tile, issue-before-compute.
#define FSTR 72
#define MASKVAL 1.4426950409e-9f
#define KVSTG 4608          // halves per K (or V) stage: 64 * 72
#define NT (SEQ / 64)

__global__ void __launch_bounds__(256, 2) flash_mma(
    const __half* __restrict__ qhi, const __half* __restrict__ khi,
    const __half* __restrict__ vhi, __half* __restrict__ chi)
{
    extern __shared__ __half sh[];
    const int O_QHI = 0;                      // 128 x 72
    const int O_KH0 = 9216;                   // 3 K stages
    const int O_V0  = 9216 + 3 * KVSTG;       // 3 V stages
    uint32_t sb = smem_u32(sh);

    int tid = threadIdx.x, lane = tid & 31, wm = tid >> 5;   // 8 warps
    int q0 = blockIdx.x * 128, h = blockIdx.y, b = blockIdx.z;
    size_t rowbase = (size_t)b * SEQ;
    int r4 = lane >> 2, c2 = lane & 3;

    {
        const __half* qh = qhi + (rowbase + q0) * DMODEL + h * 64;
        #pragma unroll
        for (int c = tid; c < 1024; c += 256) {
            int r = c >> 3, dc = c & 7;
            CP_ASYNC16(sb + (O_QHI + r * FSTR + dc * 8) * 2, qh + (size_t)r * DMODEL + dc * 8);
        }
        CP_COMMIT();
    }
    const __half* kbh = khi + rowbase * DMODEL + h * 64;
    const __half* vb  = vhi + rowbase * DMODEL + h * 64;

    auto issue_kv = [&](int t) {
        int st = t % 3;
        int k0 = t * 64;
        #pragma unroll
        for (int c = tid; c < 512; c += 256) {
            int r = c >> 3, dc = c & 7;
            size_t g = (size_t)(k0 + r) * DMODEL + dc * 8;
            CP_ASYNC16(sb + (O_KH0 + st * KVSTG + r * FSTR + dc * 8) * 2, kbh + g);
            CP_ASYNC16(sb + (O_V0  + st * KVSTG + r * FSTR + dc * 8) * 2, vb + g);
        }
        CP_COMMIT();
    };
    issue_kv(0);
    issue_kv(1);

    float O[8][4];
    #pragma unroll
    for (int ni = 0; ni < 8; ni++)
        #pragma unroll
        for (int q = 0; q < 4; q++) O[ni][q] = 0.0f;
    float lsum[2] = {0.f, 0.f};
    float mrow[2] = {-1e30f, -1e30f};

    for (int t = 0; t < NT; t++) {
        if (t + 2 < NT) { CP_WAIT(1); } else { CP_WAIT(0); }
        __syncthreads();
        if (t + 2 < NT) issue_kv(t + 2);

        int st = t % 3;
        uint32_t kbase = sb + (O_KH0 + st * KVSTG) * 2;
        uint32_t vbase = sb + (O_V0  + st * KVSTG) * 2;

        uint2 mw[2];
        #pragma unroll
        for (int rr = 0; rr < 2; rr++) {
            int grow = q0 + wm * 16 + r4 + rr * 8;
            mw[rr] = __ldg((const uint2*)&g_mbits[(size_t)grow * MWORDS + 2 * t]);
        }

        float S[8][4];
        #pragma unroll
        for (int ni = 0; ni < 8; ni++)
            #pragma unroll
            for (int q = 0; q < 4; q++) S[ni][q] = 0.0f;

        #pragma unroll
        for (int ks = 0; ks < 4; ks++) {
            uint32_t aH[4];
            {
                uint32_t abase = sb + (((wm * 16 + (lane & 15)) * FSTR) +
                                       (lane >> 4) * 8 + ks * 16) * 2;
                ldsm4(aH, abase);
            }
            uint32_t bH[8][2];
            #pragma unroll
            for (int np = 0; np < 4; np++) {
                uint32_t r4v[4];
                uint32_t boff = ((np * 16 + (lane & 7) + ((lane >> 4) & 1) * 8) * FSTR +
                                 ks * 16 + ((lane >> 3) & 1) * 8) * 2;
                ldsm4(r4v, kbase + boff);
                bH[2 * np][0] = r4v[0];     bH[2 * np][1] = r4v[1];
                bH[2 * np + 1][0] = r4v[2]; bH[2 * np + 1][1] = r4v[3];
            }
            #pragma unroll
            for (int ni = 0; ni < 8; ni++)
                mma_f16(S[ni], aH, bH[ni]);
        }

        float mnew[2] = {mrow[0], mrow[1]};
        #pragma unroll
        for (int ni = 0; ni < 8; ni++) {
            uint32_t w0 = (ni < 4) ? mw[0].x : mw[0].y;
            uint32_t w1 = (ni < 4) ? mw[1].x : mw[1].y;
            int shf = (ni & 3) * 8 + 2 * c2;
            if ((w0 >> shf) & 1u)       S[ni][0] = MASKVAL;
            if ((w0 >> (shf + 1)) & 1u) S[ni][1] = MASKVAL;
            if ((w1 >> shf) & 1u)       S[ni][2] = MASKVAL;
            if ((w1 >> (shf + 1)) & 1u) S[ni][3] = MASKVAL;
            mnew[0] = fmaxf(mnew[0], fmaxf(S[ni][0], S[ni][1]));
            mnew[1] = fmaxf(mnew[1], fmaxf(S[ni][2], S[ni][3]));
        }
        #pragma unroll
        for (int j = 0; j < 2; j++) {
            mnew[j] = fmaxf(mnew[j], __shfl_xor_sync(0xffffffffu, mnew[j], 1));
            mnew[j] = fmaxf(mnew[j], __shfl_xor_sync(0xffffffffu, mnew[j], 2));
        }
        float al[2];
        #pragma unroll
        for (int j = 0; j < 2; j++) {
            al[j] = ex2f(mrow[j] - mnew[j]);
            mrow[j] = mnew[j];
            lsum[j] *= al[j];
        }
        #pragma unroll
        for (int ni = 0; ni < 8; ni++) {
            O[ni][0] *= al[0]; O[ni][1] *= al[0];
            O[ni][2] *= al[1]; O[ni][3] *= al[1];
        }

        uint32_t pa[4][4];
        #pragma unroll
        for (int ni = 0; ni < 8; ni++) {
            float p0 = ex2f(S[ni][0] - mnew[0]);
            float p1 = ex2f(S[ni][1] - mnew[0]);
            float p2 = ex2f(S[ni][2] - mnew[1]);
            float p3 = ex2f(S[ni][3] - mnew[1]);
            lsum[0] += p0 + p1;
            lsum[1] += p2 + p3;
            int ks = ni >> 1, half = ni & 1;
            pa[ks][half * 2 + 0] = packh2(p0, p1);
            pa[ks][half * 2 + 1] = packh2(p2, p3);
        }

        #pragma unroll
        for (int ks = 0; ks < 4; ks++) {
            #pragma unroll
            for (int nn = 0; nn < 4; nn++) {
                uint32_t vb4[4];
                int key = ks * 16 + (lane & 7) + ((lane >> 3) & 1) * 8;
                int dim = nn * 16 + ((lane >> 4) & 1) * 8;
                ldsm4t(vb4, vbase + (key * FSTR + dim) * 2);
                mma_f16(O[2 * nn],     pa[ks], &vb4[0]);
                mma_f16(O[2 * nn + 1], pa[ks], &vb4[2]);
            }
        }
    }

    #pragma unroll
    for (int j = 0; j < 2; j++) {
        lsum[j] += __shfl_xor_sync(0xffffffffu, lsum[j], 1);
        lsum[j] += __shfl_xor_sync(0xffffffffu, lsum[j], 2);
        lsum[j] = 1.0f / lsum[j];
    }
    #pragma unroll
    for (int ni = 0; ni < 8; ni++) {
        size_t grow = rowbase + q0 + wm * 16 + r4;
        int col = h * 64 + ni * 8 + 2 * c2;
        float x00 = O[ni][0] * lsum[0];
        float x01 = O[ni][1] * lsum[0];
        float x10 = O[ni][2] * lsum[1];
        float x11 = O[ni][3] * lsum[1];
        *(__half2*)(chi + grow * DMODEL + col) =
            __half2{__float2half_rn(x00), __float2half_rn(x01)};
        *(__half2*)(chi + (grow + 8) * DMODEL + col) =
            __half2{__float2half_rn(x10), __float2half_rn(x11)};
    }
}

// ---------------- launch ------------------------------------------------------
extern "C" void kernel_launch(void* const* d_in, const int* in_sizes, int n_in,
                              void* d_out, int out_size)
{
    const float* q    = (const float*)d_in[0];
    const float* k    = (const float*)d_in[1];
    const float* v    = (const float*)d_in[2];
    const void*  mask = d_in[3];
    const float* Wq   = (const float*)d_in[4];
    const float* bq   = (const float*)d_in[5];
    const float* Wk   = (const float*)d_in[6];
    const float* bk   = (const float*)d_in[7];
    const float* Wv   = (const float*)d_in[8];
    const float* bv   = (const float*)d_in[9];
    const float* Wo   = (const float*)d_in[10];
    const float* bo   = (const float*)d_in[11];

    __half *qsh, *ksh, *vsh, *qhi, *khi, *vhi, *chi, *w16;
    cudaGetSymbolAddress((void**)&qsh, g_qsh);
    cudaGetSymbolAddress((void**)&ksh, g_ksh);
    cudaGetSymbolAddress((void**)&vsh, g_vsh);
    cudaGetSymbolAddress((void**)&qhi, g_qhi);
    cudaGetSymbolAddress((void**)&khi, g_khi);
    cudaGetSymbolAddress((void**)&vhi, g_vhi);
    cudaGetSymbolAddress((void**)&chi, g_chi);
    cudaGetSymbolAddress((void**)&w16, g_w16);

    const int gemm_smem = 3 * STAGE_B;            // 61440
    const int flash_smem = (9216 + 6 * KVSTG) * 2;  // 73728
    static bool attr_set = false;
    if (!attr_set) {
        cudaFuncSetAttribute(gemm_mma, cudaFuncAttributeMaxDynamicSharedMemorySize, gemm_smem);
        cudaFuncSetAttribute(flash_mma, cudaFuncAttributeMaxDynamicSharedMemorySize, flash_smem);
        attr_set = true;
    }

    const float qscale = 0.125f * LOG2E;

    detect_mask<<<1, 256>>>((const unsigned*)mask);
    pack_mask<<<(SEQ * MWORDS) / 256, 256>>>(mask);

    conv_all<<<dim3(NACT8 / 256, 7), 256>>>(
        (const float4*)q, (const float4*)k, (const float4*)v,
        (const float4*)Wq, (const float4*)Wk, (const float4*)Wv, (const float4*)Wo,
        qsh, ksh, vsh, w16);

    Jobs3 pj;
    pj.j[0] = Job{qsh, w16,                     bq, nullptr, qhi, 2, qscale};
    pj.j[1] = Job{ksh, w16 + 1 * DMODEL*DMODEL, bk, nullptr, khi, 2, 1.0f};
    pj.j[2] = Job{vsh, w16 + 2 * DMODEL*DMODEL, bv, nullptr, vhi, 2, 1.0f};
    gemm_mma<<<dim3(8, 64, 3), 128, gemm_smem>>>(pj);

    flash_mma<<<dim3(SEQ / 128, NHEAD, NBATCH), 256, flash_smem>>>(qhi, khi, vhi, chi);

    Jobs3 oj;
    oj.j[0] = Job{chi, w16 + 3 * DMODEL*DMODEL, bo, (float*)d_out, nullptr, 0, 1.0f};
    oj.j[1] = oj.j[0];
    oj.j[2] = oj.j[0];
    gemm_mma<<<dim3(8, 64, 1), 128, gemm_smem>>>(oj);
}